// round 1
// baseline (speedup 1.0000x reference)
#include <cuda_runtime.h>
#include <math.h>

#define TOK 4096        // B*S
#define Hd  1024
#define Id  4096
#define NHh 16
#define DHh 64

// ---------------- scratch (device globals; no allocs) ----------------
__device__ float g_xs[TOK * Hd];
__device__ float g_ys[TOK * Hd];
__device__ float g_q [TOK * Hd];
__device__ float g_k [TOK * Hd];
__device__ float g_v [TOK * Hd];
__device__ float g_ctx[TOK * Hd];
__device__ float g_att[TOK * Hd];
__device__ float g_tmp[TOK * Hd];
__device__ float g_inter[TOK * Id];

// ---------------- routing: collapse squash/dot loop to 3 scalars ----------------
__global__ void __launch_bounds__(256) routing_kernel(
    const float* __restrict__ x, const float* __restrict__ y,
    const int* __restrict__ tptr,
    float* __restrict__ xs, float* __restrict__ ys) {
  const int token = blockIdx.x, tid = threadIdx.x;
  const long base = (long)token * Hd;
  float sxx = 0.f, sxy = 0.f, syy = 0.f;
  for (int i = tid; i < Hd; i += 256) {
    float a = x[base + i], b = y[base + i];
    sxx += a * a; sxy += a * b; syy += b * b;
  }
  #pragma unroll
  for (int o = 16; o; o >>= 1) {
    sxx += __shfl_xor_sync(0xffffffffu, sxx, o);
    sxy += __shfl_xor_sync(0xffffffffu, sxy, o);
    syy += __shfl_xor_sync(0xffffffffu, syy, o);
  }
  __shared__ float red[8][3];
  __shared__ float sc[2];
  if ((tid & 31) == 0) { red[tid >> 5][0] = sxx; red[tid >> 5][1] = sxy; red[tid >> 5][2] = syy; }
  __syncthreads();
  if (tid == 0) {
    float a = 0.f, bb = 0.f, c = 0.f;
    #pragma unroll
    for (int i = 0; i < 8; i++) { a += red[i][0]; bb += red[i][1]; c += red[i][2]; }
    const int t = *tptr;
    float b1 = 0.f, b2 = 0.f, c1 = 0.5f, c2 = 0.5f;
    for (int it = 0; it < t; it++) {
      if (it > 0) {
        float mm = fmaxf(b1, b2);
        float e1 = expf(b1 - mm), e2 = expf(b2 - mm);
        float inv = 1.0f / (e1 + e2);
        c1 = e1 * inv; c2 = e2 * inv;
      }
      float vv = c1 * c1 * a + 2.0f * c1 * c2 * bb + c2 * c2 * c; // ||v||^2
      float n  = sqrtf(vv);
      float f  = n / (1.0f + vv);             // squash scale: n/(1+n^2)
      b1 += f * (c1 * a  + c2 * bb);          // a.x
      b2 += f * (c1 * bb + c2 * c );          // a.y
    }
    sc[0] = c1; sc[1] = c2;
  }
  __syncthreads();
  const float c1 = sc[0], c2 = sc[1];
  for (int i = tid; i < Hd; i += 256) {
    xs[base + i] = c1 * x[base + i];
    ys[base + i] = c2 * y[base + i];
  }
}

// ---------------- SIMT SGEMM: C[M,N] = A[M,K] @ B[K,N] + bias (opt GELU) ----------------
// BM=BN=128, BK=16, 256 threads, 8x8 per-thread tile, double-buffered smem.
template<bool GELU>
__global__ void __launch_bounds__(256) gemm_kernel(
    const float* __restrict__ A, const float* __restrict__ B,
    const float* __restrict__ bias, float* __restrict__ C,
    int M, int N, int K) {
  __shared__ float As[2][16][128];
  __shared__ float Bs[2][16][128];
  const int tid = threadIdx.x;
  const int bm = blockIdx.y * 128;
  const int bn = blockIdx.x * 128;
  const int tx = tid & 15, ty = tid >> 4;

  float4 ra[2], rb[2];
  const int nkt = K >> 4;

  // prologue: load tile 0
  #pragma unroll
  for (int it = 0; it < 2; it++) {
    int idx = tid + it * 256;
    int r = idx >> 2, c = (idx & 3) << 2;
    ra[it] = *(const float4*)(A + (long)(bm + r) * K + c);
    int kk = idx >> 5, n = (idx & 31) << 2;
    rb[it] = *(const float4*)(B + (long)kk * N + bn + n);
  }
  #pragma unroll
  for (int it = 0; it < 2; it++) {
    int idx = tid + it * 256;
    int r = idx >> 2, c = (idx & 3) << 2;
    As[0][c + 0][r] = ra[it].x; As[0][c + 1][r] = ra[it].y;
    As[0][c + 2][r] = ra[it].z; As[0][c + 3][r] = ra[it].w;
    int kk = idx >> 5, n = (idx & 31) << 2;
    *(float4*)&Bs[0][kk][n] = rb[it];
  }
  __syncthreads();

  float acc[8][8];
  #pragma unroll
  for (int i = 0; i < 8; i++)
    #pragma unroll
    for (int j = 0; j < 8; j++) acc[i][j] = 0.f;

  for (int kt = 0; kt < nkt; kt++) {
    const int cur = kt & 1;
    if (kt + 1 < nkt) {
      #pragma unroll
      for (int it = 0; it < 2; it++) {
        int idx = tid + it * 256;
        int r = idx >> 2, c = (idx & 3) << 2;
        ra[it] = *(const float4*)(A + (long)(bm + r) * K + (kt + 1) * 16 + c);
        int kk = idx >> 5, n = (idx & 31) << 2;
        rb[it] = *(const float4*)(B + (long)((kt + 1) * 16 + kk) * N + bn + n);
      }
    }
    #pragma unroll
    for (int kk = 0; kk < 16; kk++) {
      float fa[8], fb[8];
      *(float4*)&fa[0] = *(const float4*)&As[cur][kk][ty * 8];
      *(float4*)&fa[4] = *(const float4*)&As[cur][kk][ty * 8 + 4];
      *(float4*)&fb[0] = *(const float4*)&Bs[cur][kk][tx * 8];
      *(float4*)&fb[4] = *(const float4*)&Bs[cur][kk][tx * 8 + 4];
      #pragma unroll
      for (int i = 0; i < 8; i++)
        #pragma unroll
        for (int j = 0; j < 8; j++)
          acc[i][j] += fa[i] * fb[j];
    }
    __syncthreads();
    if (kt + 1 < nkt) {
      const int nb = 1 - cur;
      #pragma unroll
      for (int it = 0; it < 2; it++) {
        int idx = tid + it * 256;
        int r = idx >> 2, c = (idx & 3) << 2;
        As[nb][c + 0][r] = ra[it].x; As[nb][c + 1][r] = ra[it].y;
        As[nb][c + 2][r] = ra[it].z; As[nb][c + 3][r] = ra[it].w;
        int kk = idx >> 5, n = (idx & 31) << 2;
        *(float4*)&Bs[nb][kk][n] = rb[it];
      }
      __syncthreads();
    }
  }

  // epilogue: +bias (opt GELU exact)
  #pragma unroll
  for (int i = 0; i < 8; i++) {
    const long row = bm + ty * 8 + i;
    #pragma unroll
    for (int j = 0; j < 8; j += 4) {
      const int col = bn + tx * 8 + j;
      float4 bv = *(const float4*)(bias + col);
      float4 v;
      v.x = acc[i][j + 0] + bv.x;
      v.y = acc[i][j + 1] + bv.y;
      v.z = acc[i][j + 2] + bv.z;
      v.w = acc[i][j + 3] + bv.w;
      if (GELU) {
        v.x = 0.5f * v.x * (1.0f + erff(v.x * 0.70710678118654752f));
        v.y = 0.5f * v.y * (1.0f + erff(v.y * 0.70710678118654752f));
        v.z = 0.5f * v.z * (1.0f + erff(v.z * 0.70710678118654752f));
        v.w = 0.5f * v.w * (1.0f + erff(v.w * 0.70710678118654752f));
      }
      *(float4*)(C + row * N + col) = v;
    }
  }
}

// ---------------- flash attention (fp32, online softmax) ----------------
// grid (S/64, NH, B); 256 threads = 8 warps; warp owns 8 q rows;
// lane ln holds output dims {ln, ln+32}; K/V tiles of 32 keys.
__global__ void __launch_bounds__(256) attn_kernel(
    const float* __restrict__ Q, const float* __restrict__ K,
    const float* __restrict__ V, const float* __restrict__ mask,
    float* __restrict__ O) {
  const int qt = blockIdx.x, h = blockIdx.y, b = blockIdx.z;
  const int tid = threadIdx.x, w = tid >> 5, ln = tid & 31;
  __shared__ float Qs[64][64];   // broadcast reads -> no pad needed
  __shared__ float Ks[32][65];
  __shared__ float Vs[32][65];
  __shared__ float Ps[8][32];

  for (int i = tid; i < 64 * 64; i += 256) {
    int r = i >> 6, d = i & 63;
    Qs[r][d] = Q[(long)(b * 1024 + qt * 64 + r) * Hd + h * DHh + d];
  }
  float m[8], l[8], acc0[8], acc1[8];
  #pragma unroll
  for (int i = 0; i < 8; i++) { m[i] = -1e30f; l[i] = 0.f; acc0[i] = 0.f; acc1[i] = 0.f; }

  for (int kt = 0; kt < 32; kt++) {
    __syncthreads();
    for (int i = tid; i < 32 * 64; i += 256) {
      int r = i >> 6, d = i & 63;
      long g = (long)(b * 1024 + kt * 32 + r) * Hd + h * DHh + d;
      Ks[r][d] = K[g];
      Vs[r][d] = V[g];
    }
    __syncthreads();
    const float msk = mask[b * 1024 + kt * 32 + ln];
    #pragma unroll
    for (int rr = 0; rr < 8; rr++) {
      const int r = w * 8 + rr;
      float s = 0.f;
      #pragma unroll
      for (int d = 0; d < 64; d++) s += Qs[r][d] * Ks[ln][d];
      s = s * 0.125f + msk;
      float mx = s;
      #pragma unroll
      for (int o = 16; o; o >>= 1) mx = fmaxf(mx, __shfl_xor_sync(0xffffffffu, mx, o));
      const float mnew = fmaxf(m[rr], mx);
      const float p = __expf(s - mnew);
      float psum = p;
      #pragma unroll
      for (int o = 16; o; o >>= 1) psum += __shfl_xor_sync(0xffffffffu, psum, o);
      const float scale = __expf(m[rr] - mnew);
      l[rr] = l[rr] * scale + psum;
      m[rr] = mnew;
      float a0 = acc0[rr] * scale, a1 = acc1[rr] * scale;
      Ps[w][ln] = p;
      __syncwarp();
      #pragma unroll
      for (int j = 0; j < 32; j++) {
        const float pj = Ps[w][j];
        a0 += pj * Vs[j][ln];
        a1 += pj * Vs[j][ln + 32];
      }
      acc0[rr] = a0; acc1[rr] = a1;
      __syncwarp();
    }
  }
  #pragma unroll
  for (int rr = 0; rr < 8; rr++) {
    const int r = w * 8 + rr;
    const float inv = 1.0f / l[rr];
    const long g = (long)(b * 1024 + qt * 64 + r) * Hd + h * DHh;
    O[g + ln]      = acc0[rr] * inv;
    O[g + ln + 32] = acc1[rr] * inv;
  }
}

// ---------------- fused residual + RMSNorm ----------------
__global__ void __launch_bounds__(256) rms_kernel(
    const float* __restrict__ in, const float* __restrict__ res,
    const float* __restrict__ g, float* __restrict__ out) {
  const int row = blockIdx.x, tid = threadIdx.x;
  __shared__ float buf[Hd];
  __shared__ float red[8];
  __shared__ float s_inv;
  const long base = (long)row * Hd;
  float ss = 0.f;
  for (int i = tid; i < Hd; i += 256) {
    float v = in[base + i] + res[base + i];
    buf[i] = v; ss += v * v;
  }
  #pragma unroll
  for (int o = 16; o; o >>= 1) ss += __shfl_xor_sync(0xffffffffu, ss, o);
  if ((tid & 31) == 0) red[tid >> 5] = ss;
  __syncthreads();
  if (tid == 0) {
    float tot = 0.f;
    #pragma unroll
    for (int i = 0; i < 8; i++) tot += red[i];
    s_inv = rsqrtf(tot * (1.0f / (float)Hd) + 1e-6f);
  }
  __syncthreads();
  const float inv = s_inv;
  for (int i = tid; i < Hd; i += 256) out[base + i] = buf[i] * inv * g[i];
}

// ---------------- host ----------------
static void run_gemm(const float* A, const float* B, const float* bias, float* C,
                     int M, int N, int K, bool gelu) {
  dim3 grid(N / 128, M / 128);
  if (gelu) gemm_kernel<true ><<<grid, 256>>>(A, B, bias, C, M, N, K);
  else      gemm_kernel<false><<<grid, 256>>>(A, B, bias, C, M, N, K);
}

extern "C" void kernel_launch(void* const* d_in, const int* in_sizes, int n_in,
                              void* d_out, int out_size) {
  const float* x    = (const float*)d_in[0];
  const float* y    = (const float*)d_in[1];
  const float* mask = (const float*)d_in[2];
  const float* Wq   = (const float*)d_in[3];
  const float* bq   = (const float*)d_in[4];
  const float* Wk   = (const float*)d_in[5];
  const float* bk   = (const float*)d_in[6];
  const float* Wv   = (const float*)d_in[7];
  const float* bv   = (const float*)d_in[8];
  const float* Wo   = (const float*)d_in[9];
  const float* bo   = (const float*)d_in[10];
  const float* g1   = (const float*)d_in[11];
  const float* Wi   = (const float*)d_in[12];
  const float* bi   = (const float*)d_in[13];
  const float* Wo2  = (const float*)d_in[14];
  const float* bo2  = (const float*)d_in[15];
  const float* g2   = (const float*)d_in[16];
  const int*   t    = (const int*)d_in[17];
  float* out = (float*)d_out;

  float *xs, *ys, *q, *k, *v, *ctx, *att, *tmp, *inter;
  cudaGetSymbolAddress((void**)&xs,    g_xs);
  cudaGetSymbolAddress((void**)&ys,    g_ys);
  cudaGetSymbolAddress((void**)&q,     g_q);
  cudaGetSymbolAddress((void**)&k,     g_k);
  cudaGetSymbolAddress((void**)&v,     g_v);
  cudaGetSymbolAddress((void**)&ctx,   g_ctx);
  cudaGetSymbolAddress((void**)&att,   g_att);
  cudaGetSymbolAddress((void**)&tmp,   g_tmp);
  cudaGetSymbolAddress((void**)&inter, g_inter);

  routing_kernel<<<TOK, 256>>>(x, y, t, xs, ys);

  run_gemm(xs, Wq, bq, q, TOK, Hd, Hd, false);
  run_gemm(ys, Wk, bk, k, TOK, Hd, Hd, false);
  run_gemm(ys, Wv, bv, v, TOK, Hd, Hd, false);

  attn_kernel<<<dim3(16, NHh, 4), 256>>>(q, k, v, mask, ctx);

  run_gemm(ctx, Wo, bo, tmp, TOK, Hd, Hd, false);
  rms_kernel<<<TOK, 256>>>(tmp, xs, g1, att);

  run_gemm(att, Wi, bi, inter, TOK, Id, Hd, true);
  run_gemm(inter, Wo2, bo2, tmp, TOK, Hd, Id, false);
  rms_kernel<<<TOK, 256>>>(tmp, att, g2, out);
}

// round 3
// speedup vs baseline: 1.6147x; 1.6147x over previous
#include <cuda_runtime.h>
#include <cuda_bf16.h>
#include <math.h>
#include <stdint.h>

#define TOK 4096        // B*S
#define Hd  1024
#define Id  4096
#define NHh 16
#define DHh 64

// ---------------- scratch (device globals; no allocs) ----------------
__device__ float g_xs[TOK * Hd];
__device__ float g_ys[TOK * Hd];
__device__ float g_q [TOK * Hd];
__device__ float g_k [TOK * Hd];
__device__ float g_v [TOK * Hd];
__device__ float g_ctx[TOK * Hd];
__device__ float g_att[TOK * Hd];
__device__ float g_tmp[TOK * Hd];
__device__ float g_inter[TOK * Id];

// bf16 hi/lo activation buffers
__device__ __nv_bfloat16 g_actA_h[TOK * Id];
__device__ __nv_bfloat16 g_actA_l[TOK * Id];
__device__ __nv_bfloat16 g_actB_h[TOK * Hd];
__device__ __nv_bfloat16 g_actB_l[TOK * Hd];

// transposed bf16 weights [N, K]
__device__ __nv_bfloat16 g_wq_h[Hd * Hd], g_wq_l[Hd * Hd];
__device__ __nv_bfloat16 g_wk_h[Hd * Hd], g_wk_l[Hd * Hd];
__device__ __nv_bfloat16 g_wv_h[Hd * Hd], g_wv_l[Hd * Hd];
__device__ __nv_bfloat16 g_wo_h[Hd * Hd], g_wo_l[Hd * Hd];
__device__ __nv_bfloat16 g_wi_h[Id * Hd], g_wi_l[Id * Hd];
__device__ __nv_bfloat16 g_w2_h[Hd * Id], g_w2_l[Hd * Id];

// ---------------- helpers ----------------
__device__ __forceinline__ uint32_t smem_u32(const void* p) {
  uint32_t a;
  asm("{ .reg .u64 t; cvta.to.shared.u64 t, %1; cvt.u32.u64 %0, t; }" : "=r"(a) : "l"(p));
  return a;
}
__device__ __forceinline__ void cp_async16(uint32_t dst, const void* src) {
  asm volatile("cp.async.cg.shared.global [%0], [%1], 16;" :: "r"(dst), "l"(src) : "memory");
}
#define CP_COMMIT() asm volatile("cp.async.commit_group;" ::: "memory")
#define CP_WAIT(n)  asm volatile("cp.async.wait_group %0;" :: "n"(n) : "memory")

__device__ __forceinline__ void ldsm4(uint32_t* r, uint32_t addr) {
  asm volatile("ldmatrix.sync.aligned.m8n8.x4.shared.b16 {%0,%1,%2,%3}, [%4];"
               : "=r"(r[0]), "=r"(r[1]), "=r"(r[2]), "=r"(r[3]) : "r"(addr));
}
__device__ __forceinline__ void mma16816(float* d, const uint32_t* a, const uint32_t* b) {
  asm volatile("mma.sync.aligned.m16n8k16.row.col.f32.bf16.bf16.f32 "
               "{%0,%1,%2,%3}, {%4,%5,%6,%7}, {%8,%9}, {%0,%1,%2,%3};"
               : "+f"(d[0]), "+f"(d[1]), "+f"(d[2]), "+f"(d[3])
               : "r"(a[0]), "r"(a[1]), "r"(a[2]), "r"(a[3]), "r"(b[0]), "r"(b[1]));
}

// swizzled offset inside a [128 rows x 64B] tile; c16 = 16B-chunk index (0..3)
__device__ __forceinline__ uint32_t swz(int row, int c16) {
  return (uint32_t)(row * 64 + ((c16 ^ ((row >> 1) & 3)) << 4));
}

// ---------------- conversions ----------------
__global__ void __launch_bounds__(256) cvt_act_kernel(
    const float* __restrict__ in, __nv_bfloat16* __restrict__ h,
    __nv_bfloat16* __restrict__ l, int n) {
  int base = (blockIdx.x * 256 + threadIdx.x) * 8;
  if (base >= n) return;
  float4 v0 = *(const float4*)(in + base);
  float4 v1 = *(const float4*)(in + base + 4);
  __nv_bfloat16 hh[8], ll[8];
  float f[8] = {v0.x, v0.y, v0.z, v0.w, v1.x, v1.y, v1.z, v1.w};
  #pragma unroll
  for (int i = 0; i < 8; i++) {
    hh[i] = __float2bfloat16(f[i]);
    ll[i] = __float2bfloat16(f[i] - __bfloat162float(hh[i]));
  }
  *(uint4*)(h + base) = *(uint4*)hh;
  *(uint4*)(l + base) = *(uint4*)ll;
}

__global__ void __launch_bounds__(256) cvt_wt_t_kernel(
    const float* __restrict__ W, __nv_bfloat16* __restrict__ Th,
    __nv_bfloat16* __restrict__ Tl, int K, int N) {
  __shared__ float t[32][33];
  const int nb = blockIdx.x * 32, kb = blockIdx.y * 32;
  const int tx = threadIdx.x & 31, ty = threadIdx.x >> 5;
  #pragma unroll
  for (int i = 0; i < 32; i += 8)
    t[ty + i][tx] = W[(size_t)(kb + ty + i) * N + nb + tx];
  __syncthreads();
  #pragma unroll
  for (int i = 0; i < 32; i += 8) {
    float v = t[tx][ty + i];
    __nv_bfloat16 h = __float2bfloat16(v);
    __nv_bfloat16 l = __float2bfloat16(v - __bfloat162float(h));
    size_t o = (size_t)(nb + ty + i) * K + kb + tx;
    Th[o] = h; Tl[o] = l;
  }
}

// ---------------- HMMA GEMM: C[M,N] = A[M,K] @ B^T (B stored [N,K]), bf16x3 ----------------
// 128x128 tile, BK=32, 8 warps (2 m x 4 n), warp tile 64x32.
// smem/stage: Ah(8K) Al(8K) Bh(8K) Bl(8K) = 32KB; 2 stages = 64KB dynamic.
template<bool GELU>
__global__ void __launch_bounds__(256, 1)
gemm_mma_kernel(const __nv_bfloat16* __restrict__ Ah, const __nv_bfloat16* __restrict__ Al,
                const __nv_bfloat16* __restrict__ Bh, const __nv_bfloat16* __restrict__ Bl,
                const float* __restrict__ bias, float* __restrict__ C,
                int M, int N, int K) {
  extern __shared__ __align__(128) char sm[];
  const uint32_t smb = smem_u32(sm);
  const int tid = threadIdx.x;
  const int wid = tid >> 5, lane = tid & 31;
  const int bm = blockIdx.y * 128, bn = blockIdx.x * 128;
  const int warp_m = wid & 1, warp_n = wid >> 1;
  const int NK = K >> 5;

  // per-stage matrix offsets
  auto stage_off = [](int s, int mat) -> uint32_t { return (uint32_t)(s * 32768 + mat * 8192); };

  // loader: 2 chunks/thread/matrix
  auto load_stage = [&](int kt, int s) {
    const int koff = kt * 32;
    #pragma unroll
    for (int j = 0; j < 2; j++) {
      const int ch = tid + j * 256;       // 0..511
      const int row = ch >> 2, c = ch & 3;
      const uint32_t d = swz(row, c);
      const size_t ga = (size_t)(bm + row) * K + koff + c * 8;
      const size_t gb = (size_t)(bn + row) * K + koff + c * 8;
      cp_async16(smb + stage_off(s, 0) + d, Ah + ga);
      cp_async16(smb + stage_off(s, 1) + d, Al + ga);
      cp_async16(smb + stage_off(s, 2) + d, Bh + gb);
      cp_async16(smb + stage_off(s, 3) + d, Bl + gb);
    }
  };

  float acc[4][4][4];
  #pragma unroll
  for (int i = 0; i < 4; i++)
    #pragma unroll
    for (int j = 0; j < 4; j++)
      #pragma unroll
      for (int q = 0; q < 4; q++) acc[i][j][q] = 0.f;

  load_stage(0, 0);
  CP_COMMIT();

  // ldmatrix lane address components
  const int la_row = (lane & 7) + ((lane >> 3) & 1) * 8;   // A: row within m16
  const int la_c   = (lane >> 4);                          // A: chunk within k16
  const int lb_row = (lane & 7) + (lane >> 4) * 8;         // B: row within n16
  const int lb_c   = (lane >> 3) & 1;                      // B: chunk within k16

  for (int kt = 0; kt < NK; kt++) {
    const int s = kt & 1;
    if (kt + 1 < NK) { load_stage(kt + 1, 1 - s); CP_COMMIT(); CP_WAIT(1); }
    else             { CP_WAIT(0); }
    __syncthreads();

    const uint32_t baseAh = smb + stage_off(s, 0);
    const uint32_t baseAl = smb + stage_off(s, 1);
    const uint32_t baseBh = smb + stage_off(s, 2);
    const uint32_t baseBl = smb + stage_off(s, 3);

    #pragma unroll
    for (int ks = 0; ks < 2; ks++) {
      uint32_t aH[4][4], aL[4][4], bH[2][4], bL[2][4];
      #pragma unroll
      for (int tm = 0; tm < 4; tm++) {
        const int row = warp_m * 64 + tm * 16 + la_row;
        const int c   = ks * 2 + la_c;
        ldsm4(aH[tm], baseAh + swz(row, c));
        ldsm4(aL[tm], baseAl + swz(row, c));
      }
      #pragma unroll
      for (int tn2 = 0; tn2 < 2; tn2++) {
        const int row = warp_n * 32 + tn2 * 16 + lb_row;
        const int c   = ks * 2 + lb_c;
        ldsm4(bH[tn2], baseBh + swz(row, c));
        ldsm4(bL[tn2], baseBl + swz(row, c));
      }
      #pragma unroll
      for (int tm = 0; tm < 4; tm++)
        #pragma unroll
        for (int tn = 0; tn < 4; tn++) {
          const uint32_t* bh = &bH[tn >> 1][(tn & 1) * 2];
          const uint32_t* bl = &bL[tn >> 1][(tn & 1) * 2];
          mma16816(acc[tm][tn], aH[tm], bh);
          mma16816(acc[tm][tn], aH[tm], bl);
          mma16816(acc[tm][tn], aL[tm], bh);
        }
    }
    __syncthreads();
  }

  // epilogue: direct per-lane stores (+bias, opt GELU)
  const int g = lane >> 2, tq = lane & 3;
  #pragma unroll
  for (int tm = 0; tm < 4; tm++) {
    #pragma unroll
    for (int tn = 0; tn < 4; tn++) {
      const int col = bn + warp_n * 32 + tn * 8 + tq * 2;
      const float b0 = bias[col], b1 = bias[col + 1];
      #pragma unroll
      for (int half = 0; half < 2; half++) {
        const int row = bm + warp_m * 64 + tm * 16 + g + half * 8;
        float2 v;
        v.x = acc[tm][tn][half * 2 + 0] + b0;
        v.y = acc[tm][tn][half * 2 + 1] + b1;
        if (GELU) {
          v.x = 0.5f * v.x * (1.0f + erff(v.x * 0.7071067811865476f));
          v.y = 0.5f * v.y * (1.0f + erff(v.y * 0.7071067811865476f));
        }
        *(float2*)(C + (size_t)row * N + col) = v;
      }
    }
  }
}

// ---------------- routing ----------------
__global__ void __launch_bounds__(256) routing_kernel(
    const float* __restrict__ x, const float* __restrict__ y,
    const int* __restrict__ tptr,
    float* __restrict__ xs, float* __restrict__ ys) {
  const int token = blockIdx.x, tid = threadIdx.x;
  const long base = (long)token * Hd;
  float sxx = 0.f, sxy = 0.f, syy = 0.f;
  for (int i = tid; i < Hd; i += 256) {
    float a = x[base + i], b = y[base + i];
    sxx += a * a; sxy += a * b; syy += b * b;
  }
  #pragma unroll
  for (int o = 16; o; o >>= 1) {
    sxx += __shfl_xor_sync(0xffffffffu, sxx, o);
    sxy += __shfl_xor_sync(0xffffffffu, sxy, o);
    syy += __shfl_xor_sync(0xffffffffu, syy, o);
  }
  __shared__ float red[8][3];
  __shared__ float sc[2];
  if ((tid & 31) == 0) { red[tid >> 5][0] = sxx; red[tid >> 5][1] = sxy; red[tid >> 5][2] = syy; }
  __syncthreads();
  if (tid == 0) {
    float a = 0.f, bb = 0.f, c = 0.f;
    #pragma unroll
    for (int i = 0; i < 8; i++) { a += red[i][0]; bb += red[i][1]; c += red[i][2]; }
    const int t = *tptr;
    float b1 = 0.f, b2 = 0.f, c1 = 0.5f, c2 = 0.5f;
    for (int it = 0; it < t; it++) {
      if (it > 0) {
        float mm = fmaxf(b1, b2);
        float e1 = expf(b1 - mm), e2 = expf(b2 - mm);
        float inv = 1.0f / (e1 + e2);
        c1 = e1 * inv; c2 = e2 * inv;
      }
      float vv = c1 * c1 * a + 2.0f * c1 * c2 * bb + c2 * c2 * c;
      float n  = sqrtf(vv);
      float f  = n / (1.0f + vv);
      b1 += f * (c1 * a  + c2 * bb);
      b2 += f * (c1 * bb + c2 * c );
    }
    sc[0] = c1; sc[1] = c2;
  }
  __syncthreads();
  const float c1 = sc[0], c2 = sc[1];
  for (int i = tid; i < Hd; i += 256) {
    xs[base + i] = c1 * x[base + i];
    ys[base + i] = c2 * y[base + i];
  }
}

// ---------------- flash attention (fp32, online softmax) ----------------
__global__ void __launch_bounds__(256) attn_kernel(
    const float* __restrict__ Q, const float* __restrict__ K,
    const float* __restrict__ V, const float* __restrict__ mask,
    float* __restrict__ O) {
  const int qt = blockIdx.x, h = blockIdx.y, b = blockIdx.z;
  const int tid = threadIdx.x, w = tid >> 5, ln = tid & 31;
  __shared__ float Qs[64][64];
  __shared__ float Ks[32][65];
  __shared__ float Vs[32][65];
  __shared__ float Ps[8][32];

  for (int i = tid; i < 64 * 64; i += 256) {
    int r = i >> 6, d = i & 63;
    Qs[r][d] = Q[(long)(b * 1024 + qt * 64 + r) * Hd + h * DHh + d];
  }
  float m[8], l[8], acc0[8], acc1[8];
  #pragma unroll
  for (int i = 0; i < 8; i++) { m[i] = -1e30f; l[i] = 0.f; acc0[i] = 0.f; acc1[i] = 0.f; }

  for (int kt = 0; kt < 32; kt++) {
    __syncthreads();
    for (int i = tid; i < 32 * 64; i += 256) {
      int r = i >> 6, d = i & 63;
      long g = (long)(b * 1024 + kt * 32 + r) * Hd + h * DHh + d;
      Ks[r][d] = K[g];
      Vs[r][d] = V[g];
    }
    __syncthreads();
    const float msk = mask[b * 1024 + kt * 32 + ln];
    #pragma unroll
    for (int rr = 0; rr < 8; rr++) {
      const int r = w * 8 + rr;
      float s = 0.f;
      #pragma unroll
      for (int d = 0; d < 64; d++) s += Qs[r][d] * Ks[ln][d];
      s = s * 0.125f + msk;
      float mx = s;
      #pragma unroll
      for (int o = 16; o; o >>= 1) mx = fmaxf(mx, __shfl_xor_sync(0xffffffffu, mx, o));
      const float mnew = fmaxf(m[rr], mx);
      const float p = __expf(s - mnew);
      float psum = p;
      #pragma unroll
      for (int o = 16; o; o >>= 1) psum += __shfl_xor_sync(0xffffffffu, psum, o);
      const float scale = __expf(m[rr] - mnew);
      l[rr] = l[rr] * scale + psum;
      m[rr] = mnew;
      float a0 = acc0[rr] * scale, a1 = acc1[rr] * scale;
      Ps[w][ln] = p;
      __syncwarp();
      #pragma unroll
      for (int j = 0; j < 32; j++) {
        const float pj = Ps[w][j];
        a0 += pj * Vs[j][ln];
        a1 += pj * Vs[j][ln + 32];
      }
      acc0[rr] = a0; acc1[rr] = a1;
      __syncwarp();
    }
  }
  #pragma unroll
  for (int rr = 0; rr < 8; rr++) {
    const int r = w * 8 + rr;
    const float inv = 1.0f / l[rr];
    const long g = (long)(b * 1024 + qt * 64 + r) * Hd + h * DHh;
    O[g + ln]      = acc0[rr] * inv;
    O[g + ln + 32] = acc1[rr] * inv;
  }
}

// ---------------- fused residual + RMSNorm ----------------
__global__ void __launch_bounds__(256) rms_kernel(
    const float* __restrict__ in, const float* __restrict__ res,
    const float* __restrict__ g, float* __restrict__ out) {
  const int row = blockIdx.x, tid = threadIdx.x;
  __shared__ float buf[Hd];
  __shared__ float red[8];
  __shared__ float s_inv;
  const long base = (long)row * Hd;
  float ss = 0.f;
  for (int i = tid; i < Hd; i += 256) {
    float v = in[base + i] + res[base + i];
    buf[i] = v; ss += v * v;
  }
  #pragma unroll
  for (int o = 16; o; o >>= 1) ss += __shfl_xor_sync(0xffffffffu, ss, o);
  if ((tid & 31) == 0) red[tid >> 5] = ss;
  __syncthreads();
  if (tid == 0) {
    float tot = 0.f;
    #pragma unroll
    for (int i = 0; i < 8; i++) tot += red[i];
    s_inv = rsqrtf(tot * (1.0f / (float)Hd) + 1e-6f);
  }
  __syncthreads();
  const float inv = s_inv;
  for (int i = tid; i < Hd; i += 256) out[base + i] = buf[i] * inv * g[i];
}

// ---------------- host ----------------
static const int GEMM_SMEM = 65536;

static void run_gemm(const __nv_bfloat16* Ah, const __nv_bfloat16* Al,
                     const __nv_bfloat16* Bh, const __nv_bfloat16* Bl,
                     const float* bias, float* C, int M, int N, int K, bool gelu) {
  dim3 grid(N / 128, M / 128);
  if (gelu) gemm_mma_kernel<true ><<<grid, 256, GEMM_SMEM>>>(Ah, Al, Bh, Bl, bias, C, M, N, K);
  else      gemm_mma_kernel<false><<<grid, 256, GEMM_SMEM>>>(Ah, Al, Bh, Bl, bias, C, M, N, K);
}

extern "C" void kernel_launch(void* const* d_in, const int* in_sizes, int n_in,
                              void* d_out, int out_size) {
  const float* x    = (const float*)d_in[0];
  const float* y    = (const float*)d_in[1];
  const float* mask = (const float*)d_in[2];
  const float* Wq   = (const float*)d_in[3];
  const float* bq   = (const float*)d_in[4];
  const float* Wk   = (const float*)d_in[5];
  const float* bk   = (const float*)d_in[6];
  const float* Wv   = (const float*)d_in[7];
  const float* bv   = (const float*)d_in[8];
  const float* Wo   = (const float*)d_in[9];
  const float* bo   = (const float*)d_in[10];
  const float* g1   = (const float*)d_in[11];
  const float* Wi   = (const float*)d_in[12];
  const float* bi   = (const float*)d_in[13];
  const float* Wo2  = (const float*)d_in[14];
  const float* bo2  = (const float*)d_in[15];
  const float* g2   = (const float*)d_in[16];
  const int*   t    = (const int*)d_in[17];
  float* out = (float*)d_out;

  cudaFuncSetAttribute(gemm_mma_kernel<false>, cudaFuncAttributeMaxDynamicSharedMemorySize, GEMM_SMEM);
  cudaFuncSetAttribute(gemm_mma_kernel<true >, cudaFuncAttributeMaxDynamicSharedMemorySize, GEMM_SMEM);

  float *xs, *ys, *q, *k, *v, *ctx, *att, *tmp, *inter;
  cudaGetSymbolAddress((void**)&xs,    g_xs);
  cudaGetSymbolAddress((void**)&ys,    g_ys);
  cudaGetSymbolAddress((void**)&q,     g_q);
  cudaGetSymbolAddress((void**)&k,     g_k);
  cudaGetSymbolAddress((void**)&v,     g_v);
  cudaGetSymbolAddress((void**)&ctx,   g_ctx);
  cudaGetSymbolAddress((void**)&att,   g_att);
  cudaGetSymbolAddress((void**)&tmp,   g_tmp);
  cudaGetSymbolAddress((void**)&inter, g_inter);

  __nv_bfloat16 *aAh, *aAl, *aBh, *aBl;
  cudaGetSymbolAddress((void**)&aAh, g_actA_h);
  cudaGetSymbolAddress((void**)&aAl, g_actA_l);
  cudaGetSymbolAddress((void**)&aBh, g_actB_h);
  cudaGetSymbolAddress((void**)&aBl, g_actB_l);

  __nv_bfloat16 *wqh,*wql,*wkh,*wkl,*wvh,*wvl,*woh,*wol,*wih,*wil,*w2h,*w2l;
  cudaGetSymbolAddress((void**)&wqh, g_wq_h); cudaGetSymbolAddress((void**)&wql, g_wq_l);
  cudaGetSymbolAddress((void**)&wkh, g_wk_h); cudaGetSymbolAddress((void**)&wkl, g_wk_l);
  cudaGetSymbolAddress((void**)&wvh, g_wv_h); cudaGetSymbolAddress((void**)&wvl, g_wv_l);
  cudaGetSymbolAddress((void**)&woh, g_wo_h); cudaGetSymbolAddress((void**)&wol, g_wo_l);
  cudaGetSymbolAddress((void**)&wih, g_wi_h); cudaGetSymbolAddress((void**)&wil, g_wi_l);
  cudaGetSymbolAddress((void**)&w2h, g_w2_h); cudaGetSymbolAddress((void**)&w2l, g_w2_l);

  routing_kernel<<<TOK, 256>>>(x, y, t, xs, ys);

  // weight conversions (transposed to [N,K], bf16 hi/lo)
  cvt_wt_t_kernel<<<dim3(Hd/32, Hd/32), 256>>>(Wq,  wqh, wql, Hd, Hd);
  cvt_wt_t_kernel<<<dim3(Hd/32, Hd/32), 256>>>(Wk,  wkh, wkl, Hd, Hd);
  cvt_wt_t_kernel<<<dim3(Hd/32, Hd/32), 256>>>(Wv,  wvh, wvl, Hd, Hd);
  cvt_wt_t_kernel<<<dim3(Hd/32, Hd/32), 256>>>(Wo,  woh, wol, Hd, Hd);
  cvt_wt_t_kernel<<<dim3(Id/32, Hd/32), 256>>>(Wi,  wih, wil, Hd, Id);
  cvt_wt_t_kernel<<<dim3(Hd/32, Id/32), 256>>>(Wo2, w2h, w2l, Id, Hd);

  // activation splits
  cvt_act_kernel<<<TOK*Hd/2048, 256>>>(xs, aBh, aBl, TOK*Hd);
  cvt_act_kernel<<<TOK*Hd/2048, 256>>>(ys, aAh, aAl, TOK*Hd);

  run_gemm(aBh, aBl, wqh, wql, bq, q, TOK, Hd, Hd, false);
  run_gemm(aAh, aAl, wkh, wkl, bk, k, TOK, Hd, Hd, false);
  run_gemm(aAh, aAl, wvh, wvl, bv, v, TOK, Hd, Hd, false);

  attn_kernel<<<dim3(16, NHh, 4), 256>>>(q, k, v, mask, ctx);

  cvt_act_kernel<<<TOK*Hd/2048, 256>>>(ctx, aAh, aAl, TOK*Hd);
  run_gemm(aAh, aAl, woh, wol, bo, tmp, TOK, Hd, Hd, false);
  rms_kernel<<<TOK, 256>>>(tmp, xs, g1, att);

  cvt_act_kernel<<<TOK*Hd/2048, 256>>>(att, aAh, aAl, TOK*Hd);
  run_gemm(aAh, aAl, wih, wil, bi, inter, TOK, Id, Hd, true);

  cvt_act_kernel<<<TOK*Id/2048, 256>>>(inter, aAh, aAl, TOK*Id);
  run_gemm(aAh, aAl, w2h, w2l, bo2, tmp, TOK, Hd, Id, false);
  rms_kernel<<<TOK, 256>>>(tmp, att, g2, out);
}

// round 4
// speedup vs baseline: 3.3561x; 2.0784x over previous
#include <cuda_runtime.h>
#include <cuda_bf16.h>
#include <math.h>
#include <stdint.h>

#define TOK 4096        // B*S
#define Hd  1024
#define Id  4096
#define NHh 16
#define DHh 64

// ---------------- scratch (device globals; no allocs) ----------------
__device__ float g_xs [TOK * Hd];
__device__ float g_att[TOK * Hd];
__device__ float g_tmp[TOK * Hd];

// bf16 hi/lo buffers
__device__ __nv_bfloat16 g_xh[TOK * Hd], g_xl[TOK * Hd];
__device__ __nv_bfloat16 g_yh[TOK * Hd], g_yl[TOK * Hd];
__device__ __nv_bfloat16 g_qh[TOK * Hd], g_ql[TOK * Hd];
__device__ __nv_bfloat16 g_kh[TOK * Hd], g_kl[TOK * Hd];
__device__ __nv_bfloat16 g_vh[TOK * Hd], g_vl[TOK * Hd];
__device__ __nv_bfloat16 g_ch[TOK * Hd], g_cl[TOK * Hd];
__device__ __nv_bfloat16 g_ah[TOK * Hd], g_al[TOK * Hd];
__device__ __nv_bfloat16 g_ih[TOK * Id], g_il[TOK * Id];

// transposed bf16 weights [N, K]
__device__ __nv_bfloat16 g_wq_h[Hd * Hd], g_wq_l[Hd * Hd];
__device__ __nv_bfloat16 g_wk_h[Hd * Hd], g_wk_l[Hd * Hd];
__device__ __nv_bfloat16 g_wv_h[Hd * Hd], g_wv_l[Hd * Hd];
__device__ __nv_bfloat16 g_wo_h[Hd * Hd], g_wo_l[Hd * Hd];
__device__ __nv_bfloat16 g_wi_h[Id * Hd], g_wi_l[Id * Hd];
__device__ __nv_bfloat16 g_w2_h[Hd * Id], g_w2_l[Hd * Id];

// ---------------- helpers ----------------
__device__ __forceinline__ uint32_t smem_u32(const void* p) {
  uint32_t a;
  asm("{ .reg .u64 t; cvta.to.shared.u64 t, %1; cvt.u32.u64 %0, t; }" : "=r"(a) : "l"(p));
  return a;
}
__device__ __forceinline__ void cp_async16(uint32_t dst, const void* src) {
  asm volatile("cp.async.cg.shared.global [%0], [%1], 16;" :: "r"(dst), "l"(src) : "memory");
}
#define CP_COMMIT() asm volatile("cp.async.commit_group;" ::: "memory")
#define CP_WAIT(n)  asm volatile("cp.async.wait_group %0;" :: "n"(n) : "memory")

__device__ __forceinline__ void ldsm4(uint32_t* r, uint32_t addr) {
  asm volatile("ldmatrix.sync.aligned.m8n8.x4.shared.b16 {%0,%1,%2,%3}, [%4];"
               : "=r"(r[0]), "=r"(r[1]), "=r"(r[2]), "=r"(r[3]) : "r"(addr));
}
__device__ __forceinline__ void ldsm4t(uint32_t* r, uint32_t addr) {
  asm volatile("ldmatrix.sync.aligned.m8n8.x4.trans.shared.b16 {%0,%1,%2,%3}, [%4];"
               : "=r"(r[0]), "=r"(r[1]), "=r"(r[2]), "=r"(r[3]) : "r"(addr));
}
__device__ __forceinline__ void mma16816(float* d, const uint32_t* a, const uint32_t* b) {
  asm volatile("mma.sync.aligned.m16n8k16.row.col.f32.bf16.bf16.f32 "
               "{%0,%1,%2,%3}, {%4,%5,%6,%7}, {%8,%9}, {%0,%1,%2,%3};"
               : "+f"(d[0]), "+f"(d[1]), "+f"(d[2]), "+f"(d[3])
               : "r"(a[0]), "r"(a[1]), "r"(a[2]), "r"(a[3]), "r"(b[0]), "r"(b[1]));
}
__device__ __forceinline__ uint32_t packbf(float a, float b) {
  __nv_bfloat162 t = __floats2bfloat162_rn(a, b);
  return *(uint32_t*)&t;
}
__device__ __forceinline__ void split_hl(float v, __nv_bfloat16& h, __nv_bfloat16& l) {
  h = __float2bfloat16(v);
  l = __float2bfloat16(v - __bfloat162float(h));
}

// swizzle for 64B rows (GEMM, BK=32) and 128B rows (attention tiles)
__device__ __forceinline__ uint32_t swz64(int row, int c16) {
  return (uint32_t)(row * 64 + ((c16 ^ ((row >> 1) & 3)) << 4));
}
__device__ __forceinline__ uint32_t swz128(int row, int c16) {
  return (uint32_t)(row * 128 + ((c16 ^ (row & 7)) << 4));
}

// ---------------- weight conversion (transpose + hi/lo split) ----------------
__global__ void __launch_bounds__(256) cvt_wt_t_kernel(
    const float* __restrict__ W, __nv_bfloat16* __restrict__ Th,
    __nv_bfloat16* __restrict__ Tl, int K, int N) {
  __shared__ float t[32][33];
  const int nb = blockIdx.x * 32, kb = blockIdx.y * 32;
  const int tx = threadIdx.x & 31, ty = threadIdx.x >> 5;
  #pragma unroll
  for (int i = 0; i < 32; i += 8)
    t[ty + i][tx] = W[(size_t)(kb + ty + i) * N + nb + tx];
  __syncthreads();
  #pragma unroll
  for (int i = 0; i < 32; i += 8) {
    float v = t[tx][ty + i];
    __nv_bfloat16 h, l; split_hl(v, h, l);
    size_t o = (size_t)(nb + ty + i) * K + kb + tx;
    Th[o] = h; Tl[o] = l;
  }
}

// ---------------- HMMA GEMM: C[M,N] = A @ B^T (B stored [N,K]), bf16x3 ----------------
// 128x128 tile, BK=32, 8 warps (2m x 4n), warp tile 64x32.
template<bool GELU, bool SPLIT>
__global__ void __launch_bounds__(256, 1)
gemm_mma_kernel(const __nv_bfloat16* __restrict__ Ah, const __nv_bfloat16* __restrict__ Al,
                const __nv_bfloat16* __restrict__ Bh, const __nv_bfloat16* __restrict__ Bl,
                const float* __restrict__ bias, float* __restrict__ C,
                __nv_bfloat16* __restrict__ Ch, __nv_bfloat16* __restrict__ Cl,
                int M, int N, int K) {
  extern __shared__ __align__(128) char sm[];
  const uint32_t smb = smem_u32(sm);
  const int tid = threadIdx.x;
  const int wid = tid >> 5, lane = tid & 31;
  const int bm = blockIdx.y * 128, bn = blockIdx.x * 128;
  const int warp_m = wid & 1, warp_n = wid >> 1;
  const int NK = K >> 5;

  auto stage_off = [](int s, int mat) -> uint32_t { return (uint32_t)(s * 32768 + mat * 8192); };

  auto load_stage = [&](int kt, int s) {
    const int koff = kt * 32;
    #pragma unroll
    for (int j = 0; j < 2; j++) {
      const int ch = tid + j * 256;
      const int row = ch >> 2, c = ch & 3;
      const uint32_t d = swz64(row, c);
      const size_t ga = (size_t)(bm + row) * K + koff + c * 8;
      const size_t gb = (size_t)(bn + row) * K + koff + c * 8;
      cp_async16(smb + stage_off(s, 0) + d, Ah + ga);
      cp_async16(smb + stage_off(s, 1) + d, Al + ga);
      cp_async16(smb + stage_off(s, 2) + d, Bh + gb);
      cp_async16(smb + stage_off(s, 3) + d, Bl + gb);
    }
  };

  float acc[4][4][4];
  #pragma unroll
  for (int i = 0; i < 4; i++)
    #pragma unroll
    for (int j = 0; j < 4; j++)
      #pragma unroll
      for (int q = 0; q < 4; q++) acc[i][j][q] = 0.f;

  load_stage(0, 0);
  CP_COMMIT();

  const int la_row = (lane & 7) + ((lane >> 3) & 1) * 8;
  const int la_c   = (lane >> 4);
  const int lb_row = (lane & 7) + (lane >> 4) * 8;
  const int lb_c   = (lane >> 3) & 1;

  for (int kt = 0; kt < NK; kt++) {
    const int s = kt & 1;
    if (kt + 1 < NK) { load_stage(kt + 1, 1 - s); CP_COMMIT(); CP_WAIT(1); }
    else             { CP_WAIT(0); }
    __syncthreads();

    const uint32_t baseAh = smb + stage_off(s, 0);
    const uint32_t baseAl = smb + stage_off(s, 1);
    const uint32_t baseBh = smb + stage_off(s, 2);
    const uint32_t baseBl = smb + stage_off(s, 3);

    #pragma unroll
    for (int ks = 0; ks < 2; ks++) {
      uint32_t aH[4][4], aL[4][4], bH[2][4], bL[2][4];
      #pragma unroll
      for (int tm = 0; tm < 4; tm++) {
        const int row = warp_m * 64 + tm * 16 + la_row;
        const int c   = ks * 2 + la_c;
        ldsm4(aH[tm], baseAh + swz64(row, c));
        ldsm4(aL[tm], baseAl + swz64(row, c));
      }
      #pragma unroll
      for (int tn2 = 0; tn2 < 2; tn2++) {
        const int row = warp_n * 32 + tn2 * 16 + lb_row;
        const int c   = ks * 2 + lb_c;
        ldsm4(bH[tn2], baseBh + swz64(row, c));
        ldsm4(bL[tn2], baseBl + swz64(row, c));
      }
      #pragma unroll
      for (int tm = 0; tm < 4; tm++)
        #pragma unroll
        for (int tn = 0; tn < 4; tn++) {
          const uint32_t* bh = &bH[tn >> 1][(tn & 1) * 2];
          const uint32_t* bl = &bL[tn >> 1][(tn & 1) * 2];
          mma16816(acc[tm][tn], aH[tm], bh);
          mma16816(acc[tm][tn], aH[tm], bl);
          mma16816(acc[tm][tn], aL[tm], bh);
        }
    }
    __syncthreads();
  }

  // epilogue
  const int g = lane >> 2, tq = lane & 3;
  #pragma unroll
  for (int tm = 0; tm < 4; tm++) {
    #pragma unroll
    for (int tn = 0; tn < 4; tn++) {
      const int col = bn + warp_n * 32 + tn * 8 + tq * 2;
      const float b0 = bias[col], b1 = bias[col + 1];
      #pragma unroll
      for (int half = 0; half < 2; half++) {
        const int row = bm + warp_m * 64 + tm * 16 + g + half * 8;
        float vx = acc[tm][tn][half * 2 + 0] + b0;
        float vy = acc[tm][tn][half * 2 + 1] + b1;
        if (GELU) {
          vx = 0.5f * vx * (1.0f + erff(vx * 0.7071067811865476f));
          vy = 0.5f * vy * (1.0f + erff(vy * 0.7071067811865476f));
        }
        if (SPLIT) {
          __nv_bfloat16 hx, lx, hy, ly;
          split_hl(vx, hx, lx); split_hl(vy, hy, ly);
          *(uint32_t*)(Ch + (size_t)row * N + col) = packbf(__bfloat162float(hx), __bfloat162float(hy));
          *(uint32_t*)(Cl + (size_t)row * N + col) = packbf(__bfloat162float(lx), __bfloat162float(ly));
        } else {
          float2 v; v.x = vx; v.y = vy;
          *(float2*)(C + (size_t)row * N + col) = v;
        }
      }
    }
  }
}

// ---------------- HMMA flash attention (bf16x3, fp32 accum, online softmax) ----------------
// grid (S/64, NH, B), 128 threads = 4 warps; warp owns 16 q rows; K/V tiles of 64 keys.
// smem: Qh(8K) Ql(8K) + 2 stages x [Kh Kl Vh Vl](32K) = 80KB.
__global__ void __launch_bounds__(128, 2)
attn_mma_kernel(const __nv_bfloat16* __restrict__ Qh, const __nv_bfloat16* __restrict__ Ql,
                const __nv_bfloat16* __restrict__ Kh, const __nv_bfloat16* __restrict__ Kl,
                const __nv_bfloat16* __restrict__ Vh, const __nv_bfloat16* __restrict__ Vl,
                const float* __restrict__ mask,
                __nv_bfloat16* __restrict__ Ch, __nv_bfloat16* __restrict__ Cl) {
  extern __shared__ __align__(128) char sm[];
  const uint32_t smb = smem_u32(sm);
  const int tid = threadIdx.x;
  const int warp = tid >> 5, lane = tid & 31;
  const int qt = blockIdx.x, h = blockIdx.y, b = blockIdx.z;
  const int g = lane >> 2, tq = lane & 3;

  const int la_row = (lane & 7) + ((lane >> 3) & 1) * 8;   // A frag
  const int la_c   = (lane >> 4);
  const int lb_row = (lane & 7) + (lane >> 4) * 8;         // B frag (non-trans)
  const int lb_c   = (lane >> 3) & 1;
  const int lv_row = (lane & 7) + ((lane >> 3) & 1) * 8;   // B frag (trans, V)
  const int lv_c   = (lane >> 4);

  // ---- load Q (both matrices) + stage 0 ----
  {
    #pragma unroll
    for (int j = 0; j < 4; j++) {
      const int ch = tid + j * 128;
      const int row = ch >> 3, c = ch & 7;
      const uint32_t d = swz128(row, c);
      const size_t gq = (size_t)(b * 1024 + qt * 64 + row) * Hd + h * 64 + c * 8;
      cp_async16(smb + d, Qh + gq);
      cp_async16(smb + 8192 + d, Ql + gq);
    }
  }
  auto load_kv = [&](int kt, int s) {
    const uint32_t so = smb + 16384 + s * 32768;
    #pragma unroll
    for (int j = 0; j < 4; j++) {
      const int ch = tid + j * 128;
      const int row = ch >> 3, c = ch & 7;
      const uint32_t d = swz128(row, c);
      const size_t gk = (size_t)(b * 1024 + kt * 64 + row) * Hd + h * 64 + c * 8;
      cp_async16(so + d,         Kh + gk);
      cp_async16(so + 8192 + d,  Kl + gk);
      cp_async16(so + 16384 + d, Vh + gk);
      cp_async16(so + 24576 + d, Vl + gk);
    }
  };
  load_kv(0, 0);
  CP_COMMIT();

  float m0 = -1e30f, m1 = -1e30f, l0 = 0.f, l1 = 0.f;
  float oacc[8][4];
  #pragma unroll
  for (int j = 0; j < 8; j++)
    #pragma unroll
    for (int q = 0; q < 4; q++) oacc[j][q] = 0.f;

  for (int kt = 0; kt < 16; kt++) {
    const int s = kt & 1;
    if (kt + 1 < 16) { load_kv(kt + 1, 1 - s); CP_COMMIT(); CP_WAIT(1); }
    else             { CP_WAIT(0); }
    __syncthreads();

    const uint32_t sK = smb + 16384 + s * 32768;
    const uint32_t sV = sK + 16384;

    // ---- S = Q K^T (16 q x 64 keys per warp) ----
    float sacc[8][4];
    #pragma unroll
    for (int j = 0; j < 8; j++)
      #pragma unroll
      for (int q = 0; q < 4; q++) sacc[j][q] = 0.f;

    #pragma unroll
    for (int kc = 0; kc < 4; kc++) {
      uint32_t qh4[4], ql4[4];
      const uint32_t qa = swz128(warp * 16 + la_row, kc * 2 + la_c);
      ldsm4(qh4, smb + qa);
      ldsm4(ql4, smb + 8192 + qa);
      #pragma unroll
      for (int n16 = 0; n16 < 4; n16++) {
        uint32_t kh4[4], kl4[4];
        const uint32_t ka = swz128(n16 * 16 + lb_row, kc * 2 + lb_c);
        ldsm4(kh4, sK + ka);
        ldsm4(kl4, sK + 8192 + ka);
        mma16816(sacc[2 * n16],     qh4, kh4);
        mma16816(sacc[2 * n16],     qh4, kl4);
        mma16816(sacc[2 * n16],     ql4, kh4);
        mma16816(sacc[2 * n16 + 1], qh4, kh4 + 2);
        mma16816(sacc[2 * n16 + 1], qh4, kl4 + 2);
        mma16816(sacc[2 * n16 + 1], ql4, kh4 + 2);
      }
    }

    // ---- online softmax ----
    const float* mrow = mask + b * 1024 + kt * 64;
    float mx0 = -1e30f, mx1 = -1e30f;
    #pragma unroll
    for (int j = 0; j < 8; j++) {
      const float2 mv = *(const float2*)(mrow + j * 8 + 2 * tq);
      sacc[j][0] = sacc[j][0] * 0.125f + mv.x;
      sacc[j][1] = sacc[j][1] * 0.125f + mv.y;
      sacc[j][2] = sacc[j][2] * 0.125f + mv.x;
      sacc[j][3] = sacc[j][3] * 0.125f + mv.y;
      mx0 = fmaxf(mx0, fmaxf(sacc[j][0], sacc[j][1]));
      mx1 = fmaxf(mx1, fmaxf(sacc[j][2], sacc[j][3]));
    }
    mx0 = fmaxf(mx0, __shfl_xor_sync(0xffffffffu, mx0, 1));
    mx0 = fmaxf(mx0, __shfl_xor_sync(0xffffffffu, mx0, 2));
    mx1 = fmaxf(mx1, __shfl_xor_sync(0xffffffffu, mx1, 1));
    mx1 = fmaxf(mx1, __shfl_xor_sync(0xffffffffu, mx1, 2));
    const float mn0 = fmaxf(m0, mx0), mn1 = fmaxf(m1, mx1);
    const float rs0 = __expf(m0 - mn0), rs1 = __expf(m1 - mn1);
    m0 = mn0; m1 = mn1;

    float sum0 = 0.f, sum1 = 0.f;
    uint32_t ph01[8], ph23[8], pl01[8], pl23[8];
    #pragma unroll
    for (int j = 0; j < 8; j++) {
      const float p0 = __expf(sacc[j][0] - mn0), p1 = __expf(sacc[j][1] - mn0);
      const float p2 = __expf(sacc[j][2] - mn1), p3 = __expf(sacc[j][3] - mn1);
      sum0 += p0 + p1; sum1 += p2 + p3;
      __nv_bfloat16 h0, l0b, h1, l1b, h2, l2b, h3, l3b;
      split_hl(p0, h0, l0b); split_hl(p1, h1, l1b);
      split_hl(p2, h2, l2b); split_hl(p3, h3, l3b);
      ph01[j] = packbf(__bfloat162float(h0), __bfloat162float(h1));
      pl01[j] = packbf(__bfloat162float(l0b), __bfloat162float(l1b));
      ph23[j] = packbf(__bfloat162float(h2), __bfloat162float(h3));
      pl23[j] = packbf(__bfloat162float(l2b), __bfloat162float(l3b));
      oacc[j][0] *= rs0; oacc[j][1] *= rs0;
      oacc[j][2] *= rs1; oacc[j][3] *= rs1;
    }
    sum0 += __shfl_xor_sync(0xffffffffu, sum0, 1);
    sum0 += __shfl_xor_sync(0xffffffffu, sum0, 2);
    sum1 += __shfl_xor_sync(0xffffffffu, sum1, 1);
    sum1 += __shfl_xor_sync(0xffffffffu, sum1, 2);
    l0 = l0 * rs0 + sum0;
    l1 = l1 * rs1 + sum1;

    // ---- O += P V ----
    #pragma unroll
    for (int kc = 0; kc < 4; kc++) {
      uint32_t ah[4] = {ph01[2*kc], ph23[2*kc], ph01[2*kc+1], ph23[2*kc+1]};
      uint32_t al[4] = {pl01[2*kc], pl23[2*kc], pl01[2*kc+1], pl23[2*kc+1]};
      #pragma unroll
      for (int n16 = 0; n16 < 4; n16++) {
        uint32_t vh4[4], vl4[4];
        const uint32_t va = swz128(kc * 16 + lv_row, n16 * 2 + lv_c);
        ldsm4t(vh4, sV + va);
        ldsm4t(vl4, sV + 8192 + va);
        mma16816(oacc[2 * n16],     ah, vh4);
        mma16816(oacc[2 * n16],     ah, vl4);
        mma16816(oacc[2 * n16],     al, vh4);
        mma16816(oacc[2 * n16 + 1], ah, vh4 + 2);
        mma16816(oacc[2 * n16 + 1], ah, vl4 + 2);
        mma16816(oacc[2 * n16 + 1], al, vh4 + 2);
      }
    }
    __syncthreads();
  }

  // ---- epilogue: /l, hi/lo split, store ----
  const float inv0 = 1.f / l0, inv1 = 1.f / l1;
  const int row0 = b * 1024 + qt * 64 + warp * 16 + g;
  #pragma unroll
  for (int j = 0; j < 8; j++) {
    const int col = h * 64 + (j >> 1) * 16 + (j & 1) * 8 + 2 * tq;
    const float v0 = oacc[j][0] * inv0, v1 = oacc[j][1] * inv0;
    const float v2 = oacc[j][2] * inv1, v3 = oacc[j][3] * inv1;
    __nv_bfloat16 h0, l0b, h1, l1b, h2, l2b, h3, l3b;
    split_hl(v0, h0, l0b); split_hl(v1, h1, l1b);
    split_hl(v2, h2, l2b); split_hl(v3, h3, l3b);
    *(uint32_t*)(Ch + (size_t)row0 * Hd + col)       = packbf(__bfloat162float(h0), __bfloat162float(h1));
    *(uint32_t*)(Cl + (size_t)row0 * Hd + col)       = packbf(__bfloat162float(l0b), __bfloat162float(l1b));
    *(uint32_t*)(Ch + (size_t)(row0 + 8) * Hd + col) = packbf(__bfloat162float(h2), __bfloat162float(h3));
    *(uint32_t*)(Cl + (size_t)(row0 + 8) * Hd + col) = packbf(__bfloat162float(l2b), __bfloat162float(l3b));
  }
}

// ---------------- routing (fused hi/lo split outputs) ----------------
__global__ void __launch_bounds__(256) routing_kernel(
    const float* __restrict__ x, const float* __restrict__ y,
    const int* __restrict__ tptr,
    float* __restrict__ xs,
    __nv_bfloat16* __restrict__ xh, __nv_bfloat16* __restrict__ xl,
    __nv_bfloat16* __restrict__ yh, __nv_bfloat16* __restrict__ yl) {
  const int token = blockIdx.x, tid = threadIdx.x;
  const long base = (long)token * Hd;
  float sxx = 0.f, sxy = 0.f, syy = 0.f;
  for (int i = tid; i < Hd; i += 256) {
    float a = x[base + i], bb = y[base + i];
    sxx += a * a; sxy += a * bb; syy += bb * bb;
  }
  #pragma unroll
  for (int o = 16; o; o >>= 1) {
    sxx += __shfl_xor_sync(0xffffffffu, sxx, o);
    sxy += __shfl_xor_sync(0xffffffffu, sxy, o);
    syy += __shfl_xor_sync(0xffffffffu, syy, o);
  }
  __shared__ float red[8][3];
  __shared__ float sc[2];
  if ((tid & 31) == 0) { red[tid >> 5][0] = sxx; red[tid >> 5][1] = sxy; red[tid >> 5][2] = syy; }
  __syncthreads();
  if (tid == 0) {
    float a = 0.f, bb = 0.f, c = 0.f;
    #pragma unroll
    for (int i = 0; i < 8; i++) { a += red[i][0]; bb += red[i][1]; c += red[i][2]; }
    const int t = *tptr;
    float b1 = 0.f, b2 = 0.f, c1 = 0.5f, c2 = 0.5f;
    for (int it = 0; it < t; it++) {
      if (it > 0) {
        float mm = fmaxf(b1, b2);
        float e1 = expf(b1 - mm), e2 = expf(b2 - mm);
        float inv = 1.0f / (e1 + e2);
        c1 = e1 * inv; c2 = e2 * inv;
      }
      float vv = c1 * c1 * a + 2.0f * c1 * c2 * bb + c2 * c2 * c;
      float n  = sqrtf(vv);
      float f  = n / (1.0f + vv);
      b1 += f * (c1 * a  + c2 * bb);
      b2 += f * (c1 * bb + c2 * c );
    }
    sc[0] = c1; sc[1] = c2;
  }
  __syncthreads();
  const float c1 = sc[0], c2 = sc[1];
  for (int i = tid; i < Hd; i += 256) {
    const float vx = c1 * x[base + i];
    const float vy = c2 * y[base + i];
    xs[base + i] = vx;
    __nv_bfloat16 hh, ll;
    split_hl(vx, hh, ll); xh[base + i] = hh; xl[base + i] = ll;
    split_hl(vy, hh, ll); yh[base + i] = hh; yl[base + i] = ll;
  }
}

// ---------------- fused residual + RMSNorm (optional hi/lo output) ----------------
template<bool SPLIT>
__global__ void __launch_bounds__(256) rms_kernel(
    const float* __restrict__ in, const float* __restrict__ res,
    const float* __restrict__ g, float* __restrict__ out,
    __nv_bfloat16* __restrict__ oh, __nv_bfloat16* __restrict__ ol) {
  const int row = blockIdx.x, tid = threadIdx.x;
  __shared__ float buf[Hd];
  __shared__ float red[8];
  __shared__ float s_inv;
  const long base = (long)row * Hd;
  float ss = 0.f;
  for (int i = tid; i < Hd; i += 256) {
    float v = in[base + i] + res[base + i];
    buf[i] = v; ss += v * v;
  }
  #pragma unroll
  for (int o = 16; o; o >>= 1) ss += __shfl_xor_sync(0xffffffffu, ss, o);
  if ((tid & 31) == 0) red[tid >> 5] = ss;
  __syncthreads();
  if (tid == 0) {
    float tot = 0.f;
    #pragma unroll
    for (int i = 0; i < 8; i++) tot += red[i];
    s_inv = rsqrtf(tot * (1.0f / (float)Hd) + 1e-6f);
  }
  __syncthreads();
  const float inv = s_inv;
  for (int i = tid; i < Hd; i += 256) {
    const float v = buf[i] * inv * g[i];
    out[base + i] = v;
    if (SPLIT) {
      __nv_bfloat16 hh, ll;
      split_hl(v, hh, ll);
      oh[base + i] = hh; ol[base + i] = ll;
    }
  }
}

// ---------------- host ----------------
static const int GEMM_SMEM = 65536;
static const int ATTN_SMEM = 81920;

static void run_gemm(const __nv_bfloat16* Ah, const __nv_bfloat16* Al,
                     const __nv_bfloat16* Bh, const __nv_bfloat16* Bl,
                     const float* bias, float* C,
                     __nv_bfloat16* Ch, __nv_bfloat16* Cl,
                     int M, int N, int K, bool gelu, bool split) {
  dim3 grid(N / 128, M / 128);
  if (split) {
    if (gelu) gemm_mma_kernel<true , true ><<<grid, 256, GEMM_SMEM>>>(Ah, Al, Bh, Bl, bias, C, Ch, Cl, M, N, K);
    else      gemm_mma_kernel<false, true ><<<grid, 256, GEMM_SMEM>>>(Ah, Al, Bh, Bl, bias, C, Ch, Cl, M, N, K);
  } else {
    gemm_mma_kernel<false, false><<<grid, 256, GEMM_SMEM>>>(Ah, Al, Bh, Bl, bias, C, Ch, Cl, M, N, K);
  }
}

extern "C" void kernel_launch(void* const* d_in, const int* in_sizes, int n_in,
                              void* d_out, int out_size) {
  const float* x    = (const float*)d_in[0];
  const float* y    = (const float*)d_in[1];
  const float* mask = (const float*)d_in[2];
  const float* Wq   = (const float*)d_in[3];
  const float* bq   = (const float*)d_in[4];
  const float* Wk   = (const float*)d_in[5];
  const float* bk   = (const float*)d_in[6];
  const float* Wv   = (const float*)d_in[7];
  const float* bv   = (const float*)d_in[8];
  const float* Wo   = (const float*)d_in[9];
  const float* bo   = (const float*)d_in[10];
  const float* g1   = (const float*)d_in[11];
  const float* Wi   = (const float*)d_in[12];
  const float* bi   = (const float*)d_in[13];
  const float* Wo2  = (const float*)d_in[14];
  const float* bo2  = (const float*)d_in[15];
  const float* g2   = (const float*)d_in[16];
  const int*   t    = (const int*)d_in[17];
  float* out = (float*)d_out;

  cudaFuncSetAttribute(gemm_mma_kernel<false,false>, cudaFuncAttributeMaxDynamicSharedMemorySize, GEMM_SMEM);
  cudaFuncSetAttribute(gemm_mma_kernel<false,true >, cudaFuncAttributeMaxDynamicSharedMemorySize, GEMM_SMEM);
  cudaFuncSetAttribute(gemm_mma_kernel<true ,true >, cudaFuncAttributeMaxDynamicSharedMemorySize, GEMM_SMEM);
  cudaFuncSetAttribute(attn_mma_kernel, cudaFuncAttributeMaxDynamicSharedMemorySize, ATTN_SMEM);

  float *xs, *att, *tmp;
  cudaGetSymbolAddress((void**)&xs,  g_xs);
  cudaGetSymbolAddress((void**)&att, g_att);
  cudaGetSymbolAddress((void**)&tmp, g_tmp);

  __nv_bfloat16 *xh,*xl,*yh,*yl,*qh,*ql,*kh,*kl,*vh,*vl,*ch,*cl,*ah,*al,*ih,*il;
  cudaGetSymbolAddress((void**)&xh, g_xh); cudaGetSymbolAddress((void**)&xl, g_xl);
  cudaGetSymbolAddress((void**)&yh, g_yh); cudaGetSymbolAddress((void**)&yl, g_yl);
  cudaGetSymbolAddress((void**)&qh, g_qh); cudaGetSymbolAddress((void**)&ql, g_ql);
  cudaGetSymbolAddress((void**)&kh, g_kh); cudaGetSymbolAddress((void**)&kl, g_kl);
  cudaGetSymbolAddress((void**)&vh, g_vh); cudaGetSymbolAddress((void**)&vl, g_vl);
  cudaGetSymbolAddress((void**)&ch, g_ch); cudaGetSymbolAddress((void**)&cl, g_cl);
  cudaGetSymbolAddress((void**)&ah, g_ah); cudaGetSymbolAddress((void**)&al, g_al);
  cudaGetSymbolAddress((void**)&ih, g_ih); cudaGetSymbolAddress((void**)&il, g_il);

  __nv_bfloat16 *wqh,*wql,*wkh,*wkl,*wvh,*wvl,*woh,*wol,*wih,*wil,*w2h,*w2l;
  cudaGetSymbolAddress((void**)&wqh, g_wq_h); cudaGetSymbolAddress((void**)&wql, g_wq_l);
  cudaGetSymbolAddress((void**)&wkh, g_wk_h); cudaGetSymbolAddress((void**)&wkl, g_wk_l);
  cudaGetSymbolAddress((void**)&wvh, g_wv_h); cudaGetSymbolAddress((void**)&wvl, g_wv_l);
  cudaGetSymbolAddress((void**)&woh, g_wo_h); cudaGetSymbolAddress((void**)&wol, g_wo_l);
  cudaGetSymbolAddress((void**)&wih, g_wi_h); cudaGetSymbolAddress((void**)&wil, g_wi_l);
  cudaGetSymbolAddress((void**)&w2h, g_w2_h); cudaGetSymbolAddress((void**)&w2l, g_w2_l);

  routing_kernel<<<TOK, 256>>>(x, y, t, xs, xh, xl, yh, yl);

  cvt_wt_t_kernel<<<dim3(Hd/32, Hd/32), 256>>>(Wq,  wqh, wql, Hd, Hd);
  cvt_wt_t_kernel<<<dim3(Hd/32, Hd/32), 256>>>(Wk,  wkh, wkl, Hd, Hd);
  cvt_wt_t_kernel<<<dim3(Hd/32, Hd/32), 256>>>(Wv,  wvh, wvl, Hd, Hd);
  cvt_wt_t_kernel<<<dim3(Hd/32, Hd/32), 256>>>(Wo,  woh, wol, Hd, Hd);
  cvt_wt_t_kernel<<<dim3(Id/32, Hd/32), 256>>>(Wi,  wih, wil, Hd, Id);
  cvt_wt_t_kernel<<<dim3(Hd/32, Id/32), 256>>>(Wo2, w2h, w2l, Id, Hd);

  run_gemm(xh, xl, wqh, wql, bq, nullptr, qh, ql, TOK, Hd, Hd, false, true);
  run_gemm(yh, yl, wkh, wkl, bk, nullptr, kh, kl, TOK, Hd, Hd, false, true);
  run_gemm(yh, yl, wvh, wvl, bv, nullptr, vh, vl, TOK, Hd, Hd, false, true);

  attn_mma_kernel<<<dim3(16, NHh, 4), 128, ATTN_SMEM>>>(qh, ql, kh, kl, vh, vl, mask, ch, cl);

  run_gemm(ch, cl, woh, wol, bo, tmp, nullptr, nullptr, TOK, Hd, Hd, false, false);
  rms_kernel<true ><<<TOK, 256>>>(tmp, xs, g1, att, ah, al);

  run_gemm(ah, al, wih, wil, bi, nullptr, ih, il, TOK, Id, Hd, true, true);
  run_gemm(ih, il, w2h, w2l, bo2, tmp, nullptr, nullptr, TOK, Hd, Id, false, false);
  rms_kernel<false><<<TOK, 256>>>(tmp, att, g2, out, nullptr, nullptr);
}

// round 5
// speedup vs baseline: 4.4443x; 1.3242x over previous
#include <cuda_runtime.h>
#include <cuda_fp16.h>
#include <math.h>
#include <stdint.h>

#define TOK 4096        // B*S
#define Hd  1024
#define Id  4096
#define NHh 16
#define DHh 64

// ---------------- scratch (device globals; no allocs) ----------------
__device__ float g_xs [TOK * Hd];
__device__ float g_att[TOK * Hd];
__device__ float g_tmp[TOK * Hd];

// fp16 buffers (A-side operands split hi/lo; B-side single)
__device__ __half g_xh[TOK * Hd], g_xl[TOK * Hd];
__device__ __half g_yh[TOK * Hd], g_yl[TOK * Hd];
__device__ __half g_qh[TOK * Hd], g_ql[TOK * Hd];
__device__ __half g_kh[TOK * Hd];
__device__ __half g_vh[TOK * Hd];
__device__ __half g_ch[TOK * Hd], g_cl[TOK * Hd];
__device__ __half g_ah[TOK * Hd], g_al[TOK * Hd];
__device__ __half g_ih[TOK * Id], g_il[TOK * Id];

// transposed fp16 weights [N, K]
__device__ __half g_wq[Hd * Hd];
__device__ __half g_wk[Hd * Hd];
__device__ __half g_wv[Hd * Hd];
__device__ __half g_wo[Hd * Hd];
__device__ __half g_wi[Id * Hd];
__device__ __half g_w2[Hd * Id];

// ---------------- helpers ----------------
__device__ __forceinline__ uint32_t smem_u32(const void* p) {
  uint32_t a;
  asm("{ .reg .u64 t; cvta.to.shared.u64 t, %1; cvt.u32.u64 %0, t; }" : "=r"(a) : "l"(p));
  return a;
}
__device__ __forceinline__ void cp_async16(uint32_t dst, const void* src) {
  asm volatile("cp.async.cg.shared.global [%0], [%1], 16;" :: "r"(dst), "l"(src) : "memory");
}
#define CP_COMMIT() asm volatile("cp.async.commit_group;" ::: "memory")
#define CP_WAIT(n)  asm volatile("cp.async.wait_group %0;" :: "n"(n) : "memory")

__device__ __forceinline__ void ldsm4(uint32_t* r, uint32_t addr) {
  asm volatile("ldmatrix.sync.aligned.m8n8.x4.shared.b16 {%0,%1,%2,%3}, [%4];"
               : "=r"(r[0]), "=r"(r[1]), "=r"(r[2]), "=r"(r[3]) : "r"(addr));
}
__device__ __forceinline__ void ldsm4t(uint32_t* r, uint32_t addr) {
  asm volatile("ldmatrix.sync.aligned.m8n8.x4.trans.shared.b16 {%0,%1,%2,%3}, [%4];"
               : "=r"(r[0]), "=r"(r[1]), "=r"(r[2]), "=r"(r[3]) : "r"(addr));
}
__device__ __forceinline__ void mma16816(float* d, const uint32_t* a, const uint32_t* b) {
  asm volatile("mma.sync.aligned.m16n8k16.row.col.f32.f16.f16.f32 "
               "{%0,%1,%2,%3}, {%4,%5,%6,%7}, {%8,%9}, {%0,%1,%2,%3};"
               : "+f"(d[0]), "+f"(d[1]), "+f"(d[2]), "+f"(d[3])
               : "r"(a[0]), "r"(a[1]), "r"(a[2]), "r"(a[3]), "r"(b[0]), "r"(b[1]));
}
__device__ __forceinline__ uint32_t packh(float a, float b) {
  __half2 t = __floats2half2_rn(a, b);
  return *(uint32_t*)&t;
}
__device__ __forceinline__ void split_hl(float v, __half& h, __half& l) {
  h = __float2half_rn(v);
  l = __float2half_rn(v - __half2float(h));
}

// swizzle for 64B rows (GEMM, BK=32) and 128B rows (attention tiles, 64 fp16)
__device__ __forceinline__ uint32_t swz64(int row, int c16) {
  return (uint32_t)(row * 64 + ((c16 ^ ((row >> 1) & 3)) << 4));
}
__device__ __forceinline__ uint32_t swz128(int row, int c16) {
  return (uint32_t)(row * 128 + ((c16 ^ (row & 7)) << 4));
}

// ---------------- weight conversion (transpose + fp16 round) ----------------
__global__ void __launch_bounds__(256) cvt_wt_t_kernel(
    const float* __restrict__ W, __half* __restrict__ T, int K, int N) {
  __shared__ float t[32][33];
  const int nb = blockIdx.x * 32, kb = blockIdx.y * 32;
  const int tx = threadIdx.x & 31, ty = threadIdx.x >> 5;
  #pragma unroll
  for (int i = 0; i < 32; i += 8)
    t[ty + i][tx] = W[(size_t)(kb + ty + i) * N + nb + tx];
  __syncthreads();
  #pragma unroll
  for (int i = 0; i < 32; i += 8)
    T[(size_t)(nb + ty + i) * K + kb + tx] = __float2half_rn(t[tx][ty + i]);
}

// ---------------- HMMA GEMM: C[M,N] = (Ah+Al) @ B^T (B stored [N,K]), fp16x2 ----------------
// 128x128 tile, BK=32, 8 warps (2m x 4n), warp tile 64x32, 3-stage cp.async.
struct GemmJob {
  const __half *Ah, *Al, *B;
  const float* bias;
  float* C;
  __half *Ch, *Cl;
  int outmode;   // 0: fp32 C; 1: hi/lo fp16 Ch/Cl; 2: fp16 Ch only
  int gelu;
};

__global__ void __launch_bounds__(256, 1)
gemm_mma_kernel(GemmJob j0, GemmJob j1, GemmJob j2, int M, int N, int K) {
  extern __shared__ __align__(128) char sm[];
  const uint32_t smb = smem_u32(sm);
  const GemmJob j = (blockIdx.z == 0) ? j0 : ((blockIdx.z == 1) ? j1 : j2);
  const int tid = threadIdx.x;
  const int wid = tid >> 5, lane = tid & 31;
  const int bm = blockIdx.y * 128, bn = blockIdx.x * 128;
  const int warp_m = wid & 1, warp_n = wid >> 1;
  const int NK = K >> 5;

  auto so = [](int s, int mat) -> uint32_t { return (uint32_t)(s * 24576 + mat * 8192); };

  auto load_stage = [&](int kt, int s) {
    const int koff = kt * 32;
    #pragma unroll
    for (int jj = 0; jj < 2; jj++) {
      const int ch = tid + jj * 256;
      const int row = ch >> 2, c = ch & 3;
      const uint32_t d = swz64(row, c);
      const size_t ga = (size_t)(bm + row) * K + koff + c * 8;
      const size_t gb = (size_t)(bn + row) * K + koff + c * 8;
      cp_async16(smb + so(s, 0) + d, j.Ah + ga);
      cp_async16(smb + so(s, 1) + d, j.Al + ga);
      cp_async16(smb + so(s, 2) + d, j.B + gb);
    }
  };

  float acc[4][4][4];
  #pragma unroll
  for (int i = 0; i < 4; i++)
    #pragma unroll
    for (int jj = 0; jj < 4; jj++)
      #pragma unroll
      for (int q = 0; q < 4; q++) acc[i][jj][q] = 0.f;

  load_stage(0, 0); CP_COMMIT();
  load_stage(1, 1); CP_COMMIT();

  const int la_row = (lane & 7) + ((lane >> 3) & 1) * 8;
  const int la_c   = (lane >> 4);
  const int lb_row = (lane & 7) + (lane >> 4) * 8;
  const int lb_c   = (lane >> 3) & 1;

  for (int kt = 0; kt < NK; kt++) {
    const int s = kt % 3;
    if (kt + 2 < NK) { load_stage(kt + 2, (kt + 2) % 3); CP_COMMIT(); CP_WAIT(2); }
    else if (kt + 1 < NK) { CP_WAIT(1); }
    else { CP_WAIT(0); }
    __syncthreads();

    const uint32_t baseAh = smb + so(s, 0);
    const uint32_t baseAl = smb + so(s, 1);
    const uint32_t baseB  = smb + so(s, 2);

    #pragma unroll
    for (int ks = 0; ks < 2; ks++) {
      uint32_t aH[4][4], aL[4][4], bb[2][4];
      #pragma unroll
      for (int tm = 0; tm < 4; tm++) {
        const int row = warp_m * 64 + tm * 16 + la_row;
        const int c   = ks * 2 + la_c;
        ldsm4(aH[tm], baseAh + swz64(row, c));
        ldsm4(aL[tm], baseAl + swz64(row, c));
      }
      #pragma unroll
      for (int tn2 = 0; tn2 < 2; tn2++) {
        const int row = warp_n * 32 + tn2 * 16 + lb_row;
        const int c   = ks * 2 + lb_c;
        ldsm4(bb[tn2], baseB + swz64(row, c));
      }
      #pragma unroll
      for (int tm = 0; tm < 4; tm++)
        #pragma unroll
        for (int tn = 0; tn < 4; tn++) {
          const uint32_t* bp = &bb[tn >> 1][(tn & 1) * 2];
          mma16816(acc[tm][tn], aH[tm], bp);
          mma16816(acc[tm][tn], aL[tm], bp);
        }
    }
    __syncthreads();
  }

  // epilogue
  const int g = lane >> 2, tq = lane & 3;
  #pragma unroll
  for (int tm = 0; tm < 4; tm++) {
    #pragma unroll
    for (int tn = 0; tn < 4; tn++) {
      const int col = bn + warp_n * 32 + tn * 8 + tq * 2;
      const float b0 = j.bias[col], b1 = j.bias[col + 1];
      #pragma unroll
      for (int half = 0; half < 2; half++) {
        const int row = bm + warp_m * 64 + tm * 16 + g + half * 8;
        float vx = acc[tm][tn][half * 2 + 0] + b0;
        float vy = acc[tm][tn][half * 2 + 1] + b1;
        if (j.gelu) {
          vx = 0.5f * vx * (1.0f + erff(vx * 0.7071067811865476f));
          vy = 0.5f * vy * (1.0f + erff(vy * 0.7071067811865476f));
        }
        if (j.outmode == 0) {
          float2 v; v.x = vx; v.y = vy;
          *(float2*)(j.C + (size_t)row * N + col) = v;
        } else if (j.outmode == 1) {
          __half hx, lx, hy, ly;
          split_hl(vx, hx, lx); split_hl(vy, hy, ly);
          *(uint32_t*)(j.Ch + (size_t)row * N + col) = packh(__half2float(hx), __half2float(hy));
          *(uint32_t*)(j.Cl + (size_t)row * N + col) = packh(__half2float(lx), __half2float(ly));
        } else {
          *(uint32_t*)(j.Ch + (size_t)row * N + col) = packh(vx, vy);
        }
      }
    }
  }
}

// ---------------- HMMA flash attention (fp16x2, fp32 accum, online softmax) ----------------
// grid (S/64, NH, B), 128 threads = 4 warps; warp owns 16 q rows; K/V tiles of 64 keys.
// smem: Qh(8K) Ql(8K) + 2 stages x [K V](16K) = 48KB.
__global__ void __launch_bounds__(128, 2)
attn_mma_kernel(const __half* __restrict__ Qh, const __half* __restrict__ Ql,
                const __half* __restrict__ Kh, const __half* __restrict__ Vh,
                const float* __restrict__ mask,
                __half* __restrict__ Ch, __half* __restrict__ Cl) {
  extern __shared__ __align__(128) char sm[];
  const uint32_t smb = smem_u32(sm);
  const int tid = threadIdx.x;
  const int warp = tid >> 5, lane = tid & 31;
  const int qt = blockIdx.x, h = blockIdx.y, b = blockIdx.z;
  const int g = lane >> 2, tq = lane & 3;

  const int la_row = (lane & 7) + ((lane >> 3) & 1) * 8;
  const int la_c   = (lane >> 4);
  const int lb_row = (lane & 7) + (lane >> 4) * 8;
  const int lb_c   = (lane >> 3) & 1;
  const int lv_row = (lane & 7) + ((lane >> 3) & 1) * 8;
  const int lv_c   = (lane >> 4);

  // ---- load Q (hi/lo) + stage 0 ----
  {
    #pragma unroll
    for (int jj = 0; jj < 4; jj++) {
      const int ch = tid + jj * 128;
      const int row = ch >> 3, c = ch & 7;
      const uint32_t d = swz128(row, c);
      const size_t gq = (size_t)(b * 1024 + qt * 64 + row) * Hd + h * 64 + c * 8;
      cp_async16(smb + d, Qh + gq);
      cp_async16(smb + 8192 + d, Ql + gq);
    }
  }
  auto load_kv = [&](int kt, int s) {
    const uint32_t so = smb + 16384 + s * 16384;
    #pragma unroll
    for (int jj = 0; jj < 4; jj++) {
      const int ch = tid + jj * 128;
      const int row = ch >> 3, c = ch & 7;
      const uint32_t d = swz128(row, c);
      const size_t gk = (size_t)(b * 1024 + kt * 64 + row) * Hd + h * 64 + c * 8;
      cp_async16(so + d,        Kh + gk);
      cp_async16(so + 8192 + d, Vh + gk);
    }
  };
  load_kv(0, 0);
  CP_COMMIT();

  float m0 = -1e30f, m1 = -1e30f, l0 = 0.f, l1 = 0.f;
  float oacc[8][4];
  #pragma unroll
  for (int jj = 0; jj < 8; jj++)
    #pragma unroll
    for (int q = 0; q < 4; q++) oacc[jj][q] = 0.f;

  for (int kt = 0; kt < 16; kt++) {
    const int s = kt & 1;
    if (kt + 1 < 16) { load_kv(kt + 1, 1 - s); CP_COMMIT(); CP_WAIT(1); }
    else             { CP_WAIT(0); }
    __syncthreads();

    const uint32_t sK = smb + 16384 + s * 16384;
    const uint32_t sV = sK + 8192;

    // ---- S = Q K^T ----
    float sacc[8][4];
    #pragma unroll
    for (int jj = 0; jj < 8; jj++)
      #pragma unroll
      for (int q = 0; q < 4; q++) sacc[jj][q] = 0.f;

    #pragma unroll
    for (int kc = 0; kc < 4; kc++) {
      uint32_t qh4[4], ql4[4];
      const uint32_t qa = swz128(warp * 16 + la_row, kc * 2 + la_c);
      ldsm4(qh4, smb + qa);
      ldsm4(ql4, smb + 8192 + qa);
      #pragma unroll
      for (int n16 = 0; n16 < 4; n16++) {
        uint32_t kk4[4];
        const uint32_t ka = swz128(n16 * 16 + lb_row, kc * 2 + lb_c);
        ldsm4(kk4, sK + ka);
        mma16816(sacc[2 * n16],     qh4, kk4);
        mma16816(sacc[2 * n16],     ql4, kk4);
        mma16816(sacc[2 * n16 + 1], qh4, kk4 + 2);
        mma16816(sacc[2 * n16 + 1], ql4, kk4 + 2);
      }
    }

    // ---- online softmax ----
    const float* mrow = mask + b * 1024 + kt * 64;
    float mx0 = -1e30f, mx1 = -1e30f;
    #pragma unroll
    for (int jj = 0; jj < 8; jj++) {
      const float2 mv = *(const float2*)(mrow + jj * 8 + 2 * tq);
      sacc[jj][0] = sacc[jj][0] * 0.125f + mv.x;
      sacc[jj][1] = sacc[jj][1] * 0.125f + mv.y;
      sacc[jj][2] = sacc[jj][2] * 0.125f + mv.x;
      sacc[jj][3] = sacc[jj][3] * 0.125f + mv.y;
      mx0 = fmaxf(mx0, fmaxf(sacc[jj][0], sacc[jj][1]));
      mx1 = fmaxf(mx1, fmaxf(sacc[jj][2], sacc[jj][3]));
    }
    mx0 = fmaxf(mx0, __shfl_xor_sync(0xffffffffu, mx0, 1));
    mx0 = fmaxf(mx0, __shfl_xor_sync(0xffffffffu, mx0, 2));
    mx1 = fmaxf(mx1, __shfl_xor_sync(0xffffffffu, mx1, 1));
    mx1 = fmaxf(mx1, __shfl_xor_sync(0xffffffffu, mx1, 2));
    const float mn0 = fmaxf(m0, mx0), mn1 = fmaxf(m1, mx1);
    const float rs0 = __expf(m0 - mn0), rs1 = __expf(m1 - mn1);
    m0 = mn0; m1 = mn1;

    float sum0 = 0.f, sum1 = 0.f;
    uint32_t ph01[8], ph23[8], pl01[8], pl23[8];
    #pragma unroll
    for (int jj = 0; jj < 8; jj++) {
      const float p0 = __expf(sacc[jj][0] - mn0), p1 = __expf(sacc[jj][1] - mn0);
      const float p2 = __expf(sacc[jj][2] - mn1), p3 = __expf(sacc[jj][3] - mn1);
      sum0 += p0 + p1; sum1 += p2 + p3;
      __half h0, l0b, h1, l1b, h2, l2b, h3, l3b;
      split_hl(p0, h0, l0b); split_hl(p1, h1, l1b);
      split_hl(p2, h2, l2b); split_hl(p3, h3, l3b);
      ph01[jj] = packh(__half2float(h0), __half2float(h1));
      pl01[jj] = packh(__half2float(l0b), __half2float(l1b));
      ph23[jj] = packh(__half2float(h2), __half2float(h3));
      pl23[jj] = packh(__half2float(l2b), __half2float(l3b));
      oacc[jj][0] *= rs0; oacc[jj][1] *= rs0;
      oacc[jj][2] *= rs1; oacc[jj][3] *= rs1;
    }
    sum0 += __shfl_xor_sync(0xffffffffu, sum0, 1);
    sum0 += __shfl_xor_sync(0xffffffffu, sum0, 2);
    sum1 += __shfl_xor_sync(0xffffffffu, sum1, 1);
    sum1 += __shfl_xor_sync(0xffffffffu, sum1, 2);
    l0 = l0 * rs0 + sum0;
    l1 = l1 * rs1 + sum1;

    // ---- O += P V ----
    #pragma unroll
    for (int kc = 0; kc < 4; kc++) {
      uint32_t ah[4] = {ph01[2*kc], ph23[2*kc], ph01[2*kc+1], ph23[2*kc+1]};
      uint32_t al[4] = {pl01[2*kc], pl23[2*kc], pl01[2*kc+1], pl23[2*kc+1]};
      #pragma unroll
      for (int n16 = 0; n16 < 4; n16++) {
        uint32_t v4[4];
        const uint32_t va = swz128(kc * 16 + lv_row, n16 * 2 + lv_c);
        ldsm4t(v4, sV + va);
        mma16816(oacc[2 * n16],     ah, v4);
        mma16816(oacc[2 * n16],     al, v4);
        mma16816(oacc[2 * n16 + 1], ah, v4 + 2);
        mma16816(oacc[2 * n16 + 1], al, v4 + 2);
      }
    }
    __syncthreads();
  }

  // ---- epilogue ----
  const float inv0 = 1.f / l0, inv1 = 1.f / l1;
  const int row0 = b * 1024 + qt * 64 + warp * 16 + g;
  #pragma unroll
  for (int jj = 0; jj < 8; jj++) {
    const int col = h * 64 + (jj >> 1) * 16 + (jj & 1) * 8 + 2 * tq;
    const float v0 = oacc[jj][0] * inv0, v1 = oacc[jj][1] * inv0;
    const float v2 = oacc[jj][2] * inv1, v3 = oacc[jj][3] * inv1;
    __half h0, l0b, h1, l1b, h2, l2b, h3, l3b;
    split_hl(v0, h0, l0b); split_hl(v1, h1, l1b);
    split_hl(v2, h2, l2b); split_hl(v3, h3, l3b);
    *(uint32_t*)(Ch + (size_t)row0 * Hd + col)       = packh(__half2float(h0), __half2float(h1));
    *(uint32_t*)(Cl + (size_t)row0 * Hd + col)       = packh(__half2float(l0b), __half2float(l1b));
    *(uint32_t*)(Ch + (size_t)(row0 + 8) * Hd + col) = packh(__half2float(h2), __half2float(h3));
    *(uint32_t*)(Cl + (size_t)(row0 + 8) * Hd + col) = packh(__half2float(l2b), __half2float(l3b));
  }
}

// ---------------- routing (fused hi/lo split outputs) ----------------
__global__ void __launch_bounds__(256) routing_kernel(
    const float* __restrict__ x, const float* __restrict__ y,
    const int* __restrict__ tptr,
    float* __restrict__ xs,
    __half* __restrict__ xh, __half* __restrict__ xl,
    __half* __restrict__ yh, __half* __restrict__ yl) {
  const int token = blockIdx.x, tid = threadIdx.x;
  const long base = (long)token * Hd;
  float sxx = 0.f, sxy = 0.f, syy = 0.f;
  for (int i = tid; i < Hd; i += 256) {
    float a = x[base + i], bb = y[base + i];
    sxx += a * a; sxy += a * bb; syy += bb * bb;
  }
  #pragma unroll
  for (int o = 16; o; o >>= 1) {
    sxx += __shfl_xor_sync(0xffffffffu, sxx, o);
    sxy += __shfl_xor_sync(0xffffffffu, sxy, o);
    syy += __shfl_xor_sync(0xffffffffu, syy, o);
  }
  __shared__ float red[8][3];
  __shared__ float sc[2];
  if ((tid & 31) == 0) { red[tid >> 5][0] = sxx; red[tid >> 5][1] = sxy; red[tid >> 5][2] = syy; }
  __syncthreads();
  if (tid == 0) {
    float a = 0.f, bb = 0.f, c = 0.f;
    #pragma unroll
    for (int i = 0; i < 8; i++) { a += red[i][0]; bb += red[i][1]; c += red[i][2]; }
    const int t = *tptr;
    float b1 = 0.f, b2 = 0.f, c1 = 0.5f, c2 = 0.5f;
    for (int it = 0; it < t; it++) {
      if (it > 0) {
        float mm = fmaxf(b1, b2);
        float e1 = expf(b1 - mm), e2 = expf(b2 - mm);
        float inv = 1.0f / (e1 + e2);
        c1 = e1 * inv; c2 = e2 * inv;
      }
      float vv = c1 * c1 * a + 2.0f * c1 * c2 * bb + c2 * c2 * c;
      float n  = sqrtf(vv);
      float f  = n / (1.0f + vv);
      b1 += f * (c1 * a  + c2 * bb);
      b2 += f * (c1 * bb + c2 * c );
    }
    sc[0] = c1; sc[1] = c2;
  }
  __syncthreads();
  const float c1 = sc[0], c2 = sc[1];
  for (int i = tid; i < Hd; i += 256) {
    const float vx = c1 * x[base + i];
    const float vy = c2 * y[base + i];
    xs[base + i] = vx;
    __half hh, ll;
    split_hl(vx, hh, ll); xh[base + i] = hh; xl[base + i] = ll;
    split_hl(vy, hh, ll); yh[base + i] = hh; yl[base + i] = ll;
  }
}

// ---------------- fused residual + RMSNorm (optional hi/lo output) ----------------
template<bool SPLIT>
__global__ void __launch_bounds__(256) rms_kernel(
    const float* __restrict__ in, const float* __restrict__ res,
    const float* __restrict__ g, float* __restrict__ out,
    __half* __restrict__ oh, __half* __restrict__ ol) {
  const int row = blockIdx.x, tid = threadIdx.x;
  __shared__ float buf[Hd];
  __shared__ float red[8];
  __shared__ float s_inv;
  const long base = (long)row * Hd;
  float ss = 0.f;
  for (int i = tid; i < Hd; i += 256) {
    float v = in[base + i] + res[base + i];
    buf[i] = v; ss += v * v;
  }
  #pragma unroll
  for (int o = 16; o; o >>= 1) ss += __shfl_xor_sync(0xffffffffu, ss, o);
  if ((tid & 31) == 0) red[tid >> 5] = ss;
  __syncthreads();
  if (tid == 0) {
    float tot = 0.f;
    #pragma unroll
    for (int i = 0; i < 8; i++) tot += red[i];
    s_inv = rsqrtf(tot * (1.0f / (float)Hd) + 1e-6f);
  }
  __syncthreads();
  const float inv = s_inv;
  for (int i = tid; i < Hd; i += 256) {
    const float v = buf[i] * inv * g[i];
    out[base + i] = v;
    if (SPLIT) {
      __half hh, ll;
      split_hl(v, hh, ll);
      oh[base + i] = hh; ol[base + i] = ll;
    }
  }
}

// ---------------- host ----------------
static const int GEMM_SMEM = 73728;   // 3 stages x 3 mats x 8KB
static const int ATTN_SMEM = 49152;

extern "C" void kernel_launch(void* const* d_in, const int* in_sizes, int n_in,
                              void* d_out, int out_size) {
  const float* x    = (const float*)d_in[0];
  const float* y    = (const float*)d_in[1];
  const float* mask = (const float*)d_in[2];
  const float* Wq   = (const float*)d_in[3];
  const float* bq   = (const float*)d_in[4];
  const float* Wk   = (const float*)d_in[5];
  const float* bk   = (const float*)d_in[6];
  const float* Wv   = (const float*)d_in[7];
  const float* bv   = (const float*)d_in[8];
  const float* Wo   = (const float*)d_in[9];
  const float* bo   = (const float*)d_in[10];
  const float* g1   = (const float*)d_in[11];
  const float* Wi   = (const float*)d_in[12];
  const float* bi   = (const float*)d_in[13];
  const float* Wo2  = (const float*)d_in[14];
  const float* bo2  = (const float*)d_in[15];
  const float* g2   = (const float*)d_in[16];
  const int*   t    = (const int*)d_in[17];
  float* out = (float*)d_out;

  cudaFuncSetAttribute(gemm_mma_kernel, cudaFuncAttributeMaxDynamicSharedMemorySize, GEMM_SMEM);
  cudaFuncSetAttribute(attn_mma_kernel, cudaFuncAttributeMaxDynamicSharedMemorySize, ATTN_SMEM);

  float *xs, *att, *tmp;
  cudaGetSymbolAddress((void**)&xs,  g_xs);
  cudaGetSymbolAddress((void**)&att, g_att);
  cudaGetSymbolAddress((void**)&tmp, g_tmp);

  __half *xh,*xl,*yh,*yl,*qh,*ql,*kh,*vh,*ch,*cl,*ah,*al,*ih,*il;
  cudaGetSymbolAddress((void**)&xh, g_xh); cudaGetSymbolAddress((void**)&xl, g_xl);
  cudaGetSymbolAddress((void**)&yh, g_yh); cudaGetSymbolAddress((void**)&yl, g_yl);
  cudaGetSymbolAddress((void**)&qh, g_qh); cudaGetSymbolAddress((void**)&ql, g_ql);
  cudaGetSymbolAddress((void**)&kh, g_kh);
  cudaGetSymbolAddress((void**)&vh, g_vh);
  cudaGetSymbolAddress((void**)&ch, g_ch); cudaGetSymbolAddress((void**)&cl, g_cl);
  cudaGetSymbolAddress((void**)&ah, g_ah); cudaGetSymbolAddress((void**)&al, g_al);
  cudaGetSymbolAddress((void**)&ih, g_ih); cudaGetSymbolAddress((void**)&il, g_il);

  __half *wq,*wk,*wv,*wo,*wi,*w2;
  cudaGetSymbolAddress((void**)&wq, g_wq);
  cudaGetSymbolAddress((void**)&wk, g_wk);
  cudaGetSymbolAddress((void**)&wv, g_wv);
  cudaGetSymbolAddress((void**)&wo, g_wo);
  cudaGetSymbolAddress((void**)&wi, g_wi);
  cudaGetSymbolAddress((void**)&w2, g_w2);

  routing_kernel<<<TOK, 256>>>(x, y, t, xs, xh, xl, yh, yl);

  cvt_wt_t_kernel<<<dim3(Hd/32, Hd/32), 256>>>(Wq,  wq, Hd, Hd);
  cvt_wt_t_kernel<<<dim3(Hd/32, Hd/32), 256>>>(Wk,  wk, Hd, Hd);
  cvt_wt_t_kernel<<<dim3(Hd/32, Hd/32), 256>>>(Wv,  wv, Hd, Hd);
  cvt_wt_t_kernel<<<dim3(Hd/32, Hd/32), 256>>>(Wo,  wo, Hd, Hd);
  cvt_wt_t_kernel<<<dim3(Id/32, Hd/32), 256>>>(Wi,  wi, Hd, Id);
  cvt_wt_t_kernel<<<dim3(Hd/32, Id/32), 256>>>(Wo2, w2, Id, Hd);

  // fused QKV (z = 0,1,2)
  {
    GemmJob jq = {xh, xl, wq, bq, nullptr, qh, ql, 1, 0};
    GemmJob jk = {yh, yl, wk, bk, nullptr, kh, nullptr, 2, 0};
    GemmJob jv = {yh, yl, wv, bv, nullptr, vh, nullptr, 2, 0};
    gemm_mma_kernel<<<dim3(Hd/128, TOK/128, 3), 256, GEMM_SMEM>>>(jq, jk, jv, TOK, Hd, Hd);
  }

  attn_mma_kernel<<<dim3(16, NHh, 4), 128, ATTN_SMEM>>>(qh, ql, kh, vh, mask, ch, cl);

  {
    GemmJob jo = {ch, cl, wo, bo, tmp, nullptr, nullptr, 0, 0};
    gemm_mma_kernel<<<dim3(Hd/128, TOK/128, 1), 256, GEMM_SMEM>>>(jo, jo, jo, TOK, Hd, Hd);
  }
  rms_kernel<true ><<<TOK, 256>>>(tmp, xs, g1, att, ah, al);

  {
    GemmJob ji = {ah, al, wi, bi, nullptr, ih, il, 1, 1};
    gemm_mma_kernel<<<dim3(Id/128, TOK/128, 1), 256, GEMM_SMEM>>>(ji, ji, ji, TOK, Id, Hd);
  }
  {
    GemmJob j2 = {ih, il, w2, bo2, tmp, nullptr, nullptr, 0, 0};
    gemm_mma_kernel<<<dim3(Hd/128, TOK/128, 1), 256, GEMM_SMEM>>>(j2, j2, j2, TOK, Hd, Id);
  }
  rms_kernel<false><<<TOK, 256>>>(tmp, att, g2, out, nullptr, nullptr);
}

// round 6
// speedup vs baseline: 6.7327x; 1.5149x over previous
#include <cuda_runtime.h>
#include <cuda_fp16.h>
#include <math.h>
#include <stdint.h>

#define TOK 4096        // B*S
#define Hd  1024
#define Id  4096
#define NHh 16
#define DHh 64

// ---------------- scratch (device globals; no allocs) ----------------
__device__ float g_xs [TOK * Hd];
__device__ float g_att[TOK * Hd];
__device__ float g_tmp[TOK * Hd];

// fp16 activation buffers (single precision pass)
__device__ __half g_xh[TOK * Hd];
__device__ __half g_yh[TOK * Hd];
__device__ __half g_qh[TOK * Hd];
__device__ __half g_kh[TOK * Hd];
__device__ __half g_vh[TOK * Hd];
__device__ __half g_ch[TOK * Hd];
__device__ __half g_ah[TOK * Hd];
__device__ __half g_ih[TOK * Id];

// transposed fp16 weights [N, K]
__device__ __half g_wq[Hd * Hd];
__device__ __half g_wk[Hd * Hd];
__device__ __half g_wv[Hd * Hd];
__device__ __half g_wo[Hd * Hd];
__device__ __half g_wi[Id * Hd];
__device__ __half g_w2[Hd * Id];

// ---------------- helpers ----------------
__device__ __forceinline__ uint32_t smem_u32(const void* p) {
  uint32_t a;
  asm("{ .reg .u64 t; cvta.to.shared.u64 t, %1; cvt.u32.u64 %0, t; }" : "=r"(a) : "l"(p));
  return a;
}
__device__ __forceinline__ void cp_async16(uint32_t dst, const void* src) {
  asm volatile("cp.async.cg.shared.global [%0], [%1], 16;" :: "r"(dst), "l"(src) : "memory");
}
#define CP_COMMIT() asm volatile("cp.async.commit_group;" ::: "memory")
#define CP_WAIT(n)  asm volatile("cp.async.wait_group %0;" :: "n"(n) : "memory")

__device__ __forceinline__ void ldsm4(uint32_t* r, uint32_t addr) {
  asm volatile("ldmatrix.sync.aligned.m8n8.x4.shared.b16 {%0,%1,%2,%3}, [%4];"
               : "=r"(r[0]), "=r"(r[1]), "=r"(r[2]), "=r"(r[3]) : "r"(addr));
}
__device__ __forceinline__ void ldsm4t(uint32_t* r, uint32_t addr) {
  asm volatile("ldmatrix.sync.aligned.m8n8.x4.trans.shared.b16 {%0,%1,%2,%3}, [%4];"
               : "=r"(r[0]), "=r"(r[1]), "=r"(r[2]), "=r"(r[3]) : "r"(addr));
}
__device__ __forceinline__ void mma16816(float* d, const uint32_t* a, const uint32_t* b) {
  asm volatile("mma.sync.aligned.m16n8k16.row.col.f32.f16.f16.f32 "
               "{%0,%1,%2,%3}, {%4,%5,%6,%7}, {%8,%9}, {%0,%1,%2,%3};"
               : "+f"(d[0]), "+f"(d[1]), "+f"(d[2]), "+f"(d[3])
               : "r"(a[0]), "r"(a[1]), "r"(a[2]), "r"(a[3]), "r"(b[0]), "r"(b[1]));
}
__device__ __forceinline__ uint32_t packh(float a, float b) {
  __half2 t = __floats2half2_rn(a, b);
  return *(uint32_t*)&t;
}

// swizzle for 64B rows (GEMM, BK=32) and 128B rows (attention tiles, 64 fp16)
__device__ __forceinline__ uint32_t swz64(int row, int c16) {
  return (uint32_t)(row * 64 + ((c16 ^ ((row >> 1) & 3)) << 4));
}
__device__ __forceinline__ uint32_t swz128(int row, int c16) {
  return (uint32_t)(row * 128 + ((c16 ^ (row & 7)) << 4));
}

// ---------------- batched weight conversion (transpose + fp16 round) ----------------
struct CvtJobs {
  const float* W[6];
  __half* T[6];
  int K[6], N[6], tilesX[6], start[6];
};

__global__ void __launch_bounds__(256) cvt_wt_all_kernel(CvtJobs jb) {
  const int b = blockIdx.x;
  int j = 0;
  #pragma unroll
  for (int i = 1; i < 6; i++) if (b >= jb.start[i]) j = i;
  const int local = b - jb.start[j];
  const int K = jb.K[j], N = jb.N[j];
  const int nb = (local % jb.tilesX[j]) * 32;
  const int kb = (local / jb.tilesX[j]) * 32;
  const float* W = jb.W[j];
  __half* T = jb.T[j];

  __shared__ float t[32][33];
  const int tx = threadIdx.x & 31, ty = threadIdx.x >> 5;
  #pragma unroll
  for (int i = 0; i < 32; i += 8)
    t[ty + i][tx] = W[(size_t)(kb + ty + i) * N + nb + tx];
  __syncthreads();
  #pragma unroll
  for (int i = 0; i < 32; i += 8)
    T[(size_t)(nb + ty + i) * K + kb + tx] = __float2half_rn(t[tx][ty + i]);
}

// ---------------- HMMA GEMM: C[M,N] = A @ B^T (B stored [N,K]), fp16 single-pass ----------------
// 128x128 tile, BK=32, 8 warps (2m x 4n), warp tile 64x32, 4-stage cp.async.
struct GemmJob {
  const __half *A, *B;
  const float* bias;
  float* C;
  __half* Ch;
  int outmode;   // 0: fp32 C; 2: fp16 Ch
  int gelu;
};

__global__ void __launch_bounds__(256, 1)
gemm_mma_kernel(GemmJob j0, GemmJob j1, GemmJob j2, int M, int N, int K) {
  extern __shared__ __align__(128) char sm[];
  const uint32_t smb = smem_u32(sm);
  const GemmJob j = (blockIdx.z == 0) ? j0 : ((blockIdx.z == 1) ? j1 : j2);
  const int tid = threadIdx.x;
  const int wid = tid >> 5, lane = tid & 31;
  const int bm = blockIdx.y * 128, bn = blockIdx.x * 128;
  const int warp_m = wid & 1, warp_n = wid >> 1;
  const int NK = K >> 5;

  auto so = [](int s, int mat) -> uint32_t { return (uint32_t)(s * 16384 + mat * 8192); };

  auto load_stage = [&](int kt, int s) {
    const int koff = kt * 32;
    #pragma unroll
    for (int jj = 0; jj < 2; jj++) {
      const int ch = tid + jj * 256;
      const int row = ch >> 2, c = ch & 3;
      const uint32_t d = swz64(row, c);
      cp_async16(smb + so(s, 0) + d, j.A + (size_t)(bm + row) * K + koff + c * 8);
      cp_async16(smb + so(s, 1) + d, j.B + (size_t)(bn + row) * K + koff + c * 8);
    }
  };

  float acc[4][4][4];
  #pragma unroll
  for (int i = 0; i < 4; i++)
    #pragma unroll
    for (int jj = 0; jj < 4; jj++)
      #pragma unroll
      for (int q = 0; q < 4; q++) acc[i][jj][q] = 0.f;

  load_stage(0, 0); CP_COMMIT();
  load_stage(1, 1); CP_COMMIT();
  load_stage(2, 2); CP_COMMIT();

  const int la_row = (lane & 7) + ((lane >> 3) & 1) * 8;
  const int la_c   = (lane >> 4);
  const int lb_row = (lane & 7) + (lane >> 4) * 8;
  const int lb_c   = (lane >> 3) & 1;

  for (int kt = 0; kt < NK; kt++) {
    const int s = kt & 3;
    const int rem = NK - 1 - kt;
    if (rem >= 2) { CP_WAIT(2); } else if (rem == 1) { CP_WAIT(1); } else { CP_WAIT(0); }
    __syncthreads();
    if (kt + 3 < NK) { load_stage(kt + 3, (kt + 3) & 3); CP_COMMIT(); }

    const uint32_t baseA = smb + so(s, 0);
    const uint32_t baseB = smb + so(s, 1);

    #pragma unroll
    for (int ks = 0; ks < 2; ks++) {
      uint32_t a4[4][4], b4[2][4];
      #pragma unroll
      for (int tm = 0; tm < 4; tm++)
        ldsm4(a4[tm], baseA + swz64(warp_m * 64 + tm * 16 + la_row, ks * 2 + la_c));
      #pragma unroll
      for (int tn2 = 0; tn2 < 2; tn2++)
        ldsm4(b4[tn2], baseB + swz64(warp_n * 32 + tn2 * 16 + lb_row, ks * 2 + lb_c));
      #pragma unroll
      for (int tm = 0; tm < 4; tm++)
        #pragma unroll
        for (int tn = 0; tn < 4; tn++)
          mma16816(acc[tm][tn], a4[tm], &b4[tn >> 1][(tn & 1) * 2]);
    }
  }

  // epilogue
  const int g = lane >> 2, tq = lane & 3;
  #pragma unroll
  for (int tm = 0; tm < 4; tm++) {
    #pragma unroll
    for (int tn = 0; tn < 4; tn++) {
      const int col = bn + warp_n * 32 + tn * 8 + tq * 2;
      const float b0 = j.bias[col], b1 = j.bias[col + 1];
      #pragma unroll
      for (int half = 0; half < 2; half++) {
        const int row = bm + warp_m * 64 + tm * 16 + g + half * 8;
        float vx = acc[tm][tn][half * 2 + 0] + b0;
        float vy = acc[tm][tn][half * 2 + 1] + b1;
        if (j.gelu) {
          vx = 0.5f * vx * (1.0f + erff(vx * 0.7071067811865476f));
          vy = 0.5f * vy * (1.0f + erff(vy * 0.7071067811865476f));
        }
        if (j.outmode == 0) {
          float2 v; v.x = vx; v.y = vy;
          *(float2*)(j.C + (size_t)row * N + col) = v;
        } else {
          *(uint32_t*)(j.Ch + (size_t)row * N + col) = packh(vx, vy);
        }
      }
    }
  }
}

// ---------------- HMMA flash attention (fp16 single-pass, fp32 accum) ----------------
// grid (S/64, NH, B), 128 threads = 4 warps; warp owns 16 q rows; K/V tiles of 64 keys.
// smem: Q(8K) + 2 stages x [K V](16K) = 40KB.
__global__ void __launch_bounds__(128, 2)
attn_mma_kernel(const __half* __restrict__ Qh,
                const __half* __restrict__ Kh, const __half* __restrict__ Vh,
                const float* __restrict__ mask,
                __half* __restrict__ Ch) {
  extern __shared__ __align__(128) char sm[];
  const uint32_t smb = smem_u32(sm);
  const int tid = threadIdx.x;
  const int warp = tid >> 5, lane = tid & 31;
  const int qt = blockIdx.x, h = blockIdx.y, b = blockIdx.z;
  const int g = lane >> 2, tq = lane & 3;

  const int la_row = (lane & 7) + ((lane >> 3) & 1) * 8;
  const int la_c   = (lane >> 4);
  const int lb_row = (lane & 7) + (lane >> 4) * 8;
  const int lb_c   = (lane >> 3) & 1;
  const int lv_row = (lane & 7) + ((lane >> 3) & 1) * 8;
  const int lv_c   = (lane >> 4);

  // ---- load Q + stage 0 ----
  {
    #pragma unroll
    for (int jj = 0; jj < 4; jj++) {
      const int ch = tid + jj * 128;
      const int row = ch >> 3, c = ch & 7;
      cp_async16(smb + swz128(row, c),
                 Qh + (size_t)(b * 1024 + qt * 64 + row) * Hd + h * 64 + c * 8);
    }
  }
  auto load_kv = [&](int kt, int s) {
    const uint32_t so = smb + 8192 + s * 16384;
    #pragma unroll
    for (int jj = 0; jj < 4; jj++) {
      const int ch = tid + jj * 128;
      const int row = ch >> 3, c = ch & 7;
      const uint32_t d = swz128(row, c);
      const size_t gk = (size_t)(b * 1024 + kt * 64 + row) * Hd + h * 64 + c * 8;
      cp_async16(so + d,        Kh + gk);
      cp_async16(so + 8192 + d, Vh + gk);
    }
  };
  load_kv(0, 0);
  CP_COMMIT();

  float m0 = -1e30f, m1 = -1e30f, l0 = 0.f, l1 = 0.f;
  float oacc[8][4];
  #pragma unroll
  for (int jj = 0; jj < 8; jj++)
    #pragma unroll
    for (int q = 0; q < 4; q++) oacc[jj][q] = 0.f;

  for (int kt = 0; kt < 16; kt++) {
    const int s = kt & 1;
    if (kt + 1 < 16) { load_kv(kt + 1, 1 - s); CP_COMMIT(); CP_WAIT(1); }
    else             { CP_WAIT(0); }
    __syncthreads();

    const uint32_t sK = smb + 8192 + s * 16384;
    const uint32_t sV = sK + 8192;

    // ---- S = Q K^T ----
    float sacc[8][4];
    #pragma unroll
    for (int jj = 0; jj < 8; jj++)
      #pragma unroll
      for (int q = 0; q < 4; q++) sacc[jj][q] = 0.f;

    #pragma unroll
    for (int kc = 0; kc < 4; kc++) {
      uint32_t q4[4];
      ldsm4(q4, smb + swz128(warp * 16 + la_row, kc * 2 + la_c));
      #pragma unroll
      for (int n16 = 0; n16 < 4; n16++) {
        uint32_t k4[4];
        ldsm4(k4, sK + swz128(n16 * 16 + lb_row, kc * 2 + lb_c));
        mma16816(sacc[2 * n16],     q4, k4);
        mma16816(sacc[2 * n16 + 1], q4, k4 + 2);
      }
    }

    // ---- online softmax ----
    const float* mrow = mask + b * 1024 + kt * 64;
    float mx0 = -1e30f, mx1 = -1e30f;
    #pragma unroll
    for (int jj = 0; jj < 8; jj++) {
      const float2 mv = *(const float2*)(mrow + jj * 8 + 2 * tq);
      sacc[jj][0] = sacc[jj][0] * 0.125f + mv.x;
      sacc[jj][1] = sacc[jj][1] * 0.125f + mv.y;
      sacc[jj][2] = sacc[jj][2] * 0.125f + mv.x;
      sacc[jj][3] = sacc[jj][3] * 0.125f + mv.y;
      mx0 = fmaxf(mx0, fmaxf(sacc[jj][0], sacc[jj][1]));
      mx1 = fmaxf(mx1, fmaxf(sacc[jj][2], sacc[jj][3]));
    }
    mx0 = fmaxf(mx0, __shfl_xor_sync(0xffffffffu, mx0, 1));
    mx0 = fmaxf(mx0, __shfl_xor_sync(0xffffffffu, mx0, 2));
    mx1 = fmaxf(mx1, __shfl_xor_sync(0xffffffffu, mx1, 1));
    mx1 = fmaxf(mx1, __shfl_xor_sync(0xffffffffu, mx1, 2));
    const float mn0 = fmaxf(m0, mx0), mn1 = fmaxf(m1, mx1);
    const float rs0 = __expf(m0 - mn0), rs1 = __expf(m1 - mn1);
    m0 = mn0; m1 = mn1;

    float sum0 = 0.f, sum1 = 0.f;
    uint32_t ph01[8], ph23[8];
    #pragma unroll
    for (int jj = 0; jj < 8; jj++) {
      const float p0 = __expf(sacc[jj][0] - mn0), p1 = __expf(sacc[jj][1] - mn0);
      const float p2 = __expf(sacc[jj][2] - mn1), p3 = __expf(sacc[jj][3] - mn1);
      sum0 += p0 + p1; sum1 += p2 + p3;
      ph01[jj] = packh(p0, p1);
      ph23[jj] = packh(p2, p3);
      oacc[jj][0] *= rs0; oacc[jj][1] *= rs0;
      oacc[jj][2] *= rs1; oacc[jj][3] *= rs1;
    }
    sum0 += __shfl_xor_sync(0xffffffffu, sum0, 1);
    sum0 += __shfl_xor_sync(0xffffffffu, sum0, 2);
    sum1 += __shfl_xor_sync(0xffffffffu, sum1, 1);
    sum1 += __shfl_xor_sync(0xffffffffu, sum1, 2);
    l0 = l0 * rs0 + sum0;
    l1 = l1 * rs1 + sum1;

    // ---- O += P V ----
    #pragma unroll
    for (int kc = 0; kc < 4; kc++) {
      uint32_t ah[4] = {ph01[2*kc], ph23[2*kc], ph01[2*kc+1], ph23[2*kc+1]};
      #pragma unroll
      for (int n16 = 0; n16 < 4; n16++) {
        uint32_t v4[4];
        ldsm4t(v4, sV + swz128(kc * 16 + lv_row, n16 * 2 + lv_c));
        mma16816(oacc[2 * n16],     ah, v4);
        mma16816(oacc[2 * n16 + 1], ah, v4 + 2);
      }
    }
    __syncthreads();
  }

  // ---- epilogue ----
  const float inv0 = 1.f / l0, inv1 = 1.f / l1;
  const int row0 = b * 1024 + qt * 64 + warp * 16 + g;
  #pragma unroll
  for (int jj = 0; jj < 8; jj++) {
    const int col = h * 64 + (jj >> 1) * 16 + (jj & 1) * 8 + 2 * tq;
    *(uint32_t*)(Ch + (size_t)row0 * Hd + col)       = packh(oacc[jj][0] * inv0, oacc[jj][1] * inv0);
    *(uint32_t*)(Ch + (size_t)(row0 + 8) * Hd + col) = packh(oacc[jj][2] * inv1, oacc[jj][3] * inv1);
  }
}

// ---------------- routing (fused fp16 outputs) ----------------
__global__ void __launch_bounds__(256) routing_kernel(
    const float* __restrict__ x, const float* __restrict__ y,
    const int* __restrict__ tptr,
    float* __restrict__ xs,
    __half* __restrict__ xh, __half* __restrict__ yh) {
  const int token = blockIdx.x, tid = threadIdx.x;
  const long base = (long)token * Hd;
  float sxx = 0.f, sxy = 0.f, syy = 0.f;
  for (int i = tid; i < Hd; i += 256) {
    float a = x[base + i], bb = y[base + i];
    sxx += a * a; sxy += a * bb; syy += bb * bb;
  }
  #pragma unroll
  for (int o = 16; o; o >>= 1) {
    sxx += __shfl_xor_sync(0xffffffffu, sxx, o);
    sxy += __shfl_xor_sync(0xffffffffu, sxy, o);
    syy += __shfl_xor_sync(0xffffffffu, syy, o);
  }
  __shared__ float red[8][3];
  __shared__ float sc[2];
  if ((tid & 31) == 0) { red[tid >> 5][0] = sxx; red[tid >> 5][1] = sxy; red[tid >> 5][2] = syy; }
  __syncthreads();
  if (tid == 0) {
    float a = 0.f, bb = 0.f, c = 0.f;
    #pragma unroll
    for (int i = 0; i < 8; i++) { a += red[i][0]; bb += red[i][1]; c += red[i][2]; }
    const int t = *tptr;
    float b1 = 0.f, b2 = 0.f, c1 = 0.5f, c2 = 0.5f;
    for (int it = 0; it < t; it++) {
      if (it > 0) {
        float mm = fmaxf(b1, b2);
        float e1 = expf(b1 - mm), e2 = expf(b2 - mm);
        float inv = 1.0f / (e1 + e2);
        c1 = e1 * inv; c2 = e2 * inv;
      }
      float vv = c1 * c1 * a + 2.0f * c1 * c2 * bb + c2 * c2 * c;
      float n  = sqrtf(vv);
      float f  = n / (1.0f + vv);
      b1 += f * (c1 * a  + c2 * bb);
      b2 += f * (c1 * bb + c2 * c );
    }
    sc[0] = c1; sc[1] = c2;
  }
  __syncthreads();
  const float c1 = sc[0], c2 = sc[1];
  for (int i = tid; i < Hd; i += 256) {
    const float vx = c1 * x[base + i];
    const float vy = c2 * y[base + i];
    xs[base + i] = vx;
    xh[base + i] = __float2half_rn(vx);
    yh[base + i] = __float2half_rn(vy);
  }
}

// ---------------- fused residual + RMSNorm (optional fp16 output) ----------------
template<bool FOUT>
__global__ void __launch_bounds__(256) rms_kernel(
    const float* __restrict__ in, const float* __restrict__ res,
    const float* __restrict__ g, float* __restrict__ out,
    __half* __restrict__ oh) {
  const int row = blockIdx.x, tid = threadIdx.x;
  __shared__ float buf[Hd];
  __shared__ float red[8];
  __shared__ float s_inv;
  const long base = (long)row * Hd;
  float ss = 0.f;
  for (int i = tid; i < Hd; i += 256) {
    float v = in[base + i] + res[base + i];
    buf[i] = v; ss += v * v;
  }
  #pragma unroll
  for (int o = 16; o; o >>= 1) ss += __shfl_xor_sync(0xffffffffu, ss, o);
  if ((tid & 31) == 0) red[tid >> 5] = ss;
  __syncthreads();
  if (tid == 0) {
    float tot = 0.f;
    #pragma unroll
    for (int i = 0; i < 8; i++) tot += red[i];
    s_inv = rsqrtf(tot * (1.0f / (float)Hd) + 1e-6f);
  }
  __syncthreads();
  const float inv = s_inv;
  for (int i = tid; i < Hd; i += 256) {
    const float v = buf[i] * inv * g[i];
    out[base + i] = v;
    if (FOUT) oh[base + i] = __float2half_rn(v);
  }
}

// ---------------- host ----------------
static const int GEMM_SMEM = 65536;   // 4 stages x 2 mats x 8KB
static const int ATTN_SMEM = 40960;   // Q 8KB + 2 x (K+V 16KB)

extern "C" void kernel_launch(void* const* d_in, const int* in_sizes, int n_in,
                              void* d_out, int out_size) {
  const float* x    = (const float*)d_in[0];
  const float* y    = (const float*)d_in[1];
  const float* mask = (const float*)d_in[2];
  const float* Wq   = (const float*)d_in[3];
  const float* bq   = (const float*)d_in[4];
  const float* Wk   = (const float*)d_in[5];
  const float* bk   = (const float*)d_in[6];
  const float* Wv   = (const float*)d_in[7];
  const float* bv   = (const float*)d_in[8];
  const float* Wo   = (const float*)d_in[9];
  const float* bo   = (const float*)d_in[10];
  const float* g1   = (const float*)d_in[11];
  const float* Wi   = (const float*)d_in[12];
  const float* bi   = (const float*)d_in[13];
  const float* Wo2  = (const float*)d_in[14];
  const float* bo2  = (const float*)d_in[15];
  const float* g2   = (const float*)d_in[16];
  const int*   t    = (const int*)d_in[17];
  float* out = (float*)d_out;

  cudaFuncSetAttribute(gemm_mma_kernel, cudaFuncAttributeMaxDynamicSharedMemorySize, GEMM_SMEM);
  cudaFuncSetAttribute(attn_mma_kernel, cudaFuncAttributeMaxDynamicSharedMemorySize, ATTN_SMEM);

  float *xs, *att, *tmp;
  cudaGetSymbolAddress((void**)&xs,  g_xs);
  cudaGetSymbolAddress((void**)&att, g_att);
  cudaGetSymbolAddress((void**)&tmp, g_tmp);

  __half *xh,*yh,*qh,*kh,*vh,*ch,*ah,*ih;
  cudaGetSymbolAddress((void**)&xh, g_xh);
  cudaGetSymbolAddress((void**)&yh, g_yh);
  cudaGetSymbolAddress((void**)&qh, g_qh);
  cudaGetSymbolAddress((void**)&kh, g_kh);
  cudaGetSymbolAddress((void**)&vh, g_vh);
  cudaGetSymbolAddress((void**)&ch, g_ch);
  cudaGetSymbolAddress((void**)&ah, g_ah);
  cudaGetSymbolAddress((void**)&ih, g_ih);

  __half *wq,*wk,*wv,*wo,*wi,*w2;
  cudaGetSymbolAddress((void**)&wq, g_wq);
  cudaGetSymbolAddress((void**)&wk, g_wk);
  cudaGetSymbolAddress((void**)&wv, g_wv);
  cudaGetSymbolAddress((void**)&wo, g_wo);
  cudaGetSymbolAddress((void**)&wi, g_wi);
  cudaGetSymbolAddress((void**)&w2, g_w2);

  routing_kernel<<<TOK, 256>>>(x, y, t, xs, xh, yh);

  // batched weight conversion: one launch for all 6 weights
  {
    CvtJobs jb;
    const float* Ws[6] = {Wq, Wk, Wv, Wo, Wi, Wo2};
    __half* Ts[6] = {wq, wk, wv, wo, wi, w2};
    int Ks[6] = {Hd, Hd, Hd, Hd, Hd, Id};
    int Ns[6] = {Hd, Hd, Hd, Hd, Id, Hd};
    int cum = 0;
    for (int i = 0; i < 6; i++) {
      jb.W[i] = Ws[i]; jb.T[i] = Ts[i];
      jb.K[i] = Ks[i]; jb.N[i] = Ns[i];
      jb.tilesX[i] = Ns[i] / 32;
      jb.start[i] = cum;
      cum += (Ns[i] / 32) * (Ks[i] / 32);
    }
    cvt_wt_all_kernel<<<cum, 256>>>(jb);
  }

  // fused QKV (z = 0,1,2)
  {
    GemmJob jq = {xh, wq, bq, nullptr, qh, 2, 0};
    GemmJob jk = {yh, wk, bk, nullptr, kh, 2, 0};
    GemmJob jv = {yh, wv, bv, nullptr, vh, 2, 0};
    gemm_mma_kernel<<<dim3(Hd/128, TOK/128, 3), 256, GEMM_SMEM>>>(jq, jk, jv, TOK, Hd, Hd);
  }

  attn_mma_kernel<<<dim3(16, NHh, 4), 128, ATTN_SMEM>>>(qh, kh, vh, mask, ch);

  {
    GemmJob jo = {ch, wo, bo, tmp, nullptr, 0, 0};
    gemm_mma_kernel<<<dim3(Hd/128, TOK/128, 1), 256, GEMM_SMEM>>>(jo, jo, jo, TOK, Hd, Hd);
  }
  rms_kernel<true ><<<TOK, 256>>>(tmp, xs, g1, att, ah);

  {
    GemmJob ji = {ah, wi, bi, nullptr, ih, 2, 1};
    gemm_mma_kernel<<<dim3(Id/128, TOK/128, 1), 256, GEMM_SMEM>>>(ji, ji, ji, TOK, Id, Hd);
  }
  {
    GemmJob j2 = {ih, w2, bo2, tmp, nullptr, 0, 0};
    gemm_mma_kernel<<<dim3(Hd/128, TOK/128, 1), 256, GEMM_SMEM>>>(j2, j2, j2, TOK, Hd, Id);
  }
  rms_kernel<false><<<TOK, 256>>>(tmp, att, g2, out, nullptr);
}

// round 7
// speedup vs baseline: 6.9832x; 1.0372x over previous
#include <cuda_runtime.h>
#include <cuda_fp16.h>
#include <math.h>
#include <stdint.h>

#define TOK 4096        // B*S
#define Hd  1024
#define Id  4096
#define NHh 16
#define DHh 64

// ---------------- scratch (device globals; no allocs) ----------------
__device__ float g_xs [TOK * Hd];
__device__ float g_att[TOK * Hd];
__device__ float g_tmp[TOK * Hd];

// fp16 activation buffers
__device__ __half g_xh[TOK * Hd];
__device__ __half g_yh[TOK * Hd];
__device__ __half g_qh[TOK * Hd];
__device__ __half g_kh[TOK * Hd];
__device__ __half g_vh[TOK * Hd];
__device__ __half g_ch[TOK * Hd];
__device__ __half g_ah[TOK * Hd];
__device__ __half g_ih[TOK * Id];

// transposed fp16 weights [N, K]
__device__ __half g_wq[Hd * Hd];
__device__ __half g_wk[Hd * Hd];
__device__ __half g_wv[Hd * Hd];
__device__ __half g_wo[Hd * Hd];
__device__ __half g_wi[Id * Hd];
__device__ __half g_w2[Hd * Id];

// ---------------- helpers ----------------
__device__ __forceinline__ uint32_t smem_u32(const void* p) {
  uint32_t a;
  asm("{ .reg .u64 t; cvta.to.shared.u64 t, %1; cvt.u32.u64 %0, t; }" : "=r"(a) : "l"(p));
  return a;
}
__device__ __forceinline__ void cp_async16(uint32_t dst, const void* src) {
  asm volatile("cp.async.cg.shared.global [%0], [%1], 16;" :: "r"(dst), "l"(src) : "memory");
}
#define CP_COMMIT() asm volatile("cp.async.commit_group;" ::: "memory")
#define CP_WAIT(n)  asm volatile("cp.async.wait_group %0;" :: "n"(n) : "memory")

__device__ __forceinline__ void ldsm4(uint32_t* r, uint32_t addr) {
  asm volatile("ldmatrix.sync.aligned.m8n8.x4.shared.b16 {%0,%1,%2,%3}, [%4];"
               : "=r"(r[0]), "=r"(r[1]), "=r"(r[2]), "=r"(r[3]) : "r"(addr));
}
__device__ __forceinline__ void ldsm4t(uint32_t* r, uint32_t addr) {
  asm volatile("ldmatrix.sync.aligned.m8n8.x4.trans.shared.b16 {%0,%1,%2,%3}, [%4];"
               : "=r"(r[0]), "=r"(r[1]), "=r"(r[2]), "=r"(r[3]) : "r"(addr));
}
__device__ __forceinline__ void mma16816(float* d, const uint32_t* a, const uint32_t* b) {
  asm volatile("mma.sync.aligned.m16n8k16.row.col.f32.f16.f16.f32 "
               "{%0,%1,%2,%3}, {%4,%5,%6,%7}, {%8,%9}, {%0,%1,%2,%3};"
               : "+f"(d[0]), "+f"(d[1]), "+f"(d[2]), "+f"(d[3])
               : "r"(a[0]), "r"(a[1]), "r"(a[2]), "r"(a[3]), "r"(b[0]), "r"(b[1]));
}
__device__ __forceinline__ uint32_t packh(float a, float b) {
  __half2 t = __floats2half2_rn(a, b);
  return *(uint32_t*)&t;
}

__device__ __forceinline__ uint32_t swz64(int row, int c16) {
  return (uint32_t)(row * 64 + ((c16 ^ ((row >> 1) & 3)) << 4));
}
__device__ __forceinline__ uint32_t swz128(int row, int c16) {
  return (uint32_t)(row * 128 + ((c16 ^ (row & 7)) << 4));
}

// ---------------- batched weight conversion ----------------
struct CvtJobs {
  const float* W[6];
  __half* T[6];
  int K[6], N[6], tilesX[6], start[6];
};

__global__ void __launch_bounds__(256) cvt_wt_all_kernel(CvtJobs jb) {
  const int b = blockIdx.x;
  int j = 0;
  #pragma unroll
  for (int i = 1; i < 6; i++) if (b >= jb.start[i]) j = i;
  const int local = b - jb.start[j];
  const int K = jb.K[j], N = jb.N[j];
  const int nb = (local % jb.tilesX[j]) * 32;
  const int kb = (local / jb.tilesX[j]) * 32;
  const float* W = jb.W[j];
  __half* T = jb.T[j];

  __shared__ float t[32][33];
  const int tx = threadIdx.x & 31, ty = threadIdx.x >> 5;
  #pragma unroll
  for (int i = 0; i < 32; i += 8)
    t[ty + i][tx] = W[(size_t)(kb + ty + i) * N + nb + tx];
  __syncthreads();
  #pragma unroll
  for (int i = 0; i < 32; i += 8)
    T[(size_t)(nb + ty + i) * K + kb + tx] = __float2half_rn(t[tx][ty + i]);
}

// ---------------- HMMA GEMM: C[M,N] = A @ B^T (B stored [N,K]) ----------------
// 256x128 CTA tile, BK=32, 8 warps (4m x 2n), warp tile 64x64, 3-stage cp.async.
struct GemmJob {
  const __half *A, *B;
  const float* bias;
  float* C;
  __half* Ch;
  int outmode;   // 0: fp32 C; 2: fp16 Ch
  int gelu;
};

__global__ void __launch_bounds__(256, 1)
gemm_mma_kernel(GemmJob j0, GemmJob j1, GemmJob j2, int M, int N, int K) {
  extern __shared__ __align__(128) char sm[];
  const uint32_t smb = smem_u32(sm);
  const GemmJob j = (blockIdx.z == 0) ? j0 : ((blockIdx.z == 1) ? j1 : j2);
  const int tid = threadIdx.x;
  const int wid = tid >> 5, lane = tid & 31;
  const int bm = blockIdx.y * 256, bn = blockIdx.x * 128;
  const int warp_m = wid & 3, warp_n = wid >> 2;
  const int NK = K >> 5;

  // per-stage: A 16KB, B 8KB -> 24KB/stage
  auto soA = [](int s) -> uint32_t { return (uint32_t)(s * 24576); };
  auto soB = [](int s) -> uint32_t { return (uint32_t)(s * 24576 + 16384); };

  auto load_stage = [&](int kt, int s) {
    const int koff = kt * 32;
    #pragma unroll
    for (int jj = 0; jj < 4; jj++) {            // A: 1024 chunks
      const int ch = tid + jj * 256;
      const int row = ch >> 2, c = ch & 3;
      cp_async16(smb + soA(s) + swz64(row, c),
                 j.A + (size_t)(bm + row) * K + koff + c * 8);
    }
    #pragma unroll
    for (int jj = 0; jj < 2; jj++) {            // B: 512 chunks
      const int ch = tid + jj * 256;
      const int row = ch >> 2, c = ch & 3;
      cp_async16(smb + soB(s) + swz64(row, c),
                 j.B + (size_t)(bn + row) * K + koff + c * 8);
    }
  };

  float acc[4][8][4];
  #pragma unroll
  for (int i = 0; i < 4; i++)
    #pragma unroll
    for (int jj = 0; jj < 8; jj++)
      #pragma unroll
      for (int q = 0; q < 4; q++) acc[i][jj][q] = 0.f;

  load_stage(0, 0); CP_COMMIT();
  load_stage(1, 1); CP_COMMIT();

  const int la_row = (lane & 7) + ((lane >> 3) & 1) * 8;
  const int la_c   = (lane >> 4);
  const int lb_row = (lane & 7) + (lane >> 4) * 8;
  const int lb_c   = (lane >> 3) & 1;

  for (int kt = 0; kt < NK; kt++) {
    const int s = kt % 3;
    if (kt + 1 < NK) { CP_WAIT(1); } else { CP_WAIT(0); }
    __syncthreads();
    if (kt + 2 < NK) { load_stage(kt + 2, (kt + 2) % 3); CP_COMMIT(); }

    const uint32_t baseA = smb + soA(s);
    const uint32_t baseB = smb + soB(s);

    #pragma unroll
    for (int ks = 0; ks < 2; ks++) {
      uint32_t a4[4][4], b4[4][4];
      #pragma unroll
      for (int tm = 0; tm < 4; tm++)
        ldsm4(a4[tm], baseA + swz64(warp_m * 64 + tm * 16 + la_row, ks * 2 + la_c));
      #pragma unroll
      for (int tn2 = 0; tn2 < 4; tn2++)
        ldsm4(b4[tn2], baseB + swz64(warp_n * 64 + tn2 * 16 + lb_row, ks * 2 + lb_c));
      #pragma unroll
      for (int tm = 0; tm < 4; tm++)
        #pragma unroll
        for (int tn = 0; tn < 8; tn++)
          mma16816(acc[tm][tn], a4[tm], &b4[tn >> 1][(tn & 1) * 2]);
    }
  }

  // epilogue
  const int g = lane >> 2, tq = lane & 3;
  #pragma unroll
  for (int tm = 0; tm < 4; tm++) {
    #pragma unroll
    for (int tn = 0; tn < 8; tn++) {
      const int col = bn + warp_n * 64 + tn * 8 + tq * 2;
      const float b0 = j.bias[col], b1 = j.bias[col + 1];
      #pragma unroll
      for (int half = 0; half < 2; half++) {
        const int row = bm + warp_m * 64 + tm * 16 + g + half * 8;
        float vx = acc[tm][tn][half * 2 + 0] + b0;
        float vy = acc[tm][tn][half * 2 + 1] + b1;
        if (j.gelu) {
          vx = 0.5f * vx * (1.0f + erff(vx * 0.7071067811865476f));
          vy = 0.5f * vy * (1.0f + erff(vy * 0.7071067811865476f));
        }
        if (j.outmode == 0) {
          float2 v; v.x = vx; v.y = vy;
          *(float2*)(j.C + (size_t)row * N + col) = v;
        } else {
          *(uint32_t*)(j.Ch + (size_t)row * N + col) = packh(vx, vy);
        }
      }
    }
  }
}

// ---------------- HMMA flash attention (fp16, fp32 accum) ----------------
__global__ void __launch_bounds__(128, 3)
attn_mma_kernel(const __half* __restrict__ Qh,
                const __half* __restrict__ Kh, const __half* __restrict__ Vh,
                const float* __restrict__ mask,
                __half* __restrict__ Ch) {
  extern __shared__ __align__(128) char sm[];
  const uint32_t smb = smem_u32(sm);
  const int tid = threadIdx.x;
  const int warp = tid >> 5, lane = tid & 31;
  const int qt = blockIdx.x, h = blockIdx.y, b = blockIdx.z;
  const int g = lane >> 2, tq = lane & 3;

  const int la_row = (lane & 7) + ((lane >> 3) & 1) * 8;
  const int la_c   = (lane >> 4);
  const int lb_row = (lane & 7) + (lane >> 4) * 8;
  const int lb_c   = (lane >> 3) & 1;
  const int lv_row = (lane & 7) + ((lane >> 3) & 1) * 8;
  const int lv_c   = (lane >> 4);

  {
    #pragma unroll
    for (int jj = 0; jj < 4; jj++) {
      const int ch = tid + jj * 128;
      const int row = ch >> 3, c = ch & 7;
      cp_async16(smb + swz128(row, c),
                 Qh + (size_t)(b * 1024 + qt * 64 + row) * Hd + h * 64 + c * 8);
    }
  }
  auto load_kv = [&](int kt, int s) {
    const uint32_t so = smb + 8192 + s * 16384;
    #pragma unroll
    for (int jj = 0; jj < 4; jj++) {
      const int ch = tid + jj * 128;
      const int row = ch >> 3, c = ch & 7;
      const uint32_t d = swz128(row, c);
      const size_t gk = (size_t)(b * 1024 + kt * 64 + row) * Hd + h * 64 + c * 8;
      cp_async16(so + d,        Kh + gk);
      cp_async16(so + 8192 + d, Vh + gk);
    }
  };
  load_kv(0, 0);
  CP_COMMIT();

  float m0 = -1e30f, m1 = -1e30f, l0 = 0.f, l1 = 0.f;
  float oacc[8][4];
  #pragma unroll
  for (int jj = 0; jj < 8; jj++)
    #pragma unroll
    for (int q = 0; q < 4; q++) oacc[jj][q] = 0.f;

  for (int kt = 0; kt < 16; kt++) {
    const int s = kt & 1;
    if (kt + 1 < 16) { load_kv(kt + 1, 1 - s); CP_COMMIT(); CP_WAIT(1); }
    else             { CP_WAIT(0); }
    __syncthreads();

    const uint32_t sK = smb + 8192 + s * 16384;
    const uint32_t sV = sK + 8192;

    float sacc[8][4];
    #pragma unroll
    for (int jj = 0; jj < 8; jj++)
      #pragma unroll
      for (int q = 0; q < 4; q++) sacc[jj][q] = 0.f;

    #pragma unroll
    for (int kc = 0; kc < 4; kc++) {
      uint32_t q4[4];
      ldsm4(q4, smb + swz128(warp * 16 + la_row, kc * 2 + la_c));
      #pragma unroll
      for (int n16 = 0; n16 < 4; n16++) {
        uint32_t k4[4];
        ldsm4(k4, sK + swz128(n16 * 16 + lb_row, kc * 2 + lb_c));
        mma16816(sacc[2 * n16],     q4, k4);
        mma16816(sacc[2 * n16 + 1], q4, k4 + 2);
      }
    }

    const float* mrow = mask + b * 1024 + kt * 64;
    float mx0 = -1e30f, mx1 = -1e30f;
    #pragma unroll
    for (int jj = 0; jj < 8; jj++) {
      const float2 mv = *(const float2*)(mrow + jj * 8 + 2 * tq);
      sacc[jj][0] = sacc[jj][0] * 0.125f + mv.x;
      sacc[jj][1] = sacc[jj][1] * 0.125f + mv.y;
      sacc[jj][2] = sacc[jj][2] * 0.125f + mv.x;
      sacc[jj][3] = sacc[jj][3] * 0.125f + mv.y;
      mx0 = fmaxf(mx0, fmaxf(sacc[jj][0], sacc[jj][1]));
      mx1 = fmaxf(mx1, fmaxf(sacc[jj][2], sacc[jj][3]));
    }
    mx0 = fmaxf(mx0, __shfl_xor_sync(0xffffffffu, mx0, 1));
    mx0 = fmaxf(mx0, __shfl_xor_sync(0xffffffffu, mx0, 2));
    mx1 = fmaxf(mx1, __shfl_xor_sync(0xffffffffu, mx1, 1));
    mx1 = fmaxf(mx1, __shfl_xor_sync(0xffffffffu, mx1, 2));
    const float mn0 = fmaxf(m0, mx0), mn1 = fmaxf(m1, mx1);
    const float rs0 = __expf(m0 - mn0), rs1 = __expf(m1 - mn1);
    m0 = mn0; m1 = mn1;

    float sum0 = 0.f, sum1 = 0.f;
    uint32_t ph01[8], ph23[8];
    #pragma unroll
    for (int jj = 0; jj < 8; jj++) {
      const float p0 = __expf(sacc[jj][0] - mn0), p1 = __expf(sacc[jj][1] - mn0);
      const float p2 = __expf(sacc[jj][2] - mn1), p3 = __expf(sacc[jj][3] - mn1);
      sum0 += p0 + p1; sum1 += p2 + p3;
      ph01[jj] = packh(p0, p1);
      ph23[jj] = packh(p2, p3);
      oacc[jj][0] *= rs0; oacc[jj][1] *= rs0;
      oacc[jj][2] *= rs1; oacc[jj][3] *= rs1;
    }
    sum0 += __shfl_xor_sync(0xffffffffu, sum0, 1);
    sum0 += __shfl_xor_sync(0xffffffffu, sum0, 2);
    sum1 += __shfl_xor_sync(0xffffffffu, sum1, 1);
    sum1 += __shfl_xor_sync(0xffffffffu, sum1, 2);
    l0 = l0 * rs0 + sum0;
    l1 = l1 * rs1 + sum1;

    #pragma unroll
    for (int kc = 0; kc < 4; kc++) {
      uint32_t ah[4] = {ph01[2*kc], ph23[2*kc], ph01[2*kc+1], ph23[2*kc+1]};
      #pragma unroll
      for (int n16 = 0; n16 < 4; n16++) {
        uint32_t v4[4];
        ldsm4t(v4, sV + swz128(kc * 16 + lv_row, n16 * 2 + lv_c));
        mma16816(oacc[2 * n16],     ah, v4);
        mma16816(oacc[2 * n16 + 1], ah, v4 + 2);
      }
    }
    __syncthreads();
  }

  const float inv0 = 1.f / l0, inv1 = 1.f / l1;
  const int row0 = b * 1024 + qt * 64 + warp * 16 + g;
  #pragma unroll
  for (int jj = 0; jj < 8; jj++) {
    const int col = h * 64 + (jj >> 1) * 16 + (jj & 1) * 8 + 2 * tq;
    *(uint32_t*)(Ch + (size_t)row0 * Hd + col)       = packh(oacc[jj][0] * inv0, oacc[jj][1] * inv0);
    *(uint32_t*)(Ch + (size_t)(row0 + 8) * Hd + col) = packh(oacc[jj][2] * inv1, oacc[jj][3] * inv1);
  }
}

// ---------------- routing ----------------
__global__ void __launch_bounds__(256) routing_kernel(
    const float* __restrict__ x, const float* __restrict__ y,
    const int* __restrict__ tptr,
    float* __restrict__ xs,
    __half* __restrict__ xh, __half* __restrict__ yh) {
  const int token = blockIdx.x, tid = threadIdx.x;
  const long base = (long)token * Hd;
  float sxx = 0.f, sxy = 0.f, syy = 0.f;
  for (int i = tid; i < Hd; i += 256) {
    float a = x[base + i], bb = y[base + i];
    sxx += a * a; sxy += a * bb; syy += bb * bb;
  }
  #pragma unroll
  for (int o = 16; o; o >>= 1) {
    sxx += __shfl_xor_sync(0xffffffffu, sxx, o);
    sxy += __shfl_xor_sync(0xffffffffu, sxy, o);
    syy += __shfl_xor_sync(0xffffffffu, syy, o);
  }
  __shared__ float red[8][3];
  __shared__ float sc[2];
  if ((tid & 31) == 0) { red[tid >> 5][0] = sxx; red[tid >> 5][1] = sxy; red[tid >> 5][2] = syy; }
  __syncthreads();
  if (tid == 0) {
    float a = 0.f, bb = 0.f, c = 0.f;
    #pragma unroll
    for (int i = 0; i < 8; i++) { a += red[i][0]; bb += red[i][1]; c += red[i][2]; }
    const int t = *tptr;
    float b1 = 0.f, b2 = 0.f, c1 = 0.5f, c2 = 0.5f;
    for (int it = 0; it < t; it++) {
      if (it > 0) {
        float mm = fmaxf(b1, b2);
        float e1 = expf(b1 - mm), e2 = expf(b2 - mm);
        float inv = 1.0f / (e1 + e2);
        c1 = e1 * inv; c2 = e2 * inv;
      }
      float vv = c1 * c1 * a + 2.0f * c1 * c2 * bb + c2 * c2 * c;
      float n  = sqrtf(vv);
      float f  = n / (1.0f + vv);
      b1 += f * (c1 * a  + c2 * bb);
      b2 += f * (c1 * bb + c2 * c );
    }
    sc[0] = c1; sc[1] = c2;
  }
  __syncthreads();
  const float c1 = sc[0], c2 = sc[1];
  for (int i = tid; i < Hd; i += 256) {
    const float vx = c1 * x[base + i];
    const float vy = c2 * y[base + i];
    xs[base + i] = vx;
    xh[base + i] = __float2half_rn(vx);
    yh[base + i] = __float2half_rn(vy);
  }
}

// ---------------- fused residual + RMSNorm ----------------
template<bool FOUT>
__global__ void __launch_bounds__(256) rms_kernel(
    const float* __restrict__ in, const float* __restrict__ res,
    const float* __restrict__ g, float* __restrict__ out,
    __half* __restrict__ oh) {
  const int row = blockIdx.x, tid = threadIdx.x;
  __shared__ float buf[Hd];
  __shared__ float red[8];
  __shared__ float s_inv;
  const long base = (long)row * Hd;
  float ss = 0.f;
  for (int i = tid; i < Hd; i += 256) {
    float v = in[base + i] + res[base + i];
    buf[i] = v; ss += v * v;
  }
  #pragma unroll
  for (int o = 16; o; o >>= 1) ss += __shfl_xor_sync(0xffffffffu, ss, o);
  if ((tid & 31) == 0) red[tid >> 5] = ss;
  __syncthreads();
  if (tid == 0) {
    float tot = 0.f;
    #pragma unroll
    for (int i = 0; i < 8; i++) tot += red[i];
    s_inv = rsqrtf(tot * (1.0f / (float)Hd) + 1e-6f);
  }
  __syncthreads();
  const float inv = s_inv;
  for (int i = tid; i < Hd; i += 256) {
    const float v = buf[i] * inv * g[i];
    out[base + i] = v;
    if (FOUT) oh[base + i] = __float2half_rn(v);
  }
}

// ---------------- host ----------------
static const int GEMM_SMEM = 73728;   // 3 stages x 24KB
static const int ATTN_SMEM = 40960;

extern "C" void kernel_launch(void* const* d_in, const int* in_sizes, int n_in,
                              void* d_out, int out_size) {
  const float* x    = (const float*)d_in[0];
  const float* y    = (const float*)d_in[1];
  const float* mask = (const float*)d_in[2];
  const float* Wq   = (const float*)d_in[3];
  const float* bq   = (const float*)d_in[4];
  const float* Wk   = (const float*)d_in[5];
  const float* bk   = (const float*)d_in[6];
  const float* Wv   = (const float*)d_in[7];
  const float* bv   = (const float*)d_in[8];
  const float* Wo   = (const float*)d_in[9];
  const float* bo   = (const float*)d_in[10];
  const float* g1   = (const float*)d_in[11];
  const float* Wi   = (const float*)d_in[12];
  const float* bi   = (const float*)d_in[13];
  const float* Wo2  = (const float*)d_in[14];
  const float* bo2  = (const float*)d_in[15];
  const float* g2   = (const float*)d_in[16];
  const int*   t    = (const int*)d_in[17];
  float* out = (float*)d_out;

  cudaFuncSetAttribute(gemm_mma_kernel, cudaFuncAttributeMaxDynamicSharedMemorySize, GEMM_SMEM);
  cudaFuncSetAttribute(attn_mma_kernel, cudaFuncAttributeMaxDynamicSharedMemorySize, ATTN_SMEM);

  float *xs, *att, *tmp;
  cudaGetSymbolAddress((void**)&xs,  g_xs);
  cudaGetSymbolAddress((void**)&att, g_att);
  cudaGetSymbolAddress((void**)&tmp, g_tmp);

  __half *xh,*yh,*qh,*kh,*vh,*ch,*ah,*ih;
  cudaGetSymbolAddress((void**)&xh, g_xh);
  cudaGetSymbolAddress((void**)&yh, g_yh);
  cudaGetSymbolAddress((void**)&qh, g_qh);
  cudaGetSymbolAddress((void**)&kh, g_kh);
  cudaGetSymbolAddress((void**)&vh, g_vh);
  cudaGetSymbolAddress((void**)&ch, g_ch);
  cudaGetSymbolAddress((void**)&ah, g_ah);
  cudaGetSymbolAddress((void**)&ih, g_ih);

  __half *wq,*wk,*wv,*wo,*wi,*w2;
  cudaGetSymbolAddress((void**)&wq, g_wq);
  cudaGetSymbolAddress((void**)&wk, g_wk);
  cudaGetSymbolAddress((void**)&wv, g_wv);
  cudaGetSymbolAddress((void**)&wo, g_wo);
  cudaGetSymbolAddress((void**)&wi, g_wi);
  cudaGetSymbolAddress((void**)&w2, g_w2);

  routing_kernel<<<TOK, 256>>>(x, y, t, xs, xh, yh);

  {
    CvtJobs jb;
    const float* Ws[6] = {Wq, Wk, Wv, Wo, Wi, Wo2};
    __half* Ts[6] = {wq, wk, wv, wo, wi, w2};
    int Ks[6] = {Hd, Hd, Hd, Hd, Hd, Id};
    int Ns[6] = {Hd, Hd, Hd, Hd, Id, Hd};
    int cum = 0;
    for (int i = 0; i < 6; i++) {
      jb.W[i] = Ws[i]; jb.T[i] = Ts[i];
      jb.K[i] = Ks[i]; jb.N[i] = Ns[i];
      jb.tilesX[i] = Ns[i] / 32;
      jb.start[i] = cum;
      cum += (Ns[i] / 32) * (Ks[i] / 32);
    }
    cvt_wt_all_kernel<<<cum, 256>>>(jb);
  }

  // fused QKV (z = 0,1,2)
  {
    GemmJob jq = {xh, wq, bq, nullptr, qh, 2, 0};
    GemmJob jk = {yh, wk, bk, nullptr, kh, 2, 0};
    GemmJob jv = {yh, wv, bv, nullptr, vh, 2, 0};
    gemm_mma_kernel<<<dim3(Hd/128, TOK/256, 3), 256, GEMM_SMEM>>>(jq, jk, jv, TOK, Hd, Hd);
  }

  attn_mma_kernel<<<dim3(16, NHh, 4), 128, ATTN_SMEM>>>(qh, kh, vh, mask, ch);

  {
    GemmJob jo = {ch, wo, bo, tmp, nullptr, 0, 0};
    gemm_mma_kernel<<<dim3(Hd/128, TOK/256, 1), 256, GEMM_SMEM>>>(jo, jo, jo, TOK, Hd, Hd);
  }
  rms_kernel<true ><<<TOK, 256>>>(tmp, xs, g1, att, ah);

  {
    GemmJob ji = {ah, wi, bi, nullptr, ih, 2, 1};
    gemm_mma_kernel<<<dim3(Id/128, TOK/256, 1), 256, GEMM_SMEM>>>(ji, ji, ji, TOK, Id, Hd);
  }
  {
    GemmJob j2 = {ih, w2, bo2, tmp, nullptr, 0, 0};
    gemm_mma_kernel<<<dim3(Hd/128, TOK/256, 1), 256, GEMM_SMEM>>>(j2, j2, j2, TOK, Hd, Id);
  }
  rms_kernel<false><<<TOK, 256>>>(tmp, att, g2, out, nullptr);
}

// round 8
// speedup vs baseline: 8.3821x; 1.2003x over previous
#include <cuda_runtime.h>
#include <cuda_fp16.h>
#include <math.h>
#include <stdint.h>

#define TOK 4096        // B*S
#define Hd  1024
#define Id  4096
#define NHh 16
#define DHh 64

// ---------------- scratch (device globals; no allocs) ----------------
__device__ float g_xs [TOK * Hd];
__device__ float g_att[TOK * Hd];
__device__ float g_tmp[TOK * Hd];

// fp16 activation buffers
__device__ __half g_xh[TOK * Hd];
__device__ __half g_yh[TOK * Hd];
__device__ __half g_qh[TOK * Hd];
__device__ __half g_kh[TOK * Hd];
__device__ __half g_vh[TOK * Hd];
__device__ __half g_ch[TOK * Hd];
__device__ __half g_ah[TOK * Hd];
__device__ __half g_ih[TOK * Id];

// transposed fp16 weights [N, K]
__device__ __half g_wq[Hd * Hd];
__device__ __half g_wk[Hd * Hd];
__device__ __half g_wv[Hd * Hd];
__device__ __half g_wo[Hd * Hd];
__device__ __half g_wi[Id * Hd];
__device__ __half g_w2[Hd * Id];

// ---------------- helpers ----------------
__device__ __forceinline__ uint32_t smem_u32(const void* p) {
  uint32_t a;
  asm("{ .reg .u64 t; cvta.to.shared.u64 t, %1; cvt.u32.u64 %0, t; }" : "=r"(a) : "l"(p));
  return a;
}
__device__ __forceinline__ void cp_async16(uint32_t dst, const void* src) {
  asm volatile("cp.async.cg.shared.global [%0], [%1], 16;" :: "r"(dst), "l"(src) : "memory");
}
#define CP_COMMIT() asm volatile("cp.async.commit_group;" ::: "memory")
#define CP_WAIT(n)  asm volatile("cp.async.wait_group %0;" :: "n"(n) : "memory")

__device__ __forceinline__ void ldsm4(uint32_t* r, uint32_t addr) {
  asm volatile("ldmatrix.sync.aligned.m8n8.x4.shared.b16 {%0,%1,%2,%3}, [%4];"
               : "=r"(r[0]), "=r"(r[1]), "=r"(r[2]), "=r"(r[3]) : "r"(addr));
}
__device__ __forceinline__ void ldsm4t(uint32_t* r, uint32_t addr) {
  asm volatile("ldmatrix.sync.aligned.m8n8.x4.trans.shared.b16 {%0,%1,%2,%3}, [%4];"
               : "=r"(r[0]), "=r"(r[1]), "=r"(r[2]), "=r"(r[3]) : "r"(addr));
}
__device__ __forceinline__ void mma16816(float* d, const uint32_t* a, const uint32_t* b) {
  asm volatile("mma.sync.aligned.m16n8k16.row.col.f32.f16.f16.f32 "
               "{%0,%1,%2,%3}, {%4,%5,%6,%7}, {%8,%9}, {%0,%1,%2,%3};"
               : "+f"(d[0]), "+f"(d[1]), "+f"(d[2]), "+f"(d[3])
               : "r"(a[0]), "r"(a[1]), "r"(a[2]), "r"(a[3]), "r"(b[0]), "r"(b[1]));
}
__device__ __forceinline__ uint32_t packh(float a, float b) {
  __half2 t = __floats2half2_rn(a, b);
  return *(uint32_t*)&t;
}

__device__ __forceinline__ uint32_t swz64(int row, int c16) {
  return (uint32_t)(row * 64 + ((c16 ^ ((row >> 1) & 3)) << 4));
}
__device__ __forceinline__ uint32_t swz128(int row, int c16) {
  return (uint32_t)(row * 128 + ((c16 ^ (row & 7)) << 4));
}

// ---------------- batched weight conversion ----------------
struct CvtJobs {
  const float* W[6];
  __half* T[6];
  int K[6], N[6], tilesX[6], start[6];
};

__global__ void __launch_bounds__(256) cvt_wt_all_kernel(CvtJobs jb) {
  const int b = blockIdx.x;
  int j = 0;
  #pragma unroll
  for (int i = 1; i < 6; i++) if (b >= jb.start[i]) j = i;
  const int local = b - jb.start[j];
  const int K = jb.K[j], N = jb.N[j];
  const int nb = (local % jb.tilesX[j]) * 32;
  const int kb = (local / jb.tilesX[j]) * 32;
  const float* W = jb.W[j];
  __half* T = jb.T[j];

  __shared__ float t[32][33];
  const int tx = threadIdx.x & 31, ty = threadIdx.x >> 5;
  #pragma unroll
  for (int i = 0; i < 32; i += 8)
    t[ty + i][tx] = W[(size_t)(kb + ty + i) * N + nb + tx];
  __syncthreads();
  #pragma unroll
  for (int i = 0; i < 32; i += 8)
    T[(size_t)(nb + ty + i) * K + kb + tx] = __float2half_rn(t[tx][ty + i]);
}

// ---------------- HMMA GEMM: C[M,N] = A @ B^T (B stored [N,K]) ----------------
// 128x128 CTA tile, BK=32, 8 warps (2m x 4n), warp tile 64x32, 4-stage cp.async,
// 2 CTAs/SM (regs capped at 128 via launch_bounds).
struct GemmJob {
  const __half *A, *B;
  const float* bias;
  float* C;
  __half* Ch;
  int outmode;   // 0: fp32 C; 2: fp16 Ch
  int gelu;
};

__global__ void __launch_bounds__(256, 2)
gemm_mma_kernel(GemmJob j0, GemmJob j1, GemmJob j2, int M, int N, int K) {
  extern __shared__ __align__(128) char sm[];
  const uint32_t smb = smem_u32(sm);
  const GemmJob j = (blockIdx.z == 0) ? j0 : ((blockIdx.z == 1) ? j1 : j2);
  const int tid = threadIdx.x;
  const int wid = tid >> 5, lane = tid & 31;
  const int bm = blockIdx.y * 128, bn = blockIdx.x * 128;
  const int warp_m = wid & 1, warp_n = wid >> 1;
  const int NK = K >> 5;

  // per-stage: A 8KB + B 8KB = 16KB; 4 stages = 64KB
  auto soA = [](int s) -> uint32_t { return (uint32_t)(s * 16384); };
  auto soB = [](int s) -> uint32_t { return (uint32_t)(s * 16384 + 8192); };

  auto load_stage = [&](int kt, int s) {
    const int koff = kt * 32;
    #pragma unroll
    for (int jj = 0; jj < 2; jj++) {
      const int ch = tid + jj * 256;
      const int row = ch >> 2, c = ch & 3;
      const uint32_t d = swz64(row, c);
      cp_async16(smb + soA(s) + d, j.A + (size_t)(bm + row) * K + koff + c * 8);
      cp_async16(smb + soB(s) + d, j.B + (size_t)(bn + row) * K + koff + c * 8);
    }
  };

  float acc[4][4][4];
  #pragma unroll
  for (int i = 0; i < 4; i++)
    #pragma unroll
    for (int jj = 0; jj < 4; jj++)
      #pragma unroll
      for (int q = 0; q < 4; q++) acc[i][jj][q] = 0.f;

  load_stage(0, 0); CP_COMMIT();
  load_stage(1, 1); CP_COMMIT();
  load_stage(2, 2); CP_COMMIT();

  const int la_row = (lane & 7) + ((lane >> 3) & 1) * 8;
  const int la_c   = (lane >> 4);
  const int lb_row = (lane & 7) + (lane >> 4) * 8;
  const int lb_c   = (lane >> 3) & 1;

  for (int kt = 0; kt < NK; kt++) {
    const int s = kt & 3;
    const int rem = NK - 1 - kt;
    if (rem >= 2) { CP_WAIT(2); } else if (rem == 1) { CP_WAIT(1); } else { CP_WAIT(0); }
    __syncthreads();
    if (kt + 3 < NK) { load_stage(kt + 3, (kt + 3) & 3); CP_COMMIT(); }

    const uint32_t baseA = smb + soA(s);
    const uint32_t baseB = smb + soB(s);

    #pragma unroll
    for (int ks = 0; ks < 2; ks++) {
      uint32_t a4[4][4], b4[2][4];
      #pragma unroll
      for (int tm = 0; tm < 4; tm++)
        ldsm4(a4[tm], baseA + swz64(warp_m * 64 + tm * 16 + la_row, ks * 2 + la_c));
      #pragma unroll
      for (int tn2 = 0; tn2 < 2; tn2++)
        ldsm4(b4[tn2], baseB + swz64(warp_n * 32 + tn2 * 16 + lb_row, ks * 2 + lb_c));
      #pragma unroll
      for (int tm = 0; tm < 4; tm++)
        #pragma unroll
        for (int tn = 0; tn < 4; tn++)
          mma16816(acc[tm][tn], a4[tm], &b4[tn >> 1][(tn & 1) * 2]);
    }
  }

  // epilogue
  const int g = lane >> 2, tq = lane & 3;
  #pragma unroll
  for (int tm = 0; tm < 4; tm++) {
    #pragma unroll
    for (int tn = 0; tn < 4; tn++) {
      const int col = bn + warp_n * 32 + tn * 8 + tq * 2;
      const float b0 = j.bias[col], b1 = j.bias[col + 1];
      #pragma unroll
      for (int half = 0; half < 2; half++) {
        const int row = bm + warp_m * 64 + tm * 16 + g + half * 8;
        float vx = acc[tm][tn][half * 2 + 0] + b0;
        float vy = acc[tm][tn][half * 2 + 1] + b1;
        if (j.gelu) {
          vx = 0.5f * vx * (1.0f + erff(vx * 0.7071067811865476f));
          vy = 0.5f * vy * (1.0f + erff(vy * 0.7071067811865476f));
        }
        if (j.outmode == 0) {
          float2 v; v.x = vx; v.y = vy;
          *(float2*)(j.C + (size_t)row * N + col) = v;
        } else {
          *(uint32_t*)(j.Ch + (size_t)row * N + col) = packh(vx, vy);
        }
      }
    }
  }
}

// ---------------- HMMA flash attention (fp16, fp32 accum) ----------------
__global__ void __launch_bounds__(128, 2)
attn_mma_kernel(const __half* __restrict__ Qh,
                const __half* __restrict__ Kh, const __half* __restrict__ Vh,
                const float* __restrict__ mask,
                __half* __restrict__ Ch) {
  extern __shared__ __align__(128) char sm[];
  const uint32_t smb = smem_u32(sm);
  const int tid = threadIdx.x;
  const int warp = tid >> 5, lane = tid & 31;
  const int qt = blockIdx.x, h = blockIdx.y, b = blockIdx.z;
  const int g = lane >> 2, tq = lane & 3;

  const int la_row = (lane & 7) + ((lane >> 3) & 1) * 8;
  const int la_c   = (lane >> 4);
  const int lb_row = (lane & 7) + (lane >> 4) * 8;
  const int lb_c   = (lane >> 3) & 1;
  const int lv_row = (lane & 7) + ((lane >> 3) & 1) * 8;
  const int lv_c   = (lane >> 4);

  {
    #pragma unroll
    for (int jj = 0; jj < 4; jj++) {
      const int ch = tid + jj * 128;
      const int row = ch >> 3, c = ch & 7;
      cp_async16(smb + swz128(row, c),
                 Qh + (size_t)(b * 1024 + qt * 64 + row) * Hd + h * 64 + c * 8);
    }
  }
  auto load_kv = [&](int kt, int s) {
    const uint32_t so = smb + 8192 + s * 16384;
    #pragma unroll
    for (int jj = 0; jj < 4; jj++) {
      const int ch = tid + jj * 128;
      const int row = ch >> 3, c = ch & 7;
      const uint32_t d = swz128(row, c);
      const size_t gk = (size_t)(b * 1024 + kt * 64 + row) * Hd + h * 64 + c * 8;
      cp_async16(so + d,        Kh + gk);
      cp_async16(so + 8192 + d, Vh + gk);
    }
  };
  load_kv(0, 0);
  CP_COMMIT();

  float m0 = -1e30f, m1 = -1e30f, l0 = 0.f, l1 = 0.f;
  float oacc[8][4];
  #pragma unroll
  for (int jj = 0; jj < 8; jj++)
    #pragma unroll
    for (int q = 0; q < 4; q++) oacc[jj][q] = 0.f;

  for (int kt = 0; kt < 16; kt++) {
    const int s = kt & 1;
    if (kt + 1 < 16) { load_kv(kt + 1, 1 - s); CP_COMMIT(); CP_WAIT(1); }
    else             { CP_WAIT(0); }
    __syncthreads();

    const uint32_t sK = smb + 8192 + s * 16384;
    const uint32_t sV = sK + 8192;

    float sacc[8][4];
    #pragma unroll
    for (int jj = 0; jj < 8; jj++)
      #pragma unroll
      for (int q = 0; q < 4; q++) sacc[jj][q] = 0.f;

    #pragma unroll
    for (int kc = 0; kc < 4; kc++) {
      uint32_t q4[4];
      ldsm4(q4, smb + swz128(warp * 16 + la_row, kc * 2 + la_c));
      #pragma unroll
      for (int n16 = 0; n16 < 4; n16++) {
        uint32_t k4[4];
        ldsm4(k4, sK + swz128(n16 * 16 + lb_row, kc * 2 + lb_c));
        mma16816(sacc[2 * n16],     q4, k4);
        mma16816(sacc[2 * n16 + 1], q4, k4 + 2);
      }
    }

    const float* mrow = mask + b * 1024 + kt * 64;
    float mx0 = -1e30f, mx1 = -1e30f;
    #pragma unroll
    for (int jj = 0; jj < 8; jj++) {
      const float2 mv = *(const float2*)(mrow + jj * 8 + 2 * tq);
      sacc[jj][0] = sacc[jj][0] * 0.125f + mv.x;
      sacc[jj][1] = sacc[jj][1] * 0.125f + mv.y;
      sacc[jj][2] = sacc[jj][2] * 0.125f + mv.x;
      sacc[jj][3] = sacc[jj][3] * 0.125f + mv.y;
      mx0 = fmaxf(mx0, fmaxf(sacc[jj][0], sacc[jj][1]));
      mx1 = fmaxf(mx1, fmaxf(sacc[jj][2], sacc[jj][3]));
    }
    mx0 = fmaxf(mx0, __shfl_xor_sync(0xffffffffu, mx0, 1));
    mx0 = fmaxf(mx0, __shfl_xor_sync(0xffffffffu, mx0, 2));
    mx1 = fmaxf(mx1, __shfl_xor_sync(0xffffffffu, mx1, 1));
    mx1 = fmaxf(mx1, __shfl_xor_sync(0xffffffffu, mx1, 2));
    const float mn0 = fmaxf(m0, mx0), mn1 = fmaxf(m1, mx1);
    const float rs0 = __expf(m0 - mn0), rs1 = __expf(m1 - mn1);
    m0 = mn0; m1 = mn1;

    float sum0 = 0.f, sum1 = 0.f;
    uint32_t ph01[8], ph23[8];
    #pragma unroll
    for (int jj = 0; jj < 8; jj++) {
      const float p0 = __expf(sacc[jj][0] - mn0), p1 = __expf(sacc[jj][1] - mn0);
      const float p2 = __expf(sacc[jj][2] - mn1), p3 = __expf(sacc[jj][3] - mn1);
      sum0 += p0 + p1; sum1 += p2 + p3;
      ph01[jj] = packh(p0, p1);
      ph23[jj] = packh(p2, p3);
      oacc[jj][0] *= rs0; oacc[jj][1] *= rs0;
      oacc[jj][2] *= rs1; oacc[jj][3] *= rs1;
    }
    sum0 += __shfl_xor_sync(0xffffffffu, sum0, 1);
    sum0 += __shfl_xor_sync(0xffffffffu, sum0, 2);
    sum1 += __shfl_xor_sync(0xffffffffu, sum1, 1);
    sum1 += __shfl_xor_sync(0xffffffffu, sum1, 2);
    l0 = l0 * rs0 + sum0;
    l1 = l1 * rs1 + sum1;

    #pragma unroll
    for (int kc = 0; kc < 4; kc++) {
      uint32_t ah[4] = {ph01[2*kc], ph23[2*kc], ph01[2*kc+1], ph23[2*kc+1]};
      #pragma unroll
      for (int n16 = 0; n16 < 4; n16++) {
        uint32_t v4[4];
        ldsm4t(v4, sV + swz128(kc * 16 + lv_row, n16 * 2 + lv_c));
        mma16816(oacc[2 * n16],     ah, v4);
        mma16816(oacc[2 * n16 + 1], ah, v4 + 2);
      }
    }
    __syncthreads();
  }

  const float inv0 = 1.f / l0, inv1 = 1.f / l1;
  const int row0 = b * 1024 + qt * 64 + warp * 16 + g;
  #pragma unroll
  for (int jj = 0; jj < 8; jj++) {
    const int col = h * 64 + (jj >> 1) * 16 + (jj & 1) * 8 + 2 * tq;
    *(uint32_t*)(Ch + (size_t)row0 * Hd + col)       = packh(oacc[jj][0] * inv0, oacc[jj][1] * inv0);
    *(uint32_t*)(Ch + (size_t)(row0 + 8) * Hd + col) = packh(oacc[jj][2] * inv1, oacc[jj][3] * inv1);
  }
}

// ---------------- routing ----------------
__global__ void __launch_bounds__(256) routing_kernel(
    const float* __restrict__ x, const float* __restrict__ y,
    const int* __restrict__ tptr,
    float* __restrict__ xs,
    __half* __restrict__ xh, __half* __restrict__ yh) {
  const int token = blockIdx.x, tid = threadIdx.x;
  const long base = (long)token * Hd;
  float sxx = 0.f, sxy = 0.f, syy = 0.f;
  for (int i = tid; i < Hd; i += 256) {
    float a = x[base + i], bb = y[base + i];
    sxx += a * a; sxy += a * bb; syy += bb * bb;
  }
  #pragma unroll
  for (int o = 16; o; o >>= 1) {
    sxx += __shfl_xor_sync(0xffffffffu, sxx, o);
    sxy += __shfl_xor_sync(0xffffffffu, sxy, o);
    syy += __shfl_xor_sync(0xffffffffu, syy, o);
  }
  __shared__ float red[8][3];
  __shared__ float sc[2];
  if ((tid & 31) == 0) { red[tid >> 5][0] = sxx; red[tid >> 5][1] = sxy; red[tid >> 5][2] = syy; }
  __syncthreads();
  if (tid == 0) {
    float a = 0.f, bb = 0.f, c = 0.f;
    #pragma unroll
    for (int i = 0; i < 8; i++) { a += red[i][0]; bb += red[i][1]; c += red[i][2]; }
    const int t = *tptr;
    float b1 = 0.f, b2 = 0.f, c1 = 0.5f, c2 = 0.5f;
    for (int it = 0; it < t; it++) {
      if (it > 0) {
        float mm = fmaxf(b1, b2);
        float e1 = expf(b1 - mm), e2 = expf(b2 - mm);
        float inv = 1.0f / (e1 + e2);
        c1 = e1 * inv; c2 = e2 * inv;
      }
      float vv = c1 * c1 * a + 2.0f * c1 * c2 * bb + c2 * c2 * c;
      float n  = sqrtf(vv);
      float f  = n / (1.0f + vv);
      b1 += f * (c1 * a  + c2 * bb);
      b2 += f * (c1 * bb + c2 * c );
    }
    sc[0] = c1; sc[1] = c2;
  }
  __syncthreads();
  const float c1 = sc[0], c2 = sc[1];
  for (int i = tid; i < Hd; i += 256) {
    const float vx = c1 * x[base + i];
    const float vy = c2 * y[base + i];
    xs[base + i] = vx;
    xh[base + i] = __float2half_rn(vx);
    yh[base + i] = __float2half_rn(vy);
  }
}

// ---------------- fused residual + RMSNorm ----------------
template<bool FOUT>
__global__ void __launch_bounds__(256) rms_kernel(
    const float* __restrict__ in, const float* __restrict__ res,
    const float* __restrict__ g, float* __restrict__ out,
    __half* __restrict__ oh) {
  const int row = blockIdx.x, tid = threadIdx.x;
  __shared__ float buf[Hd];
  __shared__ float red[8];
  __shared__ float s_inv;
  const long base = (long)row * Hd;
  float ss = 0.f;
  for (int i = tid; i < Hd; i += 256) {
    float v = in[base + i] + res[base + i];
    buf[i] = v; ss += v * v;
  }
  #pragma unroll
  for (int o = 16; o; o >>= 1) ss += __shfl_xor_sync(0xffffffffu, ss, o);
  if ((tid & 31) == 0) red[tid >> 5] = ss;
  __syncthreads();
  if (tid == 0) {
    float tot = 0.f;
    #pragma unroll
    for (int i = 0; i < 8; i++) tot += red[i];
    s_inv = rsqrtf(tot * (1.0f / (float)Hd) + 1e-6f);
  }
  __syncthreads();
  const float inv = s_inv;
  for (int i = tid; i < Hd; i += 256) {
    const float v = buf[i] * inv * g[i];
    out[base + i] = v;
    if (FOUT) oh[base + i] = __float2half_rn(v);
  }
}

// ---------------- host ----------------
static const int GEMM_SMEM = 65536;   // 4 stages x 16KB
static const int ATTN_SMEM = 40960;

extern "C" void kernel_launch(void* const* d_in, const int* in_sizes, int n_in,
                              void* d_out, int out_size) {
  const float* x    = (const float*)d_in[0];
  const float* y    = (const float*)d_in[1];
  const float* mask = (const float*)d_in[2];
  const float* Wq   = (const float*)d_in[3];
  const float* bq   = (const float*)d_in[4];
  const float* Wk   = (const float*)d_in[5];
  const float* bk   = (const float*)d_in[6];
  const float* Wv   = (const float*)d_in[7];
  const float* bv   = (const float*)d_in[8];
  const float* Wo   = (const float*)d_in[9];
  const float* bo   = (const float*)d_in[10];
  const float* g1   = (const float*)d_in[11];
  const float* Wi   = (const float*)d_in[12];
  const float* bi   = (const float*)d_in[13];
  const float* Wo2  = (const float*)d_in[14];
  const float* bo2  = (const float*)d_in[15];
  const float* g2   = (const float*)d_in[16];
  const int*   t    = (const int*)d_in[17];
  float* out = (float*)d_out;

  cudaFuncSetAttribute(gemm_mma_kernel, cudaFuncAttributeMaxDynamicSharedMemorySize, GEMM_SMEM);
  cudaFuncSetAttribute(attn_mma_kernel, cudaFuncAttributeMaxDynamicSharedMemorySize, ATTN_SMEM);

  float *xs, *att, *tmp;
  cudaGetSymbolAddress((void**)&xs,  g_xs);
  cudaGetSymbolAddress((void**)&att, g_att);
  cudaGetSymbolAddress((void**)&tmp, g_tmp);

  __half *xh,*yh,*qh,*kh,*vh,*ch,*ah,*ih;
  cudaGetSymbolAddress((void**)&xh, g_xh);
  cudaGetSymbolAddress((void**)&yh, g_yh);
  cudaGetSymbolAddress((void**)&qh, g_qh);
  cudaGetSymbolAddress((void**)&kh, g_kh);
  cudaGetSymbolAddress((void**)&vh, g_vh);
  cudaGetSymbolAddress((void**)&ch, g_ch);
  cudaGetSymbolAddress((void**)&ah, g_ah);
  cudaGetSymbolAddress((void**)&ih, g_ih);

  __half *wq,*wk,*wv,*wo,*wi,*w2;
  cudaGetSymbolAddress((void**)&wq, g_wq);
  cudaGetSymbolAddress((void**)&wk, g_wk);
  cudaGetSymbolAddress((void**)&wv, g_wv);
  cudaGetSymbolAddress((void**)&wo, g_wo);
  cudaGetSymbolAddress((void**)&wi, g_wi);
  cudaGetSymbolAddress((void**)&w2, g_w2);

  routing_kernel<<<TOK, 256>>>(x, y, t, xs, xh, yh);

  {
    CvtJobs jb;
    const float* Ws[6] = {Wq, Wk, Wv, Wo, Wi, Wo2};
    __half* Ts[6] = {wq, wk, wv, wo, wi, w2};
    int Ks[6] = {Hd, Hd, Hd, Hd, Hd, Id};
    int Ns[6] = {Hd, Hd, Hd, Hd, Id, Hd};
    int cum = 0;
    for (int i = 0; i < 6; i++) {
      jb.W[i] = Ws[i]; jb.T[i] = Ts[i];
      jb.K[i] = Ks[i]; jb.N[i] = Ns[i];
      jb.tilesX[i] = Ns[i] / 32;
      jb.start[i] = cum;
      cum += (Ns[i] / 32) * (Ks[i] / 32);
    }
    cvt_wt_all_kernel<<<cum, 256>>>(jb);
  }

  // fused QKV (z = 0,1,2)
  {
    GemmJob jq = {xh, wq, bq, nullptr, qh, 2, 0};
    GemmJob jk = {yh, wk, bk, nullptr, kh, 2, 0};
    GemmJob jv = {yh, wv, bv, nullptr, vh, 2, 0};
    gemm_mma_kernel<<<dim3(Hd/128, TOK/128, 3), 256, GEMM_SMEM>>>(jq, jk, jv, TOK, Hd, Hd);
  }

  attn_mma_kernel<<<dim3(16, NHh, 4), 128, ATTN_SMEM>>>(qh, kh, vh, mask, ch);

  {
    GemmJob jo = {ch, wo, bo, tmp, nullptr, 0, 0};
    gemm_mma_kernel<<<dim3(Hd/128, TOK/128, 1), 256, GEMM_SMEM>>>(jo, jo, jo, TOK, Hd, Hd);
  }
  rms_kernel<true ><<<TOK, 256>>>(tmp, xs, g1, att, ah);

  {
    GemmJob ji = {ah, wi, bi, nullptr, ih, 2, 1};
    gemm_mma_kernel<<<dim3(Id/128, TOK/128, 1), 256, GEMM_SMEM>>>(ji, ji, ji, TOK, Id, Hd);
  }
  {
    GemmJob j2 = {ih, w2, bo2, tmp, nullptr, 0, 0};
    gemm_mma_kernel<<<dim3(Hd/128, TOK/128, 1), 256, GEMM_SMEM>>>(j2, j2, j2, TOK, Hd, Id);
  }
  rms_kernel<false><<<TOK, 256>>>(tmp, att, g2, out, nullptr);
}

// round 9
// speedup vs baseline: 8.8958x; 1.0613x over previous
#include <cuda_runtime.h>
#include <cuda_fp16.h>
#include <math.h>
#include <stdint.h>

#define TOK 4096        // B*S
#define Hd  1024
#define Id  4096
#define NHh 16
#define DHh 64

// ---------------- scratch (device globals; no allocs) ----------------
__device__ float g_xs [TOK * Hd];
__device__ float g_att[TOK * Hd];
__device__ float g_tmp[TOK * Hd];
__device__ float g_mask2[TOK];          // mask * log2(e)

// fp16 activation buffers
__device__ __half g_xh[TOK * Hd];
__device__ __half g_yh[TOK * Hd];
__device__ __half g_qh[TOK * Hd];
__device__ __half g_kh[TOK * Hd];
__device__ __half g_vh[TOK * Hd];
__device__ __half g_ch[TOK * Hd];
__device__ __half g_ah[TOK * Hd];
__device__ __half g_ih[TOK * Id];

// transposed fp16 weights [N, K]
__device__ __half g_wq[Hd * Hd];
__device__ __half g_wk[Hd * Hd];
__device__ __half g_wv[Hd * Hd];
__device__ __half g_wo[Hd * Hd];
__device__ __half g_wi[Id * Hd];
__device__ __half g_w2[Hd * Id];

// ---------------- helpers ----------------
__device__ __forceinline__ uint32_t smem_u32(const void* p) {
  uint32_t a;
  asm("{ .reg .u64 t; cvta.to.shared.u64 t, %1; cvt.u32.u64 %0, t; }" : "=r"(a) : "l"(p));
  return a;
}
__device__ __forceinline__ void cp_async16(uint32_t dst, const void* src) {
  asm volatile("cp.async.cg.shared.global [%0], [%1], 16;" :: "r"(dst), "l"(src) : "memory");
}
#define CP_COMMIT() asm volatile("cp.async.commit_group;" ::: "memory")
#define CP_WAIT(n)  asm volatile("cp.async.wait_group %0;" :: "n"(n) : "memory")

__device__ __forceinline__ void ldsm4(uint32_t* r, uint32_t addr) {
  asm volatile("ldmatrix.sync.aligned.m8n8.x4.shared.b16 {%0,%1,%2,%3}, [%4];"
               : "=r"(r[0]), "=r"(r[1]), "=r"(r[2]), "=r"(r[3]) : "r"(addr));
}
__device__ __forceinline__ void ldsm4t(uint32_t* r, uint32_t addr) {
  asm volatile("ldmatrix.sync.aligned.m8n8.x4.trans.shared.b16 {%0,%1,%2,%3}, [%4];"
               : "=r"(r[0]), "=r"(r[1]), "=r"(r[2]), "=r"(r[3]) : "r"(addr));
}
__device__ __forceinline__ void mma16816(float* d, const uint32_t* a, const uint32_t* b) {
  asm volatile("mma.sync.aligned.m16n8k16.row.col.f32.f16.f16.f32 "
               "{%0,%1,%2,%3}, {%4,%5,%6,%7}, {%8,%9}, {%0,%1,%2,%3};"
               : "+f"(d[0]), "+f"(d[1]), "+f"(d[2]), "+f"(d[3])
               : "r"(a[0]), "r"(a[1]), "r"(a[2]), "r"(a[3]), "r"(b[0]), "r"(b[1]));
}
__device__ __forceinline__ uint32_t packh(float a, float b) {
  __half2 t = __floats2half2_rn(a, b);
  return *(uint32_t*)&t;
}

__device__ __forceinline__ uint32_t swz128(int row, int c16) {
  return (uint32_t)(row * 128 + ((c16 ^ (row & 7)) << 4));
}

// ---------------- batched weight conversion ----------------
struct CvtJobs {
  const float* W[6];
  __half* T[6];
  int K[6], N[6], tilesX[6], start[6];
};

__global__ void __launch_bounds__(256) cvt_wt_all_kernel(CvtJobs jb) {
  const int b = blockIdx.x;
  int j = 0;
  #pragma unroll
  for (int i = 1; i < 6; i++) if (b >= jb.start[i]) j = i;
  const int local = b - jb.start[j];
  const int K = jb.K[j], N = jb.N[j];
  const int nb = (local % jb.tilesX[j]) * 32;
  const int kb = (local / jb.tilesX[j]) * 32;
  const float* W = jb.W[j];
  __half* T = jb.T[j];

  __shared__ float t[32][33];
  const int tx = threadIdx.x & 31, ty = threadIdx.x >> 5;
  #pragma unroll
  for (int i = 0; i < 32; i += 8)
    t[ty + i][tx] = W[(size_t)(kb + ty + i) * N + nb + tx];
  __syncthreads();
  #pragma unroll
  for (int i = 0; i < 32; i += 8)
    T[(size_t)(nb + ty + i) * K + kb + tx] = __float2half_rn(t[tx][ty + i]);
}

// ---------------- HMMA GEMM: C[M,N] = A @ B^T (B stored [N,K]) ----------------
// 128x128 CTA tile, BK=64, 8 warps (2m x 4n), warp tile 64x32, 3-stage cp.async,
// 2 CTAs/SM. Stage = A 16KB + B 16KB = 32KB; 3 stages = 96KB.
struct GemmJob {
  const __half *A, *B;
  const float* bias;
  float* C;
  __half* Ch;
  float oscale;  // applied after bias (Q prescale)
  int outmode;   // 0: fp32 C; 2: fp16 Ch
  int gelu;
};

__global__ void __launch_bounds__(256, 2)
gemm_mma_kernel(GemmJob j0, GemmJob j1, GemmJob j2, int M, int N, int K) {
  extern __shared__ __align__(128) char sm[];
  const uint32_t smb = smem_u32(sm);
  const GemmJob j = (blockIdx.z == 0) ? j0 : ((blockIdx.z == 1) ? j1 : j2);
  const int tid = threadIdx.x;
  const int wid = tid >> 5, lane = tid & 31;
  const int bm = blockIdx.y * 128, bn = blockIdx.x * 128;
  const int warp_m = wid & 1, warp_n = wid >> 1;
  const int NK = K >> 6;

  auto soA = [](int s) -> uint32_t { return (uint32_t)(s * 32768); };
  auto soB = [](int s) -> uint32_t { return (uint32_t)(s * 32768 + 16384); };

  auto load_stage = [&](int kt, int s) {
    const int koff = kt * 64;
    #pragma unroll
    for (int jj = 0; jj < 4; jj++) {
      const int ch = tid + jj * 256;
      const int row = ch >> 3, c = ch & 7;
      const uint32_t d = swz128(row, c);
      cp_async16(smb + soA(s) + d, j.A + (size_t)(bm + row) * K + koff + c * 8);
      cp_async16(smb + soB(s) + d, j.B + (size_t)(bn + row) * K + koff + c * 8);
    }
  };

  float acc[4][4][4];
  #pragma unroll
  for (int i = 0; i < 4; i++)
    #pragma unroll
    for (int jj = 0; jj < 4; jj++)
      #pragma unroll
      for (int q = 0; q < 4; q++) acc[i][jj][q] = 0.f;

  load_stage(0, 0); CP_COMMIT();
  load_stage(1, 1); CP_COMMIT();

  const int la_row = (lane & 7) + ((lane >> 3) & 1) * 8;
  const int la_c   = (lane >> 4);
  const int lb_row = (lane & 7) + (lane >> 4) * 8;
  const int lb_c   = (lane >> 3) & 1;

  int s = 0;
  for (int kt = 0; kt < NK; kt++) {
    if (kt + 1 < NK) { CP_WAIT(1); } else { CP_WAIT(0); }
    __syncthreads();
    if (kt + 2 < NK) { load_stage(kt + 2, (s + 2 > 2) ? s - 1 : s + 2); CP_COMMIT(); }

    const uint32_t baseA = smb + soA(s);
    const uint32_t baseB = smb + soB(s);

    #pragma unroll
    for (int ks = 0; ks < 4; ks++) {
      uint32_t a4[4][4], b4[2][4];
      #pragma unroll
      for (int tm = 0; tm < 4; tm++)
        ldsm4(a4[tm], baseA + swz128(warp_m * 64 + tm * 16 + la_row, ks * 2 + la_c));
      #pragma unroll
      for (int tn2 = 0; tn2 < 2; tn2++)
        ldsm4(b4[tn2], baseB + swz128(warp_n * 32 + tn2 * 16 + lb_row, ks * 2 + lb_c));
      #pragma unroll
      for (int tm = 0; tm < 4; tm++)
        #pragma unroll
        for (int tn = 0; tn < 4; tn++)
          mma16816(acc[tm][tn], a4[tm], &b4[tn >> 1][(tn & 1) * 2]);
    }
    s = (s == 2) ? 0 : s + 1;
  }

  // epilogue
  const int g = lane >> 2, tq = lane & 3;
  #pragma unroll
  for (int tm = 0; tm < 4; tm++) {
    #pragma unroll
    for (int tn = 0; tn < 4; tn++) {
      const int col = bn + warp_n * 32 + tn * 8 + tq * 2;
      const float b0 = j.bias[col], b1 = j.bias[col + 1];
      #pragma unroll
      for (int half = 0; half < 2; half++) {
        const int row = bm + warp_m * 64 + tm * 16 + g + half * 8;
        float vx = (acc[tm][tn][half * 2 + 0] + b0) * j.oscale;
        float vy = (acc[tm][tn][half * 2 + 1] + b1) * j.oscale;
        if (j.gelu) {
          vx = 0.5f * vx * (1.0f + erff(vx * 0.7071067811865476f));
          vy = 0.5f * vy * (1.0f + erff(vy * 0.7071067811865476f));
        }
        if (j.outmode == 0) {
          float2 v; v.x = vx; v.y = vy;
          *(float2*)(j.C + (size_t)row * N + col) = v;
        } else {
          *(uint32_t*)(j.Ch + (size_t)row * N + col) = packh(vx, vy);
        }
      }
    }
  }
}

// ---------------- HMMA flash attention (fp16, fp32 accum, exp2-space) ----------------
// Q is pre-scaled by 0.125*log2(e); mask2 is mask*log2(e). All softmax in base-2.
__global__ void __launch_bounds__(128, 2)
attn_mma_kernel(const __half* __restrict__ Qh,
                const __half* __restrict__ Kh, const __half* __restrict__ Vh,
                const float* __restrict__ mask2,
                __half* __restrict__ Ch) {
  extern __shared__ __align__(128) char sm[];
  const uint32_t smb = smem_u32(sm);
  const int tid = threadIdx.x;
  const int warp = tid >> 5, lane = tid & 31;
  const int qt = blockIdx.x, h = blockIdx.y, b = blockIdx.z;
  const int g = lane >> 2, tq = lane & 3;

  const int la_row = (lane & 7) + ((lane >> 3) & 1) * 8;
  const int la_c   = (lane >> 4);
  const int lb_row = (lane & 7) + (lane >> 4) * 8;
  const int lb_c   = (lane >> 3) & 1;
  const int lv_row = (lane & 7) + ((lane >> 3) & 1) * 8;
  const int lv_c   = (lane >> 4);

  {
    #pragma unroll
    for (int jj = 0; jj < 4; jj++) {
      const int ch = tid + jj * 128;
      const int row = ch >> 3, c = ch & 7;
      cp_async16(smb + swz128(row, c),
                 Qh + (size_t)(b * 1024 + qt * 64 + row) * Hd + h * 64 + c * 8);
    }
  }
  auto load_kv = [&](int kt, int s) {
    const uint32_t so = smb + 8192 + s * 16384;
    #pragma unroll
    for (int jj = 0; jj < 4; jj++) {
      const int ch = tid + jj * 128;
      const int row = ch >> 3, c = ch & 7;
      const uint32_t d = swz128(row, c);
      const size_t gk = (size_t)(b * 1024 + kt * 64 + row) * Hd + h * 64 + c * 8;
      cp_async16(so + d,        Kh + gk);
      cp_async16(so + 8192 + d, Vh + gk);
    }
  };
  load_kv(0, 0);
  CP_COMMIT();

  float m0 = -1e30f, m1 = -1e30f, l0 = 0.f, l1 = 0.f;
  float oacc[8][4];
  #pragma unroll
  for (int jj = 0; jj < 8; jj++)
    #pragma unroll
    for (int q = 0; q < 4; q++) oacc[jj][q] = 0.f;

  for (int kt = 0; kt < 16; kt++) {
    const int s = kt & 1;
    if (kt + 1 < 16) { load_kv(kt + 1, 1 - s); CP_COMMIT(); CP_WAIT(1); }
    else             { CP_WAIT(0); }
    __syncthreads();

    const uint32_t sK = smb + 8192 + s * 16384;
    const uint32_t sV = sK + 8192;

    float sacc[8][4];
    #pragma unroll
    for (int jj = 0; jj < 8; jj++)
      #pragma unroll
      for (int q = 0; q < 4; q++) sacc[jj][q] = 0.f;

    #pragma unroll
    for (int kc = 0; kc < 4; kc++) {
      uint32_t q4[4];
      ldsm4(q4, smb + swz128(warp * 16 + la_row, kc * 2 + la_c));
      #pragma unroll
      for (int n16 = 0; n16 < 4; n16++) {
        uint32_t k4[4];
        ldsm4(k4, sK + swz128(n16 * 16 + lb_row, kc * 2 + lb_c));
        mma16816(sacc[2 * n16],     q4, k4);
        mma16816(sacc[2 * n16 + 1], q4, k4 + 2);
      }
    }

    const float* mrow = mask2 + b * 1024 + kt * 64;
    float mx0 = -1e30f, mx1 = -1e30f;
    #pragma unroll
    for (int jj = 0; jj < 8; jj++) {
      const float2 mv = *(const float2*)(mrow + jj * 8 + 2 * tq);
      sacc[jj][0] += mv.x;
      sacc[jj][1] += mv.y;
      sacc[jj][2] += mv.x;
      sacc[jj][3] += mv.y;
      mx0 = fmaxf(mx0, fmaxf(sacc[jj][0], sacc[jj][1]));
      mx1 = fmaxf(mx1, fmaxf(sacc[jj][2], sacc[jj][3]));
    }
    mx0 = fmaxf(mx0, __shfl_xor_sync(0xffffffffu, mx0, 1));
    mx0 = fmaxf(mx0, __shfl_xor_sync(0xffffffffu, mx0, 2));
    mx1 = fmaxf(mx1, __shfl_xor_sync(0xffffffffu, mx1, 1));
    mx1 = fmaxf(mx1, __shfl_xor_sync(0xffffffffu, mx1, 2));
    const float mn0 = fmaxf(m0, mx0), mn1 = fmaxf(m1, mx1);
    const float rs0 = exp2f(m0 - mn0), rs1 = exp2f(m1 - mn1);
    m0 = mn0; m1 = mn1;

    float sum0 = 0.f, sum1 = 0.f;
    uint32_t ph01[8], ph23[8];
    #pragma unroll
    for (int jj = 0; jj < 8; jj++) {
      const float p0 = exp2f(sacc[jj][0] - mn0), p1 = exp2f(sacc[jj][1] - mn0);
      const float p2 = exp2f(sacc[jj][2] - mn1), p3 = exp2f(sacc[jj][3] - mn1);
      sum0 += p0 + p1; sum1 += p2 + p3;
      ph01[jj] = packh(p0, p1);
      ph23[jj] = packh(p2, p3);
      oacc[jj][0] *= rs0; oacc[jj][1] *= rs0;
      oacc[jj][2] *= rs1; oacc[jj][3] *= rs1;
    }
    sum0 += __shfl_xor_sync(0xffffffffu, sum0, 1);
    sum0 += __shfl_xor_sync(0xffffffffu, sum0, 2);
    sum1 += __shfl_xor_sync(0xffffffffu, sum1, 1);
    sum1 += __shfl_xor_sync(0xffffffffu, sum1, 2);
    l0 = l0 * rs0 + sum0;
    l1 = l1 * rs1 + sum1;

    #pragma unroll
    for (int kc = 0; kc < 4; kc++) {
      uint32_t ah[4] = {ph01[2*kc], ph23[2*kc], ph01[2*kc+1], ph23[2*kc+1]};
      #pragma unroll
      for (int n16 = 0; n16 < 4; n16++) {
        uint32_t v4[4];
        ldsm4t(v4, sV + swz128(kc * 16 + lv_row, n16 * 2 + lv_c));
        mma16816(oacc[2 * n16],     ah, v4);
        mma16816(oacc[2 * n16 + 1], ah, v4 + 2);
      }
    }
    __syncthreads();
  }

  const float inv0 = 1.f / l0, inv1 = 1.f / l1;
  const int row0 = b * 1024 + qt * 64 + warp * 16 + g;
  #pragma unroll
  for (int jj = 0; jj < 8; jj++) {
    const int col = h * 64 + (jj >> 1) * 16 + (jj & 1) * 8 + 2 * tq;
    *(uint32_t*)(Ch + (size_t)row0 * Hd + col)       = packh(oacc[jj][0] * inv0, oacc[jj][1] * inv0);
    *(uint32_t*)(Ch + (size_t)(row0 + 8) * Hd + col) = packh(oacc[jj][2] * inv1, oacc[jj][3] * inv1);
  }
}

// ---------------- routing (+ mask prescale) ----------------
__global__ void __launch_bounds__(256) routing_kernel(
    const float* __restrict__ x, const float* __restrict__ y,
    const float* __restrict__ mask, const int* __restrict__ tptr,
    float* __restrict__ xs, float* __restrict__ mask2,
    __half* __restrict__ xh, __half* __restrict__ yh) {
  const int token = blockIdx.x, tid = threadIdx.x;
  const long base = (long)token * Hd;
  if (tid == 32) mask2[token] = mask[token] * 1.4426950408889634f;
  float sxx = 0.f, sxy = 0.f, syy = 0.f;
  for (int i = tid; i < Hd; i += 256) {
    float a = x[base + i], bb = y[base + i];
    sxx += a * a; sxy += a * bb; syy += bb * bb;
  }
  #pragma unroll
  for (int o = 16; o; o >>= 1) {
    sxx += __shfl_xor_sync(0xffffffffu, sxx, o);
    sxy += __shfl_xor_sync(0xffffffffu, sxy, o);
    syy += __shfl_xor_sync(0xffffffffu, syy, o);
  }
  __shared__ float red[8][3];
  __shared__ float sc[2];
  if ((tid & 31) == 0) { red[tid >> 5][0] = sxx; red[tid >> 5][1] = sxy; red[tid >> 5][2] = syy; }
  __syncthreads();
  if (tid == 0) {
    float a = 0.f, bb = 0.f, c = 0.f;
    #pragma unroll
    for (int i = 0; i < 8; i++) { a += red[i][0]; bb += red[i][1]; c += red[i][2]; }
    const int t = *tptr;
    float b1 = 0.f, b2 = 0.f, c1 = 0.5f, c2 = 0.5f;
    for (int it = 0; it < t; it++) {
      if (it > 0) {
        float mm = fmaxf(b1, b2);
        float e1 = expf(b1 - mm), e2 = expf(b2 - mm);
        float inv = 1.0f / (e1 + e2);
        c1 = e1 * inv; c2 = e2 * inv;
      }
      float vv = c1 * c1 * a + 2.0f * c1 * c2 * bb + c2 * c2 * c;
      float n  = sqrtf(vv);
      float f  = n / (1.0f + vv);
      b1 += f * (c1 * a  + c2 * bb);
      b2 += f * (c1 * bb + c2 * c );
    }
    sc[0] = c1; sc[1] = c2;
  }
  __syncthreads();
  const float c1 = sc[0], c2 = sc[1];
  for (int i = tid; i < Hd; i += 256) {
    const float vx = c1 * x[base + i];
    const float vy = c2 * y[base + i];
    xs[base + i] = vx;
    xh[base + i] = __float2half_rn(vx);
    yh[base + i] = __float2half_rn(vy);
  }
}

// ---------------- fused residual + RMSNorm ----------------
template<bool FOUT>
__global__ void __launch_bounds__(256) rms_kernel(
    const float* __restrict__ in, const float* __restrict__ res,
    const float* __restrict__ g, float* __restrict__ out,
    __half* __restrict__ oh) {
  const int row = blockIdx.x, tid = threadIdx.x;
  __shared__ float buf[Hd];
  __shared__ float red[8];
  __shared__ float s_inv;
  const long base = (long)row * Hd;
  float ss = 0.f;
  for (int i = tid; i < Hd; i += 256) {
    float v = in[base + i] + res[base + i];
    buf[i] = v; ss += v * v;
  }
  #pragma unroll
  for (int o = 16; o; o >>= 1) ss += __shfl_xor_sync(0xffffffffu, ss, o);
  if ((tid & 31) == 0) red[tid >> 5] = ss;
  __syncthreads();
  if (tid == 0) {
    float tot = 0.f;
    #pragma unroll
    for (int i = 0; i < 8; i++) tot += red[i];
    s_inv = rsqrtf(tot * (1.0f / (float)Hd) + 1e-6f);
  }
  __syncthreads();
  const float inv = s_inv;
  for (int i = tid; i < Hd; i += 256) {
    const float v = buf[i] * inv * g[i];
    out[base + i] = v;
    if (FOUT) oh[base + i] = __float2half_rn(v);
  }
}

// ---------------- host ----------------
static const int GEMM_SMEM = 98304;   // 3 stages x 32KB
static const int ATTN_SMEM = 40960;

extern "C" void kernel_launch(void* const* d_in, const int* in_sizes, int n_in,
                              void* d_out, int out_size) {
  const float* x    = (const float*)d_in[0];
  const float* y    = (const float*)d_in[1];
  const float* mask = (const float*)d_in[2];
  const float* Wq   = (const float*)d_in[3];
  const float* bq   = (const float*)d_in[4];
  const float* Wk   = (const float*)d_in[5];
  const float* bk   = (const float*)d_in[6];
  const float* Wv   = (const float*)d_in[7];
  const float* bv   = (const float*)d_in[8];
  const float* Wo   = (const float*)d_in[9];
  const float* bo   = (const float*)d_in[10];
  const float* g1   = (const float*)d_in[11];
  const float* Wi   = (const float*)d_in[12];
  const float* bi   = (const float*)d_in[13];
  const float* Wo2  = (const float*)d_in[14];
  const float* bo2  = (const float*)d_in[15];
  const float* g2   = (const float*)d_in[16];
  const int*   t    = (const int*)d_in[17];
  float* out = (float*)d_out;

  cudaFuncSetAttribute(gemm_mma_kernel, cudaFuncAttributeMaxDynamicSharedMemorySize, GEMM_SMEM);
  cudaFuncSetAttribute(attn_mma_kernel, cudaFuncAttributeMaxDynamicSharedMemorySize, ATTN_SMEM);

  float *xs, *att, *tmp, *mask2;
  cudaGetSymbolAddress((void**)&xs,    g_xs);
  cudaGetSymbolAddress((void**)&att,   g_att);
  cudaGetSymbolAddress((void**)&tmp,   g_tmp);
  cudaGetSymbolAddress((void**)&mask2, g_mask2);

  __half *xh,*yh,*qh,*kh,*vh,*ch,*ah,*ih;
  cudaGetSymbolAddress((void**)&xh, g_xh);
  cudaGetSymbolAddress((void**)&yh, g_yh);
  cudaGetSymbolAddress((void**)&qh, g_qh);
  cudaGetSymbolAddress((void**)&kh, g_kh);
  cudaGetSymbolAddress((void**)&vh, g_vh);
  cudaGetSymbolAddress((void**)&ch, g_ch);
  cudaGetSymbolAddress((void**)&ah, g_ah);
  cudaGetSymbolAddress((void**)&ih, g_ih);

  __half *wq,*wk,*wv,*wo,*wi,*w2;
  cudaGetSymbolAddress((void**)&wq, g_wq);
  cudaGetSymbolAddress((void**)&wk, g_wk);
  cudaGetSymbolAddress((void**)&wv, g_wv);
  cudaGetSymbolAddress((void**)&wo, g_wo);
  cudaGetSymbolAddress((void**)&wi, g_wi);
  cudaGetSymbolAddress((void**)&w2, g_w2);

  routing_kernel<<<TOK, 256>>>(x, y, mask, t, xs, mask2, xh, yh);

  {
    CvtJobs jb;
    const float* Ws[6] = {Wq, Wk, Wv, Wo, Wi, Wo2};
    __half* Ts[6] = {wq, wk, wv, wo, wi, w2};
    int Ks[6] = {Hd, Hd, Hd, Hd, Hd, Id};
    int Ns[6] = {Hd, Hd, Hd, Hd, Id, Hd};
    int cum = 0;
    for (int i = 0; i < 6; i++) {
      jb.W[i] = Ws[i]; jb.T[i] = Ts[i];
      jb.K[i] = Ks[i]; jb.N[i] = Ns[i];
      jb.tilesX[i] = Ns[i] / 32;
      jb.start[i] = cum;
      cum += (Ns[i] / 32) * (Ks[i] / 32);
    }
    cvt_wt_all_kernel<<<cum, 256>>>(jb);
  }

  const float QSCALE = 0.125f * 1.4426950408889634f;

  // fused QKV (z = 0,1,2); Q output pre-scaled for exp2-space softmax
  {
    GemmJob jq = {xh, wq, bq, nullptr, qh, QSCALE, 2, 0};
    GemmJob jk = {yh, wk, bk, nullptr, kh, 1.0f,   2, 0};
    GemmJob jv = {yh, wv, bv, nullptr, vh, 1.0f,   2, 0};
    gemm_mma_kernel<<<dim3(Hd/128, TOK/128, 3), 256, GEMM_SMEM>>>(jq, jk, jv, TOK, Hd, Hd);
  }

  attn_mma_kernel<<<dim3(16, NHh, 4), 128, ATTN_SMEM>>>(qh, kh, vh, mask2, ch);

  {
    GemmJob jo = {ch, wo, bo, tmp, nullptr, 1.0f, 0, 0};
    gemm_mma_kernel<<<dim3(Hd/128, TOK/128, 1), 256, GEMM_SMEM>>>(jo, jo, jo, TOK, Hd, Hd);
  }
  rms_kernel<true ><<<TOK, 256>>>(tmp, xs, g1, att, ah);

  {
    GemmJob ji = {ah, wi, bi, nullptr, ih, 1.0f, 2, 1};
    gemm_mma_kernel<<<dim3(Id/128, TOK/128, 1), 256, GEMM_SMEM>>>(ji, ji, ji, TOK, Id, Hd);
  }
  {
    GemmJob j2 = {ih, w2, bo2, tmp, nullptr, 1.0f, 0, 0};
    gemm_mma_kernel<<<dim3(Hd/128, TOK/128, 1), 256, GEMM_SMEM>>>(j2, j2, j2, TOK, Hd, Id);
  }
  rms_kernel<false><<<TOK, 256>>>(tmp, att, g2, out, nullptr);
}